// round 1
// baseline (speedup 1.0000x reference)
#include <cuda_runtime.h>
#include <math.h>

#define EMBED 768
#define HEADS 12
#define HD 64
#define MAXREL 50
#define BB 4
#define LL 1024

// ---------------- device scratch (no allocs allowed) ----------------
__device__ float g_q[BB*HEADS*LL*HD];
__device__ float g_k[BB*HEADS*LL*HD];
__device__ float g_v[BB*HEADS*LL*HD];
__device__ float g_attn[BB*LL*EMBED];
__device__ float g_dt[BB];

// ---------------- dt = guarded nanmedian of deltas ----------------
__global__ void dt_kernel(const float* __restrict__ patch) {
    int b = blockIdx.x;
    int tid = threadIdx.x;
    __shared__ float sd[LL-1];
    __shared__ int cnt;
    __shared__ float sLo, sHi;
    if (tid == 0) { cnt = 0; sLo = nanf(""); sHi = nanf(""); }
    __syncthreads();
    int local = 0;
    for (int i = tid; i < LL-1; i += blockDim.x) {
        float d = patch[b*LL + i + 1] - patch[b*LL + i];
        sd[i] = d;
        if (!isnan(d)) local++;
    }
    if (local) atomicAdd(&cnt, local);
    __syncthreads();
    int n = cnt;
    if (n > 0) {
        int kLo = (n - 1) >> 1, kHi = n >> 1;
        for (int i = tid; i < LL-1; i += blockDim.x) {
            float x = sd[i];
            if (isnan(x)) continue;
            int less = 0, eq = 0;
            for (int j = 0; j < LL-1; j++) {
                float y = sd[j];
                less += (y < x);
                eq   += (y == x);
            }
            if (less <= kLo && kLo < less + eq) sLo = x;
            if (less <= kHi && kHi < less + eq) sHi = x;
        }
    }
    __syncthreads();
    if (tid == 0) {
        float med = 0.5f * (sLo + sHi);
        if (n == 0) med = nanf("");
        float dt = (isfinite(med) && med > 0.f) ? med : 1.0f;
        g_dt[b] = dt;
    }
}

// ---------------- QKV projection GEMM (NT), epilogue scatter ----------------
// C[m,n] = query[m,:] . in_proj_w[n,:] + b[n];  M=4096, N=2304, K=768
__global__ void gemm_qkv_kernel(const float* __restrict__ A,
                                const float* __restrict__ W,
                                const float* __restrict__ bias) {
    __shared__ float sA[16][68];
    __shared__ float sB[16][68];
    const int K = EMBED;
    int tid = threadIdx.x;
    int ty = tid >> 4, tx = tid & 15;
    int m0 = blockIdx.y << 6, n0 = blockIdx.x << 6;
    float acc[4][4] = {};
    int lr = tid >> 2;
    int lk = (tid & 3) << 2;
    const float* Ap = A + (size_t)(m0 + lr) * K + lk;
    const float* Bp = W + (size_t)(n0 + lr) * K + lk;
    for (int k0 = 0; k0 < K; k0 += 16) {
        float4 av = *(const float4*)(Ap + k0);
        float4 bv = *(const float4*)(Bp + k0);
        sA[lk+0][lr]=av.x; sA[lk+1][lr]=av.y; sA[lk+2][lr]=av.z; sA[lk+3][lr]=av.w;
        sB[lk+0][lr]=bv.x; sB[lk+1][lr]=bv.y; sB[lk+2][lr]=bv.z; sB[lk+3][lr]=bv.w;
        __syncthreads();
#pragma unroll
        for (int kk = 0; kk < 16; kk++) {
            float4 a  = *(const float4*)&sA[kk][ty<<2];
            float4 bq = *(const float4*)&sB[kk][tx<<2];
            float ar[4] = {a.x, a.y, a.z, a.w};
            float br[4] = {bq.x, bq.y, bq.z, bq.w};
#pragma unroll
            for (int i = 0; i < 4; i++)
#pragma unroll
                for (int j = 0; j < 4; j++)
                    acc[i][j] = fmaf(ar[i], br[j], acc[i][j]);
        }
        __syncthreads();
    }
#pragma unroll
    for (int i = 0; i < 4; i++) {
        int m = m0 + (ty<<2) + i;
        int b = m >> 10, l = m & (LL - 1);
#pragma unroll
        for (int j = 0; j < 4; j++) {
            int nn = n0 + (tx<<2) + j;
            float c = acc[i][j] + __ldg(&bias[nn]);
            int part = nn / EMBED;
            int hn = nn - part * EMBED;
            int h = hn >> 6, d = hn & 63;
            int idx = ((b*HEADS + h)*LL + l)*HD + d;
            if (part == 0)      g_q[idx] = c * 0.125f;   // * hd^-0.5
            else if (part == 1) g_k[idx] = c;
            else                g_v[idx] = c;
        }
    }
}

// ---------------- flash attention with dual relative bias ----------------
// grid: (L/64, B*H), 256 threads, dyn smem = 4 * 64*65 floats
__global__ void attn_kernel(const float* __restrict__ patch,
                            const float* __restrict__ rel_bias) {
    extern __shared__ float smem[];
    float* sQ = smem;               // [64][65]
    float* sK = sQ + 64*65;
    float* sV = sK + 64*65;
    float* sS = sV + 64*65;
    __shared__ float sM[64], sL[64], sAl[64], sRed[256], sBias[104], sPq[64], sPk[64];

    int tid = threadIdx.x;
    int ty = tid >> 4, tx = tid & 15;
    int bh = blockIdx.y;
    int b = bh / HEADS, h = bh - b*HEADS;
    int q0 = blockIdx.x << 6;
    float dtb = g_dt[b];

    const float* gq = g_q + (size_t)bh*LL*HD;
    const float* gk = g_k + (size_t)bh*LL*HD;
    const float* gv = g_v + (size_t)bh*LL*HD;

#pragma unroll
    for (int it = 0; it < 4; it++) {
        int idx = tid + (it << 8);      // float4 index 0..1023
        int r  = idx >> 4;
        int d4 = (idx & 15) << 2;
        float4 qv = *(const float4*)&gq[(q0 + r)*HD + d4];
        float* dst = &sQ[r*65 + d4];
        dst[0]=qv.x; dst[1]=qv.y; dst[2]=qv.z; dst[3]=qv.w;
    }
    if (tid < 101) sBias[tid] = rel_bias[h*101 + tid];
    if (tid < 64)  { sPq[tid] = patch[b*LL + q0 + tid]; sM[tid] = -INFINITY; sL[tid] = 0.f; }

    float acc[4][4] = {};
    int r0 = ty << 2, c0 = tx << 2;

    for (int k0 = 0; k0 < LL; k0 += 64) {
        __syncthreads();   // prior tile's reads of sK/sV/sS done
#pragma unroll
        for (int it = 0; it < 4; it++) {
            int idx = tid + (it << 8);
            int r  = idx >> 4;
            int d4 = (idx & 15) << 2;
            float4 kv = *(const float4*)&gk[(k0 + r)*HD + d4];
            float* dk = &sK[r*65 + d4];
            dk[0]=kv.x; dk[1]=kv.y; dk[2]=kv.z; dk[3]=kv.w;
            float4 vv = *(const float4*)&gv[(k0 + r)*HD + d4];
            float* dv = &sV[r*65 + d4];
            dv[0]=vv.x; dv[1]=vv.y; dv[2]=vv.z; dv[3]=vv.w;
        }
        if (tid < 64) sPk[tid] = patch[b*LL + k0 + tid];
        __syncthreads();

        // S = Q K^T (4x4 microtile)
        float s[4][4] = {};
#pragma unroll
        for (int d = 0; d < 64; d++) {
            float ar[4], br[4];
#pragma unroll
            for (int i = 0; i < 4; i++) ar[i] = sQ[(r0+i)*65 + d];
#pragma unroll
            for (int j = 0; j < 4; j++) br[j] = sK[(c0+j)*65 + d];
#pragma unroll
            for (int i = 0; i < 4; i++)
#pragma unroll
                for (int j = 0; j < 4; j++)
                    s[i][j] = fmaf(ar[i], br[j], s[i][j]);
        }
        // add both relative biases
#pragma unroll
        for (int i = 0; i < 4; i++) {
            int r = r0 + i, qi = q0 + r;
            float pq = sPq[r];
#pragma unroll
            for (int j = 0; j < 4; j++) {
                int c = c0 + j, kj = k0 + c;
                int d1 = kj - qi;
                d1 = max(-MAXREL, min(MAXREL, d1)) + MAXREL;
                float rt = pq - sPk[c];
                if (!(rt >= -50.f && rt <= 50.f)) rt = 0.f;   // NaN or |rt|>M -> 0
                float rr = rintf(rt / dtb);                    // round-half-even, then clip
                rr = fminf(50.f, fmaxf(-50.f, rr));
                float sv = s[i][j] + sBias[d1] + sBias[(int)rr + MAXREL];
                s[i][j] = sv;
                sS[r*65 + c] = sv;
            }
        }
        __syncthreads();

        // row max (4 threads per row, 16 elems each)
        {
            int row = tid >> 2, seg = tid & 3;
            float mx = -INFINITY;
            const float* p = &sS[row*65 + (seg << 4)];
#pragma unroll
            for (int e = 0; e < 16; e++) mx = fmaxf(mx, p[e]);
            sRed[(row<<2) + seg] = mx;
        }
        __syncthreads();
        if (tid < 64) {
            float tm = fmaxf(fmaxf(sRed[tid<<2], sRed[(tid<<2)+1]),
                             fmaxf(sRed[(tid<<2)+2], sRed[(tid<<2)+3]));
            float mo = sM[tid];
            float mn = fmaxf(mo, tm);
            sAl[tid] = expf(mo - mn);     // expf(-inf)=0 on first tile
            sM[tid] = mn;
        }
        __syncthreads();

        // P = exp(S - m), rescale accumulator
#pragma unroll
        for (int i = 0; i < 4; i++) {
            int r = r0 + i;
            float mn = sM[r];
            float al = sAl[r];
#pragma unroll
            for (int j = 0; j < 4; j++) {
                float p = expf(s[i][j] - mn);
                sS[r*65 + c0 + j] = p;
                acc[i][j] *= al;
            }
        }
        __syncthreads();

        // row sum
        {
            int row = tid >> 2, seg = tid & 3;
            float sm = 0.f;
            const float* p = &sS[row*65 + (seg << 4)];
#pragma unroll
            for (int e = 0; e < 16; e++) sm += p[e];
            sRed[(row<<2) + seg] = sm;
        }
        __syncthreads();
        if (tid < 64) {
            sL[tid] = sL[tid]*sAl[tid]
                    + sRed[tid<<2] + sRed[(tid<<2)+1] + sRed[(tid<<2)+2] + sRed[(tid<<2)+3];
        }

        // O += P @ V
        for (int jj = 0; jj < 64; jj++) {
            float ar[4], br[4];
#pragma unroll
            for (int i = 0; i < 4; i++) ar[i] = sS[(r0+i)*65 + jj];
#pragma unroll
            for (int j = 0; j < 4; j++) br[j] = sV[jj*65 + c0 + j];
#pragma unroll
            for (int i = 0; i < 4; i++)
#pragma unroll
                for (int j = 0; j < 4; j++)
                    acc[i][j] = fmaf(ar[i], br[j], acc[i][j]);
        }
    }
    __syncthreads();

    // epilogue: normalize, write [B,L,H*hd]
#pragma unroll
    for (int i = 0; i < 4; i++) {
        int r = r0 + i;
        float inv = 1.0f / sL[r];
#pragma unroll
        for (int j = 0; j < 4; j++) {
            g_attn[(size_t)(b*LL + q0 + r)*EMBED + h*HD + c0 + j] = acc[i][j] * inv;
        }
    }
}

// ---------------- output projection GEMM (NT) ----------------
// out[m,n] = g_attn[m,:] . out_proj_w[n,:] + b[n];  M=4096, N=768, K=768
__global__ void gemm_out_kernel(const float* __restrict__ W,
                                const float* __restrict__ bias,
                                float* __restrict__ out) {
    __shared__ float sA[16][68];
    __shared__ float sB[16][68];
    const int K = EMBED;
    int tid = threadIdx.x;
    int ty = tid >> 4, tx = tid & 15;
    int m0 = blockIdx.y << 6, n0 = blockIdx.x << 6;
    float acc[4][4] = {};
    int lr = tid >> 2;
    int lk = (tid & 3) << 2;
    const float* Ap = g_attn + (size_t)(m0 + lr) * K + lk;
    const float* Bp = W + (size_t)(n0 + lr) * K + lk;
    for (int k0 = 0; k0 < K; k0 += 16) {
        float4 av = *(const float4*)(Ap + k0);
        float4 bv = *(const float4*)(Bp + k0);
        sA[lk+0][lr]=av.x; sA[lk+1][lr]=av.y; sA[lk+2][lr]=av.z; sA[lk+3][lr]=av.w;
        sB[lk+0][lr]=bv.x; sB[lk+1][lr]=bv.y; sB[lk+2][lr]=bv.z; sB[lk+3][lr]=bv.w;
        __syncthreads();
#pragma unroll
        for (int kk = 0; kk < 16; kk++) {
            float4 a  = *(const float4*)&sA[kk][ty<<2];
            float4 bq = *(const float4*)&sB[kk][tx<<2];
            float ar[4] = {a.x, a.y, a.z, a.w};
            float br[4] = {bq.x, bq.y, bq.z, bq.w};
#pragma unroll
            for (int i = 0; i < 4; i++)
#pragma unroll
                for (int j = 0; j < 4; j++)
                    acc[i][j] = fmaf(ar[i], br[j], acc[i][j]);
        }
        __syncthreads();
    }
#pragma unroll
    for (int i = 0; i < 4; i++) {
        int m = m0 + (ty<<2) + i;
#pragma unroll
        for (int j = 0; j < 4; j++) {
            int nn = n0 + (tx<<2) + j;
            out[(size_t)m*EMBED + nn] = acc[i][j] + __ldg(&bias[nn]);
        }
    }
}

// ---------------- launch ----------------
extern "C" void kernel_launch(void* const* d_in, const int* in_sizes, int n_in,
                              void* d_out, int out_size) {
    const float* query    = (const float*)d_in[0];
    // d_in[1] (key) and d_in[2] (value) are ignored by the reference module.
    const float* patch    = (const float*)d_in[3];
    const float* in_w     = (const float*)d_in[4];
    const float* in_b     = (const float*)d_in[5];
    const float* out_w    = (const float*)d_in[6];
    const float* out_b    = (const float*)d_in[7];
    const float* rel_bias = (const float*)d_in[8];
    float* out = (float*)d_out;

    dt_kernel<<<BB, 256>>>(patch);

    dim3 g1(2304/64, 4096/64);
    gemm_qkv_kernel<<<g1, 256>>>(query, in_w, in_b);

    size_t attn_smem = (size_t)4 * 64 * 65 * sizeof(float);   // 66560 B
    cudaFuncSetAttribute(attn_kernel, cudaFuncAttributeMaxDynamicSharedMemorySize, (int)attn_smem);
    attn_kernel<<<dim3(LL/64, BB*HEADS), 256, attn_smem>>>(patch, rel_bias);

    dim3 g2(768/64, 4096/64);
    gemm_out_kernel<<<g2, 256>>>(out_w, out_b, out);
}

// round 3
// speedup vs baseline: 1.3993x; 1.3993x over previous
#include <cuda_runtime.h>
#include <cuda_bf16.h>
#include <math.h>
#include <cstdint>

#define EMBED 768
#define HEADS 12
#define HD 64
#define MAXREL 50
#define BB 4
#define LL 1024
#define MTOT (BB*LL)
#define N_QKV (3*EMBED)

// ---------------- device scratch ----------------
__device__ float g_q[BB*HEADS*LL*HD];
__device__ float g_k[BB*HEADS*LL*HD];
__device__ float g_v[BB*HEADS*LL*HD];
__device__ float g_dt[BB];
__device__ __align__(16) __nv_bfloat16 g_qh[MTOT*EMBED];
__device__ __align__(16) __nv_bfloat16 g_ql[MTOT*EMBED];
__device__ __align__(16) __nv_bfloat16 g_w1h[N_QKV*EMBED];
__device__ __align__(16) __nv_bfloat16 g_w1l[N_QKV*EMBED];
__device__ __align__(16) __nv_bfloat16 g_w2h[EMBED*EMBED];
__device__ __align__(16) __nv_bfloat16 g_w2l[EMBED*EMBED];
__device__ __align__(16) __nv_bfloat16 g_ah[MTOT*EMBED];
__device__ __align__(16) __nv_bfloat16 g_al[MTOT*EMBED];

// ---------------- mma.sync helper (bf16, fp32 accum) ----------------
__device__ __forceinline__ void mma_bf16(float* c, const unsigned* a, const unsigned* b) {
    asm volatile(
        "mma.sync.aligned.m16n8k16.row.col.f32.bf16.bf16.f32 "
        "{%0,%1,%2,%3}, {%4,%5,%6,%7}, {%8,%9}, {%0,%1,%2,%3};"
        : "+f"(c[0]), "+f"(c[1]), "+f"(c[2]), "+f"(c[3])
        : "r"(a[0]), "r"(a[1]), "r"(a[2]), "r"(a[3]), "r"(b[0]), "r"(b[1]));
}

// ---------------- fp32 -> bf16 hi/lo split ----------------
__global__ void cvt_kernel(const float* __restrict__ src,
                           __nv_bfloat16* __restrict__ hi,
                           __nv_bfloat16* __restrict__ lo, int n) {
    int i = blockIdx.x * blockDim.x + threadIdx.x;
    if (i < n) {
        float x = src[i];
        __nv_bfloat16 h = __float2bfloat16(x);
        hi[i] = h;
        lo[i] = __float2bfloat16(x - __bfloat162float(h));
    }
}

// ---------------- dt = guarded nanmedian of deltas ----------------
__global__ void dt_kernel(const float* __restrict__ patch) {
    int b = blockIdx.x;
    int tid = threadIdx.x;
    __shared__ float sd[LL-1];
    __shared__ int cnt;
    __shared__ float sLo, sHi;
    if (tid == 0) { cnt = 0; sLo = nanf(""); sHi = nanf(""); }
    __syncthreads();
    int local = 0;
    for (int i = tid; i < LL-1; i += blockDim.x) {
        float d = patch[b*LL + i + 1] - patch[b*LL + i];
        sd[i] = d;
        if (!isnan(d)) local++;
    }
    if (local) atomicAdd(&cnt, local);
    __syncthreads();
    int n = cnt;
    if (n > 0) {
        int kLo = (n - 1) >> 1, kHi = n >> 1;
        for (int i = tid; i < LL-1; i += blockDim.x) {
            float x = sd[i];
            if (isnan(x)) continue;
            int less = 0, eq = 0;
            for (int j = 0; j < LL-1; j++) {
                float y = sd[j];
                less += (y < x);
                eq   += (y == x);
            }
            if (less <= kLo && kLo < less + eq) sLo = x;
            if (less <= kHi && kHi < less + eq) sHi = x;
        }
    }
    __syncthreads();
    if (tid == 0) {
        float med = 0.5f * (sLo + sHi);
        if (n == 0) med = nanf("");
        g_dt[b] = (isfinite(med) && med > 0.f) ? med : 1.0f;
    }
}

// ---------------- shared tile layout for mma GEMM ----------------
// [128 rows][32 bf16 = 64B data + 16B pad] -> 80B row stride, conflict-free frag loads
#define ROWB 80
struct GemmSmem {
    __align__(16) char ah[128*ROWB];
    __align__(16) char al[128*ROWB];
    __align__(16) char bh[128*ROWB];
    __align__(16) char bl[128*ROWB];
};

// Mainloop: acc[mt][nt][4] += (Ah+Al)[128,K] x (Bh+Bl)[128,K]^T  tile at (m0,n0)
__device__ __forceinline__ void gemm_mainloop(
    const __nv_bfloat16* __restrict__ Ah, const __nv_bfloat16* __restrict__ Al,
    const __nv_bfloat16* __restrict__ Bh, const __nv_bfloat16* __restrict__ Bl,
    int m0, int n0, int K, GemmSmem* sm, float acc[4][4][4]) {
    int tid = threadIdx.x;
    int lane = tid & 31, wid = tid >> 5;
    int wm = wid & 1, wn = wid >> 1;           // warp tile: rows wm*64, cols wn*32
    int fr = lane >> 2, fc = lane & 3;

    for (int kc = 0; kc < K; kc += 32) {
#pragma unroll
        for (int i = 0; i < 2; i++) {
            int id = tid + (i << 8);           // 0..511
            int row = id >> 2, part = id & 3;  // part: 8 bf16 = 16B
            size_t ga = (size_t)(m0 + row) * K + kc + part * 8;
            size_t gb = (size_t)(n0 + row) * K + kc + part * 8;
            int so = row * ROWB + part * 16;
            *(uint4*)(sm->ah + so) = *(const uint4*)(Ah + ga);
            *(uint4*)(sm->al + so) = *(const uint4*)(Al + ga);
            *(uint4*)(sm->bh + so) = *(const uint4*)(Bh + gb);
            *(uint4*)(sm->bl + so) = *(const uint4*)(Bl + gb);
        }
        __syncthreads();

#pragma unroll
        for (int kk = 0; kk < 2; kk++) {
            unsigned afh[4][4], afl[4][4], bf[4][2];
#pragma unroll
            for (int mt = 0; mt < 4; mt++) {
                int base = (wm*64 + mt*16 + fr) * ROWB + kk*32 + fc*4;
                afh[mt][0] = *(const unsigned*)(sm->ah + base);
                afh[mt][1] = *(const unsigned*)(sm->ah + base + 8*ROWB);
                afh[mt][2] = *(const unsigned*)(sm->ah + base + 16);
                afh[mt][3] = *(const unsigned*)(sm->ah + base + 8*ROWB + 16);
                afl[mt][0] = *(const unsigned*)(sm->al + base);
                afl[mt][1] = *(const unsigned*)(sm->al + base + 8*ROWB);
                afl[mt][2] = *(const unsigned*)(sm->al + base + 16);
                afl[mt][3] = *(const unsigned*)(sm->al + base + 8*ROWB + 16);
            }
#pragma unroll
            for (int nt = 0; nt < 4; nt++) {
                int base = (wn*32 + nt*8 + fr) * ROWB + kk*32 + fc*4;
                bf[nt][0] = *(const unsigned*)(sm->bh + base);
                bf[nt][1] = *(const unsigned*)(sm->bh + base + 16);
            }
#pragma unroll
            for (int mt = 0; mt < 4; mt++)
#pragma unroll
                for (int nt = 0; nt < 4; nt++) {
                    mma_bf16(acc[mt][nt], afh[mt], bf[nt]);
                    mma_bf16(acc[mt][nt], afl[mt], bf[nt]);
                }
#pragma unroll
            for (int nt = 0; nt < 4; nt++) {
                int base = (wn*32 + nt*8 + fr) * ROWB + kk*32 + fc*4;
                bf[nt][0] = *(const unsigned*)(sm->bl + base);
                bf[nt][1] = *(const unsigned*)(sm->bl + base + 16);
            }
#pragma unroll
            for (int mt = 0; mt < 4; mt++)
#pragma unroll
                for (int nt = 0; nt < 4; nt++)
                    mma_bf16(acc[mt][nt], afh[mt], bf[nt]);
        }
        __syncthreads();
    }
}

// ---------------- GEMM1: qkv projection, scatter epilogue ----------------
__global__ __launch_bounds__(256) void gemm_qkv_mma(const float* __restrict__ bias) {
    __shared__ GemmSmem sm;
    float acc[4][4][4] = {};
    int m0 = blockIdx.y << 7, n0 = blockIdx.x << 7;
    gemm_mainloop(g_qh, g_ql, g_w1h, g_w1l, m0, n0, EMBED, &sm, acc);

    int tid = threadIdx.x;
    int lane = tid & 31, wid = tid >> 5;
    int wm = wid & 1, wn = wid >> 1;
    int fr = lane >> 2, fc = lane & 3;
#pragma unroll
    for (int mt = 0; mt < 4; mt++) {
#pragma unroll
        for (int half = 0; half < 2; half++) {
            int m = m0 + wm*64 + mt*16 + fr + half*8;
            int b = m >> 10, l = m & (LL - 1);
#pragma unroll
            for (int nt = 0; nt < 4; nt++) {
                int n = n0 + wn*32 + nt*8 + 2*fc;
                float v0 = acc[mt][nt][half*2 + 0] + __ldg(&bias[n]);
                float v1 = acc[mt][nt][half*2 + 1] + __ldg(&bias[n+1]);
                int part = n / EMBED;
                int hn = n - part * EMBED;
                int h = hn >> 6, d = hn & 63;
                int idx = ((b * HEADS + h) * LL + l) * HD + d;
                if (part == 0) { v0 *= 0.125f; v1 *= 0.125f; *(float2*)&g_q[idx] = make_float2(v0, v1); }
                else if (part == 1) *(float2*)&g_k[idx] = make_float2(v0, v1);
                else                *(float2*)&g_v[idx] = make_float2(v0, v1);
            }
        }
    }
}

// ---------------- GEMM2: out projection ----------------
__global__ __launch_bounds__(256) void gemm_out_mma(const float* __restrict__ bias,
                                                    float* __restrict__ out) {
    __shared__ GemmSmem sm;
    float acc[4][4][4] = {};
    int m0 = blockIdx.y << 7, n0 = blockIdx.x << 7;
    gemm_mainloop(g_ah, g_al, g_w2h, g_w2l, m0, n0, EMBED, &sm, acc);

    int tid = threadIdx.x;
    int lane = tid & 31, wid = tid >> 5;
    int wm = wid & 1, wn = wid >> 1;
    int fr = lane >> 2, fc = lane & 3;
#pragma unroll
    for (int mt = 0; mt < 4; mt++) {
#pragma unroll
        for (int half = 0; half < 2; half++) {
            int m = m0 + wm*64 + mt*16 + fr + half*8;
#pragma unroll
            for (int nt = 0; nt < 4; nt++) {
                int n = n0 + wn*32 + nt*8 + 2*fc;
                float v0 = acc[mt][nt][half*2 + 0] + __ldg(&bias[n]);
                float v1 = acc[mt][nt][half*2 + 1] + __ldg(&bias[n+1]);
                *(float2*)&out[(size_t)m * EMBED + n] = make_float2(v0, v1);
            }
        }
    }
}

// ---------------- flash attention with dual relative bias (fp32) ----------------
__global__ void attn_kernel(const float* __restrict__ patch,
                            const float* __restrict__ rel_bias) {
    extern __shared__ float smemf[];
    float* sQ = smemf;
    float* sK = sQ + 64*65;
    float* sV = sK + 64*65;
    float* sS = sV + 64*65;
    __shared__ float sM[64], sL[64], sAl[64], sRed[256], sBias[104], sPq[64], sPk[64];

    int tid = threadIdx.x;
    int ty = tid >> 4, tx = tid & 15;
    int bh = blockIdx.y;
    int b = bh / HEADS, h = bh - b*HEADS;
    int q0 = blockIdx.x << 6;
    float dtb = g_dt[b];

    const float* gq = g_q + (size_t)bh*LL*HD;
    const float* gk = g_k + (size_t)bh*LL*HD;
    const float* gv = g_v + (size_t)bh*LL*HD;

#pragma unroll
    for (int it = 0; it < 4; it++) {
        int idx = tid + (it << 8);
        int r  = idx >> 4;
        int d4 = (idx & 15) << 2;
        float4 qv = *(const float4*)&gq[(q0 + r)*HD + d4];
        float* dst = &sQ[r*65 + d4];
        dst[0]=qv.x; dst[1]=qv.y; dst[2]=qv.z; dst[3]=qv.w;
    }
    if (tid < 101) sBias[tid] = rel_bias[h*101 + tid];
    if (tid < 64)  { sPq[tid] = patch[b*LL + q0 + tid]; sM[tid] = -INFINITY; sL[tid] = 0.f; }

    float acc[4][4] = {};
    int r0 = ty << 2, c0 = tx << 2;

    for (int k0 = 0; k0 < LL; k0 += 64) {
        __syncthreads();
#pragma unroll
        for (int it = 0; it < 4; it++) {
            int idx = tid + (it << 8);
            int r  = idx >> 4;
            int d4 = (idx & 15) << 2;
            float4 kv = *(const float4*)&gk[(k0 + r)*HD + d4];
            float* dk = &sK[r*65 + d4];
            dk[0]=kv.x; dk[1]=kv.y; dk[2]=kv.z; dk[3]=kv.w;
            float4 vv = *(const float4*)&gv[(k0 + r)*HD + d4];
            float* dv = &sV[r*65 + d4];
            dv[0]=vv.x; dv[1]=vv.y; dv[2]=vv.z; dv[3]=vv.w;
        }
        if (tid < 64) sPk[tid] = patch[b*LL + k0 + tid];
        __syncthreads();

        float s[4][4] = {};
#pragma unroll
        for (int d = 0; d < 64; d++) {
            float ar[4], br[4];
#pragma unroll
            for (int i = 0; i < 4; i++) ar[i] = sQ[(r0+i)*65 + d];
#pragma unroll
            for (int j = 0; j < 4; j++) br[j] = sK[(c0+j)*65 + d];
#pragma unroll
            for (int i = 0; i < 4; i++)
#pragma unroll
                for (int j = 0; j < 4; j++)
                    s[i][j] = fmaf(ar[i], br[j], s[i][j]);
        }
#pragma unroll
        for (int i = 0; i < 4; i++) {
            int r = r0 + i, qi = q0 + r;
            float pq = sPq[r];
#pragma unroll
            for (int j = 0; j < 4; j++) {
                int c = c0 + j, kj = k0 + c;
                int d1 = kj - qi;
                d1 = max(-MAXREL, min(MAXREL, d1)) + MAXREL;
                float rt = pq - sPk[c];
                if (!(rt >= -50.f && rt <= 50.f)) rt = 0.f;
                float rr = rintf(rt / dtb);
                rr = fminf(50.f, fmaxf(-50.f, rr));
                float sv = s[i][j] + sBias[d1] + sBias[(int)rr + MAXREL];
                s[i][j] = sv;
                sS[r*65 + c] = sv;
            }
        }
        __syncthreads();
        {
            int row = tid >> 2, seg = tid & 3;
            float mx = -INFINITY;
            const float* p = &sS[row*65 + (seg << 4)];
#pragma unroll
            for (int e = 0; e < 16; e++) mx = fmaxf(mx, p[e]);
            sRed[(row<<2) + seg] = mx;
        }
        __syncthreads();
        if (tid < 64) {
            float tm = fmaxf(fmaxf(sRed[tid<<2], sRed[(tid<<2)+1]),
                             fmaxf(sRed[(tid<<2)+2], sRed[(tid<<2)+3]));
            float mo = sM[tid];
            float mn = fmaxf(mo, tm);
            sAl[tid] = expf(mo - mn);
            sM[tid] = mn;
        }
        __syncthreads();
#pragma unroll
        for (int i = 0; i < 4; i++) {
            int r = r0 + i;
            float mn = sM[r];
            float al = sAl[r];
#pragma unroll
            for (int j = 0; j < 4; j++) {
                float p = expf(s[i][j] - mn);
                sS[r*65 + c0 + j] = p;
                acc[i][j] *= al;
            }
        }
        __syncthreads();
        {
            int row = tid >> 2, seg = tid & 3;
            float sm = 0.f;
            const float* p = &sS[row*65 + (seg << 4)];
#pragma unroll
            for (int e = 0; e < 16; e++) sm += p[e];
            sRed[(row<<2) + seg] = sm;
        }
        __syncthreads();
        if (tid < 64) {
            sL[tid] = sL[tid]*sAl[tid]
                    + sRed[tid<<2] + sRed[(tid<<2)+1] + sRed[(tid<<2)+2] + sRed[(tid<<2)+3];
        }
        for (int jj = 0; jj < 64; jj++) {
            float ar[4], br[4];
#pragma unroll
            for (int i = 0; i < 4; i++) ar[i] = sS[(r0+i)*65 + jj];
#pragma unroll
            for (int j = 0; j < 4; j++) br[j] = sV[jj*65 + c0 + j];
#pragma unroll
            for (int i = 0; i < 4; i++)
#pragma unroll
                for (int j = 0; j < 4; j++)
                    acc[i][j] = fmaf(ar[i], br[j], acc[i][j]);
        }
    }
    __syncthreads();

    // epilogue: normalize, write bf16 hi/lo for the out-projection GEMM
#pragma unroll
    for (int i = 0; i < 4; i++) {
        int r = r0 + i;
        float inv = 1.0f / sL[r];
#pragma unroll
        for (int j = 0; j < 4; j++) {
            float val = acc[i][j] * inv;
            size_t idx = (size_t)(b*LL + q0 + r)*EMBED + h*HD + c0 + j;
            __nv_bfloat16 hh = __float2bfloat16(val);
            g_ah[idx] = hh;
            g_al[idx] = __float2bfloat16(val - __bfloat162float(hh));
        }
    }
}

// ---------------- launch ----------------
extern "C" void kernel_launch(void* const* d_in, const int* in_sizes, int n_in,
                              void* d_out, int out_size) {
    const float* query    = (const float*)d_in[0];
    const float* patch    = (const float*)d_in[3];
    const float* in_w     = (const float*)d_in[4];
    const float* in_b     = (const float*)d_in[5];
    const float* out_w    = (const float*)d_in[6];
    const float* out_b    = (const float*)d_in[7];
    const float* rel_bias = (const float*)d_in[8];
    float* out = (float*)d_out;

    dt_kernel<<<BB, 256>>>(patch);

    __nv_bfloat16 *qh, *ql, *w1h, *w1l, *w2h, *w2l;
    cudaGetSymbolAddress((void**)&qh,  g_qh);  cudaGetSymbolAddress((void**)&ql,  g_ql);
    cudaGetSymbolAddress((void**)&w1h, g_w1h); cudaGetSymbolAddress((void**)&w1l, g_w1l);
    cudaGetSymbolAddress((void**)&w2h, g_w2h); cudaGetSymbolAddress((void**)&w2l, g_w2l);
    cvt_kernel<<<(MTOT*EMBED + 255)/256, 256>>>(query, qh, ql, MTOT*EMBED);
    cvt_kernel<<<(N_QKV*EMBED + 255)/256, 256>>>(in_w, w1h, w1l, N_QKV*EMBED);
    cvt_kernel<<<(EMBED*EMBED + 255)/256, 256>>>(out_w, w2h, w2l, EMBED*EMBED);

    gemm_qkv_mma<<<dim3(N_QKV/128, MTOT/128), 256>>>(in_b);

    size_t attn_smem = (size_t)4 * 64 * 65 * sizeof(float);
    cudaFuncSetAttribute(attn_kernel, cudaFuncAttributeMaxDynamicSharedMemorySize, (int)attn_smem);
    attn_kernel<<<dim3(LL/64, BB*HEADS), 256, attn_smem>>>(patch, rel_bias);

    gemm_out_mma<<<dim3(EMBED/128, MTOT/128), 256>>>(out_b, out);
}

// round 4
// speedup vs baseline: 2.5401x; 1.8153x over previous
#include <cuda_runtime.h>
#include <cuda_bf16.h>
#include <math.h>
#include <cstdint>

#define EMBED 768
#define HEADS 12
#define HD 64
#define MAXREL 50
#define BB 4
#define LL 1024
#define MTOT (BB*LL)
#define N_QKV (3*EMBED)

// ---------------- device scratch ----------------
__device__ float g_dt[BB];
// split of input query / weights (GEMM operands)
__device__ __align__(16) __nv_bfloat16 g_xh[MTOT*EMBED];
__device__ __align__(16) __nv_bfloat16 g_xl[MTOT*EMBED];
__device__ __align__(16) __nv_bfloat16 g_w1h[N_QKV*EMBED];
__device__ __align__(16) __nv_bfloat16 g_w1l[N_QKV*EMBED];
__device__ __align__(16) __nv_bfloat16 g_w2h[EMBED*EMBED];
__device__ __align__(16) __nv_bfloat16 g_w2l[EMBED*EMBED];
// per-head q/k (row-major [bh][l][d]) and v transposed ([bh][d][l]), bf16 hi/lo
__device__ __align__(16) __nv_bfloat16 g_aqh[BB*HEADS*LL*HD];
__device__ __align__(16) __nv_bfloat16 g_aql[BB*HEADS*LL*HD];
__device__ __align__(16) __nv_bfloat16 g_akh[BB*HEADS*LL*HD];
__device__ __align__(16) __nv_bfloat16 g_akl[BB*HEADS*LL*HD];
__device__ __align__(16) __nv_bfloat16 g_avh[BB*HEADS*LL*HD];
__device__ __align__(16) __nv_bfloat16 g_avl[BB*HEADS*LL*HD];
// attention output hi/lo for GEMM2
__device__ __align__(16) __nv_bfloat16 g_ah[MTOT*EMBED];
__device__ __align__(16) __nv_bfloat16 g_al[MTOT*EMBED];

// ---------------- mma.sync helper (bf16, fp32 accum) ----------------
__device__ __forceinline__ void mma_bf16(float* c, const unsigned* a, const unsigned* b) {
    asm volatile(
        "mma.sync.aligned.m16n8k16.row.col.f32.bf16.bf16.f32 "
        "{%0,%1,%2,%3}, {%4,%5,%6,%7}, {%8,%9}, {%0,%1,%2,%3};"
        : "+f"(c[0]), "+f"(c[1]), "+f"(c[2]), "+f"(c[3])
        : "r"(a[0]), "r"(a[1]), "r"(a[2]), "r"(a[3]), "r"(b[0]), "r"(b[1]));
}

__device__ __forceinline__ unsigned pack_bf16(float a, float b) {
    __nv_bfloat162 t = __floats2bfloat162_rn(a, b);
    return *(unsigned*)&t;
}
__device__ __forceinline__ float bf_hi(float x) {
    return __bfloat162float(__float2bfloat16(x));
}

// ---------------- fp32 -> bf16 hi/lo split ----------------
__global__ void cvt_kernel(const float* __restrict__ src,
                           __nv_bfloat16* __restrict__ hi,
                           __nv_bfloat16* __restrict__ lo, int n) {
    int i = blockIdx.x * blockDim.x + threadIdx.x;
    if (i < n) {
        float x = src[i];
        __nv_bfloat16 h = __float2bfloat16(x);
        hi[i] = h;
        lo[i] = __float2bfloat16(x - __bfloat162float(h));
    }
}

// ---------------- dt = guarded nanmedian of deltas ----------------
__global__ void dt_kernel(const float* __restrict__ patch) {
    int b = blockIdx.x;
    int tid = threadIdx.x;
    __shared__ float sd[LL-1];
    __shared__ int cnt;
    __shared__ float sLo, sHi;
    if (tid == 0) { cnt = 0; sLo = nanf(""); sHi = nanf(""); }
    __syncthreads();
    int local = 0;
    for (int i = tid; i < LL-1; i += blockDim.x) {
        float d = patch[b*LL + i + 1] - patch[b*LL + i];
        sd[i] = d;
        if (!isnan(d)) local++;
    }
    if (local) atomicAdd(&cnt, local);
    __syncthreads();
    int n = cnt;
    if (n > 0) {
        int kLo = (n - 1) >> 1, kHi = n >> 1;
        for (int i = tid; i < LL-1; i += blockDim.x) {
            float x = sd[i];
            if (isnan(x)) continue;
            int less = 0, eq = 0;
            for (int j = 0; j < LL-1; j++) {
                float y = sd[j];
                less += (y < x);
                eq   += (y == x);
            }
            if (less <= kLo && kLo < less + eq) sLo = x;
            if (less <= kHi && kHi < less + eq) sHi = x;
        }
    }
    __syncthreads();
    if (tid == 0) {
        float med = 0.5f * (sLo + sHi);
        if (n == 0) med = nanf("");
        g_dt[b] = (isfinite(med) && med > 0.f) ? med : 1.0f;
    }
}

// ---------------- shared tile layout for mma GEMM ----------------
#define ROWB 80
struct GemmSmem {
    __align__(16) char ah[128*ROWB];
    __align__(16) char al[128*ROWB];
    __align__(16) char bh[128*ROWB];
    __align__(16) char bl[128*ROWB];
};

__device__ __forceinline__ void gemm_mainloop(
    const __nv_bfloat16* __restrict__ Ah, const __nv_bfloat16* __restrict__ Al,
    const __nv_bfloat16* __restrict__ Bh, const __nv_bfloat16* __restrict__ Bl,
    int m0, int n0, int K, GemmSmem* sm, float acc[4][4][4]) {
    int tid = threadIdx.x;
    int lane = tid & 31, wid = tid >> 5;
    int wm = wid & 1, wn = wid >> 1;
    int fr = lane >> 2, fc = lane & 3;

    for (int kc = 0; kc < K; kc += 32) {
#pragma unroll
        for (int i = 0; i < 2; i++) {
            int id = tid + (i << 8);
            int row = id >> 2, part = id & 3;
            size_t ga = (size_t)(m0 + row) * K + kc + part * 8;
            size_t gb = (size_t)(n0 + row) * K + kc + part * 8;
            int so = row * ROWB + part * 16;
            *(uint4*)(sm->ah + so) = *(const uint4*)(Ah + ga);
            *(uint4*)(sm->al + so) = *(const uint4*)(Al + ga);
            *(uint4*)(sm->bh + so) = *(const uint4*)(Bh + gb);
            *(uint4*)(sm->bl + so) = *(const uint4*)(Bl + gb);
        }
        __syncthreads();

#pragma unroll
        for (int kk = 0; kk < 2; kk++) {
            unsigned afh[4][4], afl[4][4], bf[4][2];
#pragma unroll
            for (int mt = 0; mt < 4; mt++) {
                int base = (wm*64 + mt*16 + fr) * ROWB + kk*32 + fc*4;
                afh[mt][0] = *(const unsigned*)(sm->ah + base);
                afh[mt][1] = *(const unsigned*)(sm->ah + base + 8*ROWB);
                afh[mt][2] = *(const unsigned*)(sm->ah + base + 16);
                afh[mt][3] = *(const unsigned*)(sm->ah + base + 8*ROWB + 16);
                afl[mt][0] = *(const unsigned*)(sm->al + base);
                afl[mt][1] = *(const unsigned*)(sm->al + base + 8*ROWB);
                afl[mt][2] = *(const unsigned*)(sm->al + base + 16);
                afl[mt][3] = *(const unsigned*)(sm->al + base + 8*ROWB + 16);
            }
#pragma unroll
            for (int nt = 0; nt < 4; nt++) {
                int base = (wn*32 + nt*8 + fr) * ROWB + kk*32 + fc*4;
                bf[nt][0] = *(const unsigned*)(sm->bh + base);
                bf[nt][1] = *(const unsigned*)(sm->bh + base + 16);
            }
#pragma unroll
            for (int mt = 0; mt < 4; mt++)
#pragma unroll
                for (int nt = 0; nt < 4; nt++) {
                    mma_bf16(acc[mt][nt], afh[mt], bf[nt]);
                    mma_bf16(acc[mt][nt], afl[mt], bf[nt]);
                }
#pragma unroll
            for (int nt = 0; nt < 4; nt++) {
                int base = (wn*32 + nt*8 + fr) * ROWB + kk*32 + fc*4;
                bf[nt][0] = *(const unsigned*)(sm->bl + base);
                bf[nt][1] = *(const unsigned*)(sm->bl + base + 16);
            }
#pragma unroll
            for (int mt = 0; mt < 4; mt++)
#pragma unroll
                for (int nt = 0; nt < 4; nt++)
                    mma_bf16(acc[mt][nt], afh[mt], bf[nt]);
        }
        __syncthreads();
    }
}

// ---------------- GEMM1: qkv projection, split+scatter epilogue ----------------
__global__ __launch_bounds__(256) void gemm_qkv_mma(const float* __restrict__ bias) {
    __shared__ GemmSmem sm;
    float acc[4][4][4] = {};
    int m0 = blockIdx.y << 7, n0 = blockIdx.x << 7;
    gemm_mainloop(g_xh, g_xl, g_w1h, g_w1l, m0, n0, EMBED, &sm, acc);

    int tid = threadIdx.x;
    int lane = tid & 31, wid = tid >> 5;
    int wm = wid & 1, wn = wid >> 1;
    int fr = lane >> 2, fc = lane & 3;
#pragma unroll
    for (int mt = 0; mt < 4; mt++) {
#pragma unroll
        for (int half = 0; half < 2; half++) {
            int m = m0 + wm*64 + mt*16 + fr + half*8;
            int b = m >> 10, l = m & (LL - 1);
#pragma unroll
            for (int nt = 0; nt < 4; nt++) {
                int n = n0 + wn*32 + nt*8 + 2*fc;
                float v0 = acc[mt][nt][half*2 + 0] + __ldg(&bias[n]);
                float v1 = acc[mt][nt][half*2 + 1] + __ldg(&bias[n+1]);
                int part = n / EMBED;
                int hn = n - part * EMBED;
                int h = hn >> 6, d = hn & 63;
                int bh = b * HEADS + h;
                if (part == 0) {
                    v0 *= 0.125f; v1 *= 0.125f;
                    int idx = (bh * LL + l) * HD + d;
                    *(unsigned*)&g_aqh[idx] = pack_bf16(v0, v1);
                    *(unsigned*)&g_aql[idx] = pack_bf16(v0 - bf_hi(v0), v1 - bf_hi(v1));
                } else if (part == 1) {
                    int idx = (bh * LL + l) * HD + d;
                    *(unsigned*)&g_akh[idx] = pack_bf16(v0, v1);
                    *(unsigned*)&g_akl[idx] = pack_bf16(v0 - bf_hi(v0), v1 - bf_hi(v1));
                } else {
                    // transposed: [bh][d][l]
                    int i0 = (bh * HD + d) * LL + l;
                    int i1 = (bh * HD + d + 1) * LL + l;
                    g_avh[i0] = __float2bfloat16(v0);
                    g_avl[i0] = __float2bfloat16(v0 - bf_hi(v0));
                    g_avh[i1] = __float2bfloat16(v1);
                    g_avl[i1] = __float2bfloat16(v1 - bf_hi(v1));
                }
            }
        }
    }
}

// ---------------- GEMM2: out projection ----------------
__global__ __launch_bounds__(256) void gemm_out_mma(const float* __restrict__ bias,
                                                    float* __restrict__ out) {
    __shared__ GemmSmem sm;
    float acc[4][4][4] = {};
    int m0 = blockIdx.y << 7, n0 = blockIdx.x << 7;
    gemm_mainloop(g_ah, g_al, g_w2h, g_w2l, m0, n0, EMBED, &sm, acc);

    int tid = threadIdx.x;
    int lane = tid & 31, wid = tid >> 5;
    int wm = wid & 1, wn = wid >> 1;
    int fr = lane >> 2, fc = lane & 3;
#pragma unroll
    for (int mt = 0; mt < 4; mt++) {
#pragma unroll
        for (int half = 0; half < 2; half++) {
            int m = m0 + wm*64 + mt*16 + fr + half*8;
#pragma unroll
            for (int nt = 0; nt < 4; nt++) {
                int n = n0 + wn*32 + nt*8 + 2*fc;
                float v0 = acc[mt][nt][half*2 + 0] + __ldg(&bias[n]);
                float v1 = acc[mt][nt][half*2 + 1] + __ldg(&bias[n+1]);
                *(float2*)&out[(size_t)m * EMBED + n] = make_float2(v0, v1);
            }
        }
    }
}

// ---------------- tensor-core flash attention with dual relative bias ----------------
// grid (L/128, B*H), 256 threads (8 warps x 16 q-rows)
#define ATP 72   // bf16 elements per smem row (64 + 8 pad)
__global__ __launch_bounds__(256) void attn_mma(const float* __restrict__ patch,
                                                const float* __restrict__ rel_bias) {
    __shared__ __nv_bfloat16 sKh[64*ATP], sKl[64*ATP], sVh[64*ATP], sVl[64*ATP];
    __shared__ float sBias[104], sPq[128], sPk[64];

    int tid = threadIdx.x;
    int lane = tid & 31, w = tid >> 5;
    int fr = lane >> 2, fc = lane & 3;
    int bh = blockIdx.y;
    int b = bh / HEADS, h = bh - b * HEADS;
    int q0 = blockIdx.x << 7;
    float inv_dt = 1.0f / g_dt[b];

    if (tid < 101) sBias[tid] = rel_bias[h*101 + tid];
    if (tid < 128) sPq[tid] = patch[b*LL + q0 + tid];

    const __nv_bfloat16* gqh = g_aqh + (size_t)bh*LL*HD;
    const __nv_bfloat16* gql = g_aql + (size_t)bh*LL*HD;
    const __nv_bfloat16* gkh = g_akh + (size_t)bh*LL*HD;
    const __nv_bfloat16* gkl = g_akl + (size_t)bh*LL*HD;
    const __nv_bfloat16* gvh = g_avh + (size_t)bh*HD*LL;
    const __nv_bfloat16* gvl = g_avl + (size_t)bh*HD*LL;

    // Q fragments (held in registers for the whole kernel)
    unsigned qh[4][4], ql[4][4];
    int qr = q0 + w*16;
#pragma unroll
    for (int ks = 0; ks < 4; ks++) {
        int k = ks*16 + 2*fc;
        qh[ks][0] = *(const unsigned*)&gqh[(qr+fr)*HD + k];
        qh[ks][1] = *(const unsigned*)&gqh[(qr+fr+8)*HD + k];
        qh[ks][2] = *(const unsigned*)&gqh[(qr+fr)*HD + k + 8];
        qh[ks][3] = *(const unsigned*)&gqh[(qr+fr+8)*HD + k + 8];
        ql[ks][0] = *(const unsigned*)&gql[(qr+fr)*HD + k];
        ql[ks][1] = *(const unsigned*)&gql[(qr+fr+8)*HD + k];
        ql[ks][2] = *(const unsigned*)&gql[(qr+fr)*HD + k + 8];
        ql[ks][3] = *(const unsigned*)&gql[(qr+fr+8)*HD + k + 8];
    }

    float accO[8][4] = {};
    float m0 = -INFINITY, m1 = -INFINITY, l0 = 0.f, l1 = 0.f;
    int i0 = qr + fr, i1 = i0 + 8;
    float pq0 = 0.f, pq1 = 0.f;

    for (int k0 = 0; k0 < LL; k0 += 64) {
        __syncthreads();
        // load K/Vt tiles (64 rows x 64 bf16 each, hi+lo)
#pragma unroll
        for (int i = 0; i < 2; i++) {
            int id = tid + (i << 8);        // 0..511
            int row = id >> 3, seg = (id & 7) * 8;
            *(uint4*)&sKh[row*ATP + seg] = *(const uint4*)&gkh[(k0+row)*HD + seg];
            *(uint4*)&sKl[row*ATP + seg] = *(const uint4*)&gkl[(k0+row)*HD + seg];
            *(uint4*)&sVh[row*ATP + seg] = *(const uint4*)&gvh[row*LL + k0 + seg];
            *(uint4*)&sVl[row*ATP + seg] = *(const uint4*)&gvl[row*LL + k0 + seg];
        }
        if (tid < 64) sPk[tid] = patch[b*LL + k0 + tid];
        __syncthreads();
        if (k0 == 0) { pq0 = sPq[w*16 + fr]; pq1 = sPq[w*16 + fr + 8]; }

        // ---- S = Q K^T (bf16 split, 3 passes) ----
        float accS[8][4] = {};
#pragma unroll
        for (int ks = 0; ks < 4; ks++) {
            unsigned bkh[8][2], bkl[8][2];
#pragma unroll
            for (int nt = 0; nt < 8; nt++) {
                int base = (nt*8 + fr)*ATP + ks*16 + 2*fc;
                bkh[nt][0] = *(const unsigned*)&sKh[base];
                bkh[nt][1] = *(const unsigned*)&sKh[base + 8];
                bkl[nt][0] = *(const unsigned*)&sKl[base];
                bkl[nt][1] = *(const unsigned*)&sKl[base + 8];
            }
#pragma unroll
            for (int nt = 0; nt < 8; nt++) {
                mma_bf16(accS[nt], qh[ks], bkh[nt]);
                mma_bf16(accS[nt], qh[ks], bkl[nt]);
                mma_bf16(accS[nt], ql[ks], bkh[nt]);
            }
        }

        // ---- bias + online softmax ----
        float mx0 = -INFINITY, mx1 = -INFINITY;
#pragma unroll
        for (int nt = 0; nt < 8; nt++) {
#pragma unroll
            for (int e = 0; e < 2; e++) {
                int jl = nt*8 + 2*fc + e;
                int j = k0 + jl;
                float pk = sPk[jl];
                // row i0 (c0,c1)
                int d1 = min(MAXREL, max(-MAXREL, j - i0)) + MAXREL;
                float rt = pq0 - pk;
                if (!(rt >= -50.f && rt <= 50.f)) rt = 0.f;
                float rr = fminf(50.f, fmaxf(-50.f, rintf(rt * inv_dt)));
                float s0 = accS[nt][e] + sBias[d1] + sBias[(int)rr + MAXREL];
                accS[nt][e] = s0;
                mx0 = fmaxf(mx0, s0);
                // row i1 (c2,c3)
                int d2 = min(MAXREL, max(-MAXREL, j - i1)) + MAXREL;
                float rt1 = pq1 - pk;
                if (!(rt1 >= -50.f && rt1 <= 50.f)) rt1 = 0.f;
                float rr1 = fminf(50.f, fmaxf(-50.f, rintf(rt1 * inv_dt)));
                float s1 = accS[nt][2+e] + sBias[d2] + sBias[(int)rr1 + MAXREL];
                accS[nt][2+e] = s1;
                mx1 = fmaxf(mx1, s1);
            }
        }
        mx0 = fmaxf(mx0, __shfl_xor_sync(0xffffffffu, mx0, 1));
        mx0 = fmaxf(mx0, __shfl_xor_sync(0xffffffffu, mx0, 2));
        mx1 = fmaxf(mx1, __shfl_xor_sync(0xffffffffu, mx1, 1));
        mx1 = fmaxf(mx1, __shfl_xor_sync(0xffffffffu, mx1, 2));
        float mn0 = fmaxf(m0, mx0), mn1 = fmaxf(m1, mx1);
        float al0 = __expf(m0 - mn0), al1 = __expf(m1 - mn1);
        m0 = mn0; m1 = mn1;
        l0 *= al0; l1 *= al1;
#pragma unroll
        for (int nt = 0; nt < 8; nt++) {
            accO[nt][0] *= al0; accO[nt][1] *= al0;
            accO[nt][2] *= al1; accO[nt][3] *= al1;
        }

        // ---- P = exp(S - m), split hi/lo, pack register-direct A fragments ----
        unsigned pfh[4][4], pfl[4][4];
#pragma unroll
        for (int nt = 0; nt < 8; nt++) {
            float p0 = __expf(accS[nt][0] - m0);
            float p1 = __expf(accS[nt][1] - m0);
            float p2 = __expf(accS[nt][2] - m1);
            float p3 = __expf(accS[nt][3] - m1);
            l0 += p0 + p1; l1 += p2 + p3;
            int kc = nt >> 1, off = (nt & 1) << 1;
            pfh[kc][off]   = pack_bf16(p0, p1);
            pfh[kc][off+1] = pack_bf16(p2, p3);
            pfl[kc][off]   = pack_bf16(p0 - bf_hi(p0), p1 - bf_hi(p1));
            pfl[kc][off+1] = pack_bf16(p2 - bf_hi(p2), p3 - bf_hi(p3));
        }

        // ---- O += P Vt (3 passes) ----
#pragma unroll
        for (int kc = 0; kc < 4; kc++) {
            unsigned bvh[8][2], bvl[8][2];
#pragma unroll
            for (int nt = 0; nt < 8; nt++) {
                int base = (nt*8 + fr)*ATP + kc*16 + 2*fc;
                bvh[nt][0] = *(const unsigned*)&sVh[base];
                bvh[nt][1] = *(const unsigned*)&sVh[base + 8];
                bvl[nt][0] = *(const unsigned*)&sVl[base];
                bvl[nt][1] = *(const unsigned*)&sVl[base + 8];
            }
#pragma unroll
            for (int nt = 0; nt < 8; nt++) {
                mma_bf16(accO[nt], pfh[kc], bvh[nt]);
                mma_bf16(accO[nt], pfh[kc], bvl[nt]);
                mma_bf16(accO[nt], pfl[kc], bvh[nt]);
            }
        }
    }

    // row sums across quad
    l0 += __shfl_xor_sync(0xffffffffu, l0, 1);
    l0 += __shfl_xor_sync(0xffffffffu, l0, 2);
    l1 += __shfl_xor_sync(0xffffffffu, l1, 1);
    l1 += __shfl_xor_sync(0xffffffffu, l1, 2);
    float inv0 = 1.0f / l0, inv1 = 1.0f / l1;

    // epilogue: write bf16 hi/lo attention output [m][768]
#pragma unroll
    for (int nt = 0; nt < 8; nt++) {
        int d = nt*8 + 2*fc;
        size_t r0 = (size_t)(b*LL + i0) * EMBED + h*HD + d;
        size_t r1 = (size_t)(b*LL + i1) * EMBED + h*HD + d;
        float v0 = accO[nt][0] * inv0, v1 = accO[nt][1] * inv0;
        float v2 = accO[nt][2] * inv1, v3 = accO[nt][3] * inv1;
        *(unsigned*)&g_ah[r0] = pack_bf16(v0, v1);
        *(unsigned*)&g_al[r0] = pack_bf16(v0 - bf_hi(v0), v1 - bf_hi(v1));
        *(unsigned*)&g_ah[r1] = pack_bf16(v2, v3);
        *(unsigned*)&g_al[r1] = pack_bf16(v2 - bf_hi(v2), v3 - bf_hi(v3));
    }
}

// ---------------- launch ----------------
extern "C" void kernel_launch(void* const* d_in, const int* in_sizes, int n_in,
                              void* d_out, int out_size) {
    const float* query    = (const float*)d_in[0];
    const float* patch    = (const float*)d_in[3];
    const float* in_w     = (const float*)d_in[4];
    const float* in_b     = (const float*)d_in[5];
    const float* out_w    = (const float*)d_in[6];
    const float* out_b    = (const float*)d_in[7];
    const float* rel_bias = (const float*)d_in[8];
    float* out = (float*)d_out;

    dt_kernel<<<BB, 256>>>(patch);

    __nv_bfloat16 *xh, *xl, *w1h, *w1l, *w2h, *w2l;
    cudaGetSymbolAddress((void**)&xh,  g_xh);  cudaGetSymbolAddress((void**)&xl,  g_xl);
    cudaGetSymbolAddress((void**)&w1h, g_w1h); cudaGetSymbolAddress((void**)&w1l, g_w1l);
    cudaGetSymbolAddress((void**)&w2h, g_w2h); cudaGetSymbolAddress((void**)&w2l, g_w2l);
    cvt_kernel<<<(MTOT*EMBED + 255)/256, 256>>>(query, xh, xl, MTOT*EMBED);
    cvt_kernel<<<(N_QKV*EMBED + 255)/256, 256>>>(in_w, w1h, w1l, N_QKV*EMBED);
    cvt_kernel<<<(EMBED*EMBED + 255)/256, 256>>>(out_w, w2h, w2l, EMBED*EMBED);

    gemm_qkv_mma<<<dim3(N_QKV/128, MTOT/128), 256>>>(in_b);

    attn_mma<<<dim3(LL/128, BB*HEADS), 256>>>(patch, rel_bias);

    gemm_out_mma<<<dim3(EMBED/128, MTOT/128), 256>>>(out_b, out);
}

// round 5
// speedup vs baseline: 2.8866x; 1.1364x over previous
#include <cuda_runtime.h>
#include <cuda_bf16.h>
#include <math.h>
#include <cstdint>

#define EMBED 768
#define HEADS 12
#define HD 64
#define MAXREL 50
#define BB 4
#define LL 1024
#define MTOT (BB*LL)
#define N_QKV (3*EMBED)

// ---------------- device scratch ----------------
__device__ float g_dt[BB];
__device__ __align__(16) __nv_bfloat16 g_xh[MTOT*EMBED];
__device__ __align__(16) __nv_bfloat16 g_xl[MTOT*EMBED];
__device__ __align__(16) __nv_bfloat16 g_w1h[N_QKV*EMBED];
__device__ __align__(16) __nv_bfloat16 g_w1l[N_QKV*EMBED];
__device__ __align__(16) __nv_bfloat16 g_w2h[EMBED*EMBED];
__device__ __align__(16) __nv_bfloat16 g_w2l[EMBED*EMBED];
__device__ __align__(16) __nv_bfloat16 g_aqh[BB*HEADS*LL*HD];
__device__ __align__(16) __nv_bfloat16 g_aql[BB*HEADS*LL*HD];
__device__ __align__(16) __nv_bfloat16 g_akh[BB*HEADS*LL*HD];
__device__ __align__(16) __nv_bfloat16 g_akl[BB*HEADS*LL*HD];
__device__ __align__(16) __nv_bfloat16 g_avh[BB*HEADS*LL*HD];
__device__ __align__(16) __nv_bfloat16 g_avl[BB*HEADS*LL*HD];
__device__ __align__(16) __nv_bfloat16 g_ah[MTOT*EMBED];
__device__ __align__(16) __nv_bfloat16 g_al[MTOT*EMBED];

// ---------------- helpers ----------------
__device__ __forceinline__ void mma_bf16(float* c, const unsigned* a, const unsigned* b) {
    asm volatile(
        "mma.sync.aligned.m16n8k16.row.col.f32.bf16.bf16.f32 "
        "{%0,%1,%2,%3}, {%4,%5,%6,%7}, {%8,%9}, {%0,%1,%2,%3};"
        : "+f"(c[0]), "+f"(c[1]), "+f"(c[2]), "+f"(c[3])
        : "r"(a[0]), "r"(a[1]), "r"(a[2]), "r"(a[3]), "r"(b[0]), "r"(b[1]));
}
__device__ __forceinline__ unsigned pack_bf16(float a, float b) {
    __nv_bfloat162 t = __floats2bfloat162_rn(a, b);
    return *(unsigned*)&t;
}
__device__ __forceinline__ float bf_hi(float x) {
    return __bfloat162float(__float2bfloat16(x));
}
__device__ __forceinline__ uint32_t smem_u32(const void* p) {
    uint32_t a;
    asm("{ .reg .u64 t; cvta.to.shared.u64 t, %1; cvt.u32.u64 %0, t; }" : "=r"(a) : "l"(p));
    return a;
}
__device__ __forceinline__ void cp16(void* dst, const void* src) {
    asm volatile("cp.async.cg.shared.global [%0], [%1], 16;"
        :: "r"(smem_u32(dst)), "l"(src));
}
#define CP_COMMIT() asm volatile("cp.async.commit_group;" ::: "memory")
#define CP_WAIT(n)  asm volatile("cp.async.wait_group %0;" :: "n"(n) : "memory")

// ---------------- fp32 -> bf16 hi/lo split (x4 vectorized) ----------------
__global__ void cvt_kernel(const float4* __restrict__ src,
                           uint2* __restrict__ hi, uint2* __restrict__ lo, int n4) {
    int i = blockIdx.x * blockDim.x + threadIdx.x;
    if (i < n4) {
        float4 x = src[i];
        unsigned h0 = pack_bf16(x.x, x.y), h1 = pack_bf16(x.z, x.w);
        hi[i] = make_uint2(h0, h1);
        lo[i] = make_uint2(pack_bf16(x.x - bf_hi(x.x), x.y - bf_hi(x.y)),
                           pack_bf16(x.z - bf_hi(x.z), x.w - bf_hi(x.w)));
    }
}

// ---------------- dt = guarded nanmedian of deltas ----------------
__global__ void dt_kernel(const float* __restrict__ patch) {
    int b = blockIdx.x;
    int tid = threadIdx.x;
    __shared__ float sd[LL-1];
    __shared__ int cnt;
    __shared__ float sLo, sHi;
    if (tid == 0) { cnt = 0; sLo = nanf(""); sHi = nanf(""); }
    __syncthreads();
    int local = 0;
    for (int i = tid; i < LL-1; i += blockDim.x) {
        float d = patch[b*LL + i + 1] - patch[b*LL + i];
        sd[i] = d;
        if (!isnan(d)) local++;
    }
    if (local) atomicAdd(&cnt, local);
    __syncthreads();
    int n = cnt;
    if (n > 0) {
        int kLo = (n - 1) >> 1, kHi = n >> 1;
        for (int i = tid; i < LL-1; i += blockDim.x) {
            float x = sd[i];
            if (isnan(x)) continue;
            int less = 0, eq = 0;
            for (int j = 0; j < LL-1; j++) {
                float y = sd[j];
                less += (y < x);
                eq   += (y == x);
            }
            if (less <= kLo && kLo < less + eq) sLo = x;
            if (less <= kHi && kHi < less + eq) sHi = x;
        }
    }
    __syncthreads();
    if (tid == 0) {
        float med = 0.5f * (sLo + sHi);
        if (n == 0) med = nanf("");
        g_dt[b] = (isfinite(med) && med > 0.f) ? med : 1.0f;
    }
}

// ---------------- GEMM with 2-stage cp.async pipeline ----------------
#define ROWB 80
#define GARR (128*ROWB)
// dynamic smem layout: [2 stages][4 arrays][128*ROWB bytes]
#define GSMEM_TOTAL (2*4*GARR)

__device__ __forceinline__ void gemm_load_stage(
    char* st, const __nv_bfloat16* Ah, const __nv_bfloat16* Al,
    const __nv_bfloat16* Bh, const __nv_bfloat16* Bl,
    int m0, int n0, int K, int kc, int tid) {
#pragma unroll
    for (int i = 0; i < 2; i++) {
        int id = tid + (i << 8);
        int row = id >> 2, part = id & 3;
        size_t ga = (size_t)(m0 + row) * K + kc + part * 8;
        size_t gb = (size_t)(n0 + row) * K + kc + part * 8;
        int so = row * ROWB + part * 16;
        cp16(st + 0*GARR + so, Ah + ga);
        cp16(st + 1*GARR + so, Al + ga);
        cp16(st + 2*GARR + so, Bh + gb);
        cp16(st + 3*GARR + so, Bl + gb);
    }
    CP_COMMIT();
}

__device__ __forceinline__ void gemm_mainloop(
    const __nv_bfloat16* __restrict__ Ah, const __nv_bfloat16* __restrict__ Al,
    const __nv_bfloat16* __restrict__ Bh, const __nv_bfloat16* __restrict__ Bl,
    int m0, int n0, int K, char* dyn, float acc[4][4][4]) {
    int tid = threadIdx.x;
    int lane = tid & 31, wid = tid >> 5;
    int wm = wid & 1, wn = wid >> 1;
    int fr = lane >> 2, fc = lane & 3;

    gemm_load_stage(dyn, Ah, Al, Bh, Bl, m0, n0, K, 0, tid);

    for (int kc = 0, s = 0; kc < K; kc += 32, s ^= 1) {
        if (kc + 32 < K) {
            gemm_load_stage(dyn + (s^1)*4*GARR, Ah, Al, Bh, Bl, m0, n0, K, kc + 32, tid);
            CP_WAIT(1);
        } else {
            CP_WAIT(0);
        }
        __syncthreads();
        char* ah = dyn + s*4*GARR;
        char* al = ah + GARR;
        char* bh = al + GARR;
        char* bl = bh + GARR;
#pragma unroll
        for (int kk = 0; kk < 2; kk++) {
            unsigned afh[4][4], afl[4][4], bf[4][2];
#pragma unroll
            for (int mt = 0; mt < 4; mt++) {
                int base = (wm*64 + mt*16 + fr) * ROWB + kk*32 + fc*4;
                afh[mt][0] = *(const unsigned*)(ah + base);
                afh[mt][1] = *(const unsigned*)(ah + base + 8*ROWB);
                afh[mt][2] = *(const unsigned*)(ah + base + 16);
                afh[mt][3] = *(const unsigned*)(ah + base + 8*ROWB + 16);
                afl[mt][0] = *(const unsigned*)(al + base);
                afl[mt][1] = *(const unsigned*)(al + base + 8*ROWB);
                afl[mt][2] = *(const unsigned*)(al + base + 16);
                afl[mt][3] = *(const unsigned*)(al + base + 8*ROWB + 16);
            }
#pragma unroll
            for (int nt = 0; nt < 4; nt++) {
                int base = (wn*32 + nt*8 + fr) * ROWB + kk*32 + fc*4;
                bf[nt][0] = *(const unsigned*)(bh + base);
                bf[nt][1] = *(const unsigned*)(bh + base + 16);
            }
#pragma unroll
            for (int mt = 0; mt < 4; mt++)
#pragma unroll
                for (int nt = 0; nt < 4; nt++) {
                    mma_bf16(acc[mt][nt], afh[mt], bf[nt]);
                    mma_bf16(acc[mt][nt], afl[mt], bf[nt]);
                }
#pragma unroll
            for (int nt = 0; nt < 4; nt++) {
                int base = (wn*32 + nt*8 + fr) * ROWB + kk*32 + fc*4;
                bf[nt][0] = *(const unsigned*)(bl + base);
                bf[nt][1] = *(const unsigned*)(bl + base + 16);
            }
#pragma unroll
            for (int mt = 0; mt < 4; mt++)
#pragma unroll
                for (int nt = 0; nt < 4; nt++)
                    mma_bf16(acc[mt][nt], afh[mt], bf[nt]);
        }
        __syncthreads();
    }
}

// ---------------- GEMM1: qkv projection ----------------
__global__ __launch_bounds__(256) void gemm_qkv_mma(const float* __restrict__ bias) {
    extern __shared__ char dyn[];
    float acc[4][4][4] = {};
    int m0 = blockIdx.y << 7, n0 = blockIdx.x << 7;
    gemm_mainloop(g_xh, g_xl, g_w1h, g_w1l, m0, n0, EMBED, dyn, acc);

    int tid = threadIdx.x;
    int lane = tid & 31, wid = tid >> 5;
    int wm = wid & 1, wn = wid >> 1;
    int fr = lane >> 2, fc = lane & 3;
#pragma unroll
    for (int mt = 0; mt < 4; mt++) {
#pragma unroll
        for (int half = 0; half < 2; half++) {
            int m = m0 + wm*64 + mt*16 + fr + half*8;
            int b = m >> 10, l = m & (LL - 1);
#pragma unroll
            for (int nt = 0; nt < 4; nt++) {
                int n = n0 + wn*32 + nt*8 + 2*fc;
                float v0 = acc[mt][nt][half*2 + 0] + __ldg(&bias[n]);
                float v1 = acc[mt][nt][half*2 + 1] + __ldg(&bias[n+1]);
                int part = n / EMBED;
                int hn = n - part * EMBED;
                int h = hn >> 6, d = hn & 63;
                int bh = b * HEADS + h;
                if (part == 0) {
                    v0 *= 0.125f; v1 *= 0.125f;
                    int idx = (bh * LL + l) * HD + d;
                    *(unsigned*)&g_aqh[idx] = pack_bf16(v0, v1);
                    *(unsigned*)&g_aql[idx] = pack_bf16(v0 - bf_hi(v0), v1 - bf_hi(v1));
                } else if (part == 1) {
                    int idx = (bh * LL + l) * HD + d;
                    *(unsigned*)&g_akh[idx] = pack_bf16(v0, v1);
                    *(unsigned*)&g_akl[idx] = pack_bf16(v0 - bf_hi(v0), v1 - bf_hi(v1));
                } else {
                    int i0 = (bh * HD + d) * LL + l;
                    int i1 = (bh * HD + d + 1) * LL + l;
                    g_avh[i0] = __float2bfloat16(v0);
                    g_avl[i0] = __float2bfloat16(v0 - bf_hi(v0));
                    g_avh[i1] = __float2bfloat16(v1);
                    g_avl[i1] = __float2bfloat16(v1 - bf_hi(v1));
                }
            }
        }
    }
}

// ---------------- GEMM2: out projection ----------------
__global__ __launch_bounds__(256) void gemm_out_mma(const float* __restrict__ bias,
                                                    float* __restrict__ out) {
    extern __shared__ char dyn[];
    float acc[4][4][4] = {};
    int m0 = blockIdx.y << 7, n0 = blockIdx.x << 7;
    gemm_mainloop(g_ah, g_al, g_w2h, g_w2l, m0, n0, EMBED, dyn, acc);

    int tid = threadIdx.x;
    int lane = tid & 31, wid = tid >> 5;
    int wm = wid & 1, wn = wid >> 1;
    int fr = lane >> 2, fc = lane & 3;
#pragma unroll
    for (int mt = 0; mt < 4; mt++) {
#pragma unroll
        for (int half = 0; half < 2; half++) {
            int m = m0 + wm*64 + mt*16 + fr + half*8;
#pragma unroll
            for (int nt = 0; nt < 4; nt++) {
                int n = n0 + wn*32 + nt*8 + 2*fc;
                float v0 = acc[mt][nt][half*2 + 0] + __ldg(&bias[n]);
                float v1 = acc[mt][nt][half*2 + 1] + __ldg(&bias[n+1]);
                *(float2*)&out[(size_t)m * EMBED + n] = make_float2(v0, v1);
            }
        }
    }
}

// ---------------- tensor-core flash attention, 2-stage pipelined ----------------
#define ATP 72
#define AARR (64*ATP*2)              // bytes per bf16 array (64 rows x 72 x 2B)
#define ASTAGE (4*AARR + 256)        // 4 arrays + 64-float patch vector
#define ASMEM_TOTAL (2*ASTAGE)

__device__ __forceinline__ void attn_load_stage(
    char* st, const __nv_bfloat16* gkh, const __nv_bfloat16* gkl,
    const __nv_bfloat16* gvh, const __nv_bfloat16* gvl,
    const float* patch_k, int k0, int tid) {
#pragma unroll
    for (int i = 0; i < 2; i++) {
        int id = tid + (i << 8);
        int row = id >> 3, seg = (id & 7) * 8;
        int so = (row * ATP + seg) * 2;
        cp16(st + 0*AARR + so, gkh + (k0+row)*HD + seg);
        cp16(st + 1*AARR + so, gkl + (k0+row)*HD + seg);
        cp16(st + 2*AARR + so, gvh + row*LL + k0 + seg);
        cp16(st + 3*AARR + so, gvl + row*LL + k0 + seg);
    }
    if (tid < 16) cp16(st + 4*AARR + tid*16, patch_k + k0 + tid*4);
    CP_COMMIT();
}

__global__ __launch_bounds__(256) void attn_mma(const float* __restrict__ patch,
                                                const float* __restrict__ rel_bias) {
    extern __shared__ char dyn[];
    __shared__ float sBias[104], sPq[128];

    int tid = threadIdx.x;
    int lane = tid & 31, w = tid >> 5;
    int fr = lane >> 2, fc = lane & 3;
    int bh = blockIdx.y;
    int b = bh / HEADS, h = bh - b * HEADS;
    int q0 = blockIdx.x << 7;
    float inv_dt = 1.0f / g_dt[b];

    if (tid < 101) sBias[tid] = rel_bias[h*101 + tid];
    if (tid < 128) sPq[tid] = patch[b*LL + q0 + tid];

    const __nv_bfloat16* gqh = g_aqh + (size_t)bh*LL*HD;
    const __nv_bfloat16* gql = g_aql + (size_t)bh*LL*HD;
    const __nv_bfloat16* gkh = g_akh + (size_t)bh*LL*HD;
    const __nv_bfloat16* gkl = g_akl + (size_t)bh*LL*HD;
    const __nv_bfloat16* gvh = g_avh + (size_t)bh*HD*LL;
    const __nv_bfloat16* gvl = g_avl + (size_t)bh*HD*LL;
    const float* patch_b = patch + b*LL;

    attn_load_stage(dyn, gkh, gkl, gvh, gvl, patch_b, 0, tid);

    unsigned qh[4][4], ql[4][4];
    int qr = q0 + w*16;
#pragma unroll
    for (int ks = 0; ks < 4; ks++) {
        int k = ks*16 + 2*fc;
        qh[ks][0] = *(const unsigned*)&gqh[(qr+fr)*HD + k];
        qh[ks][1] = *(const unsigned*)&gqh[(qr+fr+8)*HD + k];
        qh[ks][2] = *(const unsigned*)&gqh[(qr+fr)*HD + k + 8];
        qh[ks][3] = *(const unsigned*)&gqh[(qr+fr+8)*HD + k + 8];
        ql[ks][0] = *(const unsigned*)&gql[(qr+fr)*HD + k];
        ql[ks][1] = *(const unsigned*)&gql[(qr+fr+8)*HD + k];
        ql[ks][2] = *(const unsigned*)&gql[(qr+fr)*HD + k + 8];
        ql[ks][3] = *(const unsigned*)&gql[(qr+fr+8)*HD + k + 8];
    }

    float accO[8][4] = {};
    float m0 = -INFINITY, m1 = -INFINITY, l0 = 0.f, l1 = 0.f;
    int i0 = qr + fr, i1 = i0 + 8;
    float pq0 = 0.f, pq1 = 0.f;

    for (int k0 = 0, s = 0; k0 < LL; k0 += 64, s ^= 1) {
        if (k0 + 64 < LL) {
            attn_load_stage(dyn + (s^1)*ASTAGE, gkh, gkl, gvh, gvl, patch_b, k0 + 64, tid);
            CP_WAIT(1);
        } else {
            CP_WAIT(0);
        }
        __syncthreads();
        const __nv_bfloat16* sKh = (const __nv_bfloat16*)(dyn + s*ASTAGE);
        const __nv_bfloat16* sKl = (const __nv_bfloat16*)(dyn + s*ASTAGE + AARR);
        const __nv_bfloat16* sVh = (const __nv_bfloat16*)(dyn + s*ASTAGE + 2*AARR);
        const __nv_bfloat16* sVl = (const __nv_bfloat16*)(dyn + s*ASTAGE + 3*AARR);
        const float* sPk = (const float*)(dyn + s*ASTAGE + 4*AARR);
        if (k0 == 0) { pq0 = sPq[w*16 + fr]; pq1 = sPq[w*16 + fr + 8]; }

        // ---- S = Q K^T ----
        float accS[8][4] = {};
#pragma unroll
        for (int ks = 0; ks < 4; ks++) {
            unsigned bkh[8][2], bkl[8][2];
#pragma unroll
            for (int nt = 0; nt < 8; nt++) {
                int base = (nt*8 + fr)*ATP + ks*16 + 2*fc;
                bkh[nt][0] = *(const unsigned*)&sKh[base];
                bkh[nt][1] = *(const unsigned*)&sKh[base + 8];
                bkl[nt][0] = *(const unsigned*)&sKl[base];
                bkl[nt][1] = *(const unsigned*)&sKl[base + 8];
            }
#pragma unroll
            for (int nt = 0; nt < 8; nt++) {
                mma_bf16(accS[nt], qh[ks], bkh[nt]);
                mma_bf16(accS[nt], qh[ks], bkl[nt]);
                mma_bf16(accS[nt], ql[ks], bkh[nt]);
            }
        }

        // ---- bias + online softmax ----
        float mx0 = -INFINITY, mx1 = -INFINITY;
#pragma unroll
        for (int nt = 0; nt < 8; nt++) {
#pragma unroll
            for (int e = 0; e < 2; e++) {
                int jl = nt*8 + 2*fc + e;
                int j = k0 + jl;
                float pk = sPk[jl];
                int d1 = min(MAXREL, max(-MAXREL, j - i0)) + MAXREL;
                float rt = pq0 - pk;
                if (!(rt >= -50.f && rt <= 50.f)) rt = 0.f;
                float rr = fminf(50.f, fmaxf(-50.f, rintf(rt * inv_dt)));
                float s0 = accS[nt][e] + sBias[d1] + sBias[(int)rr + MAXREL];
                accS[nt][e] = s0;
                mx0 = fmaxf(mx0, s0);
                int d2 = min(MAXREL, max(-MAXREL, j - i1)) + MAXREL;
                float rt1 = pq1 - pk;
                if (!(rt1 >= -50.f && rt1 <= 50.f)) rt1 = 0.f;
                float rr1 = fminf(50.f, fmaxf(-50.f, rintf(rt1 * inv_dt)));
                float s1 = accS[nt][2+e] + sBias[d2] + sBias[(int)rr1 + MAXREL];
                accS[nt][2+e] = s1;
                mx1 = fmaxf(mx1, s1);
            }
        }
        mx0 = fmaxf(mx0, __shfl_xor_sync(0xffffffffu, mx0, 1));
        mx0 = fmaxf(mx0, __shfl_xor_sync(0xffffffffu, mx0, 2));
        mx1 = fmaxf(mx1, __shfl_xor_sync(0xffffffffu, mx1, 1));
        mx1 = fmaxf(mx1, __shfl_xor_sync(0xffffffffu, mx1, 2));
        float mn0 = fmaxf(m0, mx0), mn1 = fmaxf(m1, mx1);
        float al0 = __expf(m0 - mn0), al1 = __expf(m1 - mn1);
        m0 = mn0; m1 = mn1;
        l0 *= al0; l1 *= al1;
#pragma unroll
        for (int nt = 0; nt < 8; nt++) {
            accO[nt][0] *= al0; accO[nt][1] *= al0;
            accO[nt][2] *= al1; accO[nt][3] *= al1;
        }

        // ---- P = exp(S - m), register-direct A-frag pack ----
        unsigned pfh[4][4], pfl[4][4];
#pragma unroll
        for (int nt = 0; nt < 8; nt++) {
            float p0 = __expf(accS[nt][0] - m0);
            float p1 = __expf(accS[nt][1] - m0);
            float p2 = __expf(accS[nt][2] - m1);
            float p3 = __expf(accS[nt][3] - m1);
            l0 += p0 + p1; l1 += p2 + p3;
            int kc = nt >> 1, off = (nt & 1) << 1;
            pfh[kc][off]   = pack_bf16(p0, p1);
            pfh[kc][off+1] = pack_bf16(p2, p3);
            pfl[kc][off]   = pack_bf16(p0 - bf_hi(p0), p1 - bf_hi(p1));
            pfl[kc][off+1] = pack_bf16(p2 - bf_hi(p2), p3 - bf_hi(p3));
        }

        // ---- O += P Vt ----
#pragma unroll
        for (int kc = 0; kc < 4; kc++) {
            unsigned bvh[8][2], bvl[8][2];
#pragma unroll
            for (int nt = 0; nt < 8; nt++) {
                int base = (nt*8 + fr)*ATP + kc*16 + 2*fc;
                bvh[nt][0] = *(const unsigned*)&sVh[base];
                bvh[nt][1] = *(const unsigned*)&sVh[base + 8];
                bvl[nt][0] = *(const unsigned*)&sVl[base];
                bvl[nt][1] = *(const unsigned*)&sVl[base + 8];
            }
#pragma unroll
            for (int nt = 0; nt < 8; nt++) {
                mma_bf16(accO[nt], pfh[kc], bvh[nt]);
                mma_bf16(accO[nt], pfh[kc], bvl[nt]);
                mma_bf16(accO[nt], pfl[kc], bvh[nt]);
            }
        }
        __syncthreads();
    }

    l0 += __shfl_xor_sync(0xffffffffu, l0, 1);
    l0 += __shfl_xor_sync(0xffffffffu, l0, 2);
    l1 += __shfl_xor_sync(0xffffffffu, l1, 1);
    l1 += __shfl_xor_sync(0xffffffffu, l1, 2);
    float inv0 = 1.0f / l0, inv1 = 1.0f / l1;

#pragma unroll
    for (int nt = 0; nt < 8; nt++) {
        int d = nt*8 + 2*fc;
        size_t r0 = (size_t)(b*LL + i0) * EMBED + h*HD + d;
        size_t r1 = (size_t)(b*LL + i1) * EMBED + h*HD + d;
        float v0 = accO[nt][0] * inv0, v1 = accO[nt][1] * inv0;
        float v2 = accO[nt][2] * inv1, v3 = accO[nt][3] * inv1;
        *(unsigned*)&g_ah[r0] = pack_bf16(v0, v1);
        *(unsigned*)&g_al[r0] = pack_bf16(v0 - bf_hi(v0), v1 - bf_hi(v1));
        *(unsigned*)&g_ah[r1] = pack_bf16(v2, v3);
        *(unsigned*)&g_al[r1] = pack_bf16(v2 - bf_hi(v2), v3 - bf_hi(v3));
    }
}

// ---------------- launch ----------------
extern "C" void kernel_launch(void* const* d_in, const int* in_sizes, int n_in,
                              void* d_out, int out_size) {
    const float* query    = (const float*)d_in[0];
    const float* patch    = (const float*)d_in[3];
    const float* in_w     = (const float*)d_in[4];
    const float* in_b     = (const float*)d_in[5];
    const float* out_w    = (const float*)d_in[6];
    const float* out_b    = (const float*)d_in[7];
    const float* rel_bias = (const float*)d_in[8];
    float* out = (float*)d_out;

    dt_kernel<<<BB, 1024>>>(patch);

    __nv_bfloat16 *xh, *xl, *w1h, *w1l, *w2h, *w2l;
    cudaGetSymbolAddress((void**)&xh,  g_xh);  cudaGetSymbolAddress((void**)&xl,  g_xl);
    cudaGetSymbolAddress((void**)&w1h, g_w1h); cudaGetSymbolAddress((void**)&w1l, g_w1l);
    cudaGetSymbolAddress((void**)&w2h, g_w2h); cudaGetSymbolAddress((void**)&w2l, g_w2l);
    cvt_kernel<<<(MTOT*EMBED/4 + 255)/256, 256>>>((const float4*)query, (uint2*)xh, (uint2*)xl, MTOT*EMBED/4);
    cvt_kernel<<<(N_QKV*EMBED/4 + 255)/256, 256>>>((const float4*)in_w, (uint2*)w1h, (uint2*)w1l, N_QKV*EMBED/4);
    cvt_kernel<<<(EMBED*EMBED/4 + 255)/256, 256>>>((const float4*)out_w, (uint2*)w2h, (uint2*)w2l, EMBED*EMBED/4);

    cudaFuncSetAttribute(gemm_qkv_mma, cudaFuncAttributeMaxDynamicSharedMemorySize, GSMEM_TOTAL);
    cudaFuncSetAttribute(gemm_out_mma, cudaFuncAttributeMaxDynamicSharedMemorySize, GSMEM_TOTAL);
    cudaFuncSetAttribute(attn_mma, cudaFuncAttributeMaxDynamicSharedMemorySize, ASMEM_TOTAL);

    gemm_qkv_mma<<<dim3(N_QKV/128, MTOT/128), 256, GSMEM_TOTAL>>>(in_b);
    attn_mma<<<dim3(LL/128, BB*HEADS), 256, ASMEM_TOTAL>>>(patch, rel_bias);
    gemm_out_mma<<<dim3(EMBED/128, MTOT/128), 256, GSMEM_TOTAL>>>(out_b, out);
}

// round 6
// speedup vs baseline: 3.0583x; 1.0595x over previous
#include <cuda_runtime.h>
#include <cuda_bf16.h>
#include <math.h>
#include <cstdint>

#define EMBED 768
#define HEADS 12
#define HD 64
#define MAXREL 50
#define BB 4
#define LL 1024
#define MTOT (BB*LL)
#define N_QKV (3*EMBED)

// ---------------- device scratch ----------------
__device__ float g_dt[BB];
__device__ __align__(16) __nv_bfloat16 g_xh[MTOT*EMBED];
__device__ __align__(16) __nv_bfloat16 g_xl[MTOT*EMBED];
__device__ __align__(16) __nv_bfloat16 g_w1h[N_QKV*EMBED];
__device__ __align__(16) __nv_bfloat16 g_w1l[N_QKV*EMBED];
__device__ __align__(16) __nv_bfloat16 g_w2h[EMBED*EMBED];
__device__ __align__(16) __nv_bfloat16 g_w2l[EMBED*EMBED];
__device__ __align__(16) __nv_bfloat16 g_aqh[BB*HEADS*LL*HD];
__device__ __align__(16) __nv_bfloat16 g_aql[BB*HEADS*LL*HD];
__device__ __align__(16) __nv_bfloat16 g_akh[BB*HEADS*LL*HD];
__device__ __align__(16) __nv_bfloat16 g_akl[BB*HEADS*LL*HD];
__device__ __align__(16) __nv_bfloat16 g_avh[BB*HEADS*LL*HD];
__device__ __align__(16) __nv_bfloat16 g_avl[BB*HEADS*LL*HD];
__device__ __align__(16) __nv_bfloat16 g_ah[MTOT*EMBED];
__device__ __align__(16) __nv_bfloat16 g_al[MTOT*EMBED];

// ---------------- helpers ----------------
__device__ __forceinline__ void mma_bf16(float* c, const unsigned* a, const unsigned* b) {
    asm volatile(
        "mma.sync.aligned.m16n8k16.row.col.f32.bf16.bf16.f32 "
        "{%0,%1,%2,%3}, {%4,%5,%6,%7}, {%8,%9}, {%0,%1,%2,%3};"
        : "+f"(c[0]), "+f"(c[1]), "+f"(c[2]), "+f"(c[3])
        : "r"(a[0]), "r"(a[1]), "r"(a[2]), "r"(a[3]), "r"(b[0]), "r"(b[1]));
}
__device__ __forceinline__ unsigned pack_bf16(float a, float b) {
    __nv_bfloat162 t = __floats2bfloat162_rn(a, b);
    return *(unsigned*)&t;
}
__device__ __forceinline__ float bf_hi(float x) {
    return __bfloat162float(__float2bfloat16(x));
}
__device__ __forceinline__ uint32_t smem_u32(const void* p) {
    uint32_t a;
    asm("{ .reg .u64 t; cvta.to.shared.u64 t, %1; cvt.u32.u64 %0, t; }" : "=r"(a) : "l"(p));
    return a;
}
__device__ __forceinline__ void cp16(void* dst, const void* src) {
    asm volatile("cp.async.cg.shared.global [%0], [%1], 16;"
        :: "r"(smem_u32(dst)), "l"(src));
}
#define CP_COMMIT() asm volatile("cp.async.commit_group;" ::: "memory")
#define CP_WAIT(n)  asm volatile("cp.async.wait_group %0;" :: "n"(n) : "memory")

#define LDSM4(r0, r1, r2, r3, addr) \
    asm volatile("ldmatrix.sync.aligned.m8n8.x4.shared.b16 {%0,%1,%2,%3}, [%4];" \
        : "=r"(r0), "=r"(r1), "=r"(r2), "=r"(r3) : "r"(addr))

// ---------------- fp32 -> bf16 hi/lo split (x4 vectorized) ----------------
__global__ void cvt_kernel(const float4* __restrict__ src,
                           uint2* __restrict__ hi, uint2* __restrict__ lo, int n4) {
    int i = blockIdx.x * blockDim.x + threadIdx.x;
    if (i < n4) {
        float4 x = src[i];
        hi[i] = make_uint2(pack_bf16(x.x, x.y), pack_bf16(x.z, x.w));
        lo[i] = make_uint2(pack_bf16(x.x - bf_hi(x.x), x.y - bf_hi(x.y)),
                           pack_bf16(x.z - bf_hi(x.z), x.w - bf_hi(x.w)));
    }
}

// ---------------- dt = guarded nanmedian of deltas ----------------
__global__ void dt_kernel(const float* __restrict__ patch) {
    int b = blockIdx.x;
    int tid = threadIdx.x;
    __shared__ float sd[LL-1];
    __shared__ int cnt;
    __shared__ float sLo, sHi;
    if (tid == 0) { cnt = 0; sLo = nanf(""); sHi = nanf(""); }
    __syncthreads();
    int local = 0;
    for (int i = tid; i < LL-1; i += blockDim.x) {
        float d = patch[b*LL + i + 1] - patch[b*LL + i];
        sd[i] = d;
        if (!isnan(d)) local++;
    }
    if (local) atomicAdd(&cnt, local);
    __syncthreads();
    int n = cnt;
    if (n > 0) {
        int kLo = (n - 1) >> 1, kHi = n >> 1;
        for (int i = tid; i < LL-1; i += blockDim.x) {
            float x = sd[i];
            if (isnan(x)) continue;
            int less = 0, eq = 0;
            for (int j = 0; j < LL-1; j++) {
                float y = sd[j];
                less += (y < x);
                eq   += (y == x);
            }
            if (less <= kLo && kLo < less + eq) sLo = x;
            if (less <= kHi && kHi < less + eq) sHi = x;
        }
    }
    __syncthreads();
    if (tid == 0) {
        float med = 0.5f * (sLo + sHi);
        if (n == 0) med = nanf("");
        g_dt[b] = (isfinite(med) && med > 0.f) ? med : 1.0f;
    }
}

// ---------------- GEMM with 2-stage cp.async pipeline + ldmatrix ----------------
#define ROWB 80
#define GARR (128*ROWB)
#define GSMEM_TOTAL (2*4*GARR)

__device__ __forceinline__ void gemm_load_stage(
    char* st, const __nv_bfloat16* Ah, const __nv_bfloat16* Al,
    const __nv_bfloat16* Bh, const __nv_bfloat16* Bl,
    int m0, int n0, int K, int kc, int tid) {
#pragma unroll
    for (int i = 0; i < 2; i++) {
        int id = tid + (i << 8);
        int row = id >> 2, part = id & 3;
        size_t ga = (size_t)(m0 + row) * K + kc + part * 8;
        size_t gb = (size_t)(n0 + row) * K + kc + part * 8;
        int so = row * ROWB + part * 16;
        cp16(st + 0*GARR + so, Ah + ga);
        cp16(st + 1*GARR + so, Al + ga);
        cp16(st + 2*GARR + so, Bh + gb);
        cp16(st + 3*GARR + so, Bl + gb);
    }
    CP_COMMIT();
}

__device__ __forceinline__ void gemm_mainloop(
    const __nv_bfloat16* __restrict__ Ah, const __nv_bfloat16* __restrict__ Al,
    const __nv_bfloat16* __restrict__ Bh, const __nv_bfloat16* __restrict__ Bl,
    int m0, int n0, int K, char* dyn, float acc[4][4][4]) {
    int tid = threadIdx.x;
    int lane = tid & 31, wid = tid >> 5;
    int wm = wid & 1, wn = wid >> 1;
    uint32_t dynb = smem_u32(dyn);

    // ldmatrix lane roles
    int l7 = lane & 7;
    int amrow = ((lane >> 3) & 1) * 8 + l7;     // A row within 16
    int akoff = (lane >> 4) * 16;               // A k-offset in bytes
    int bnrow = l7;
    int bnblk = (lane >> 4) & 1;                // B n-block (+8 rows)
    int bkoff = ((lane >> 3) & 1) * 16;         // B k-offset in bytes

    gemm_load_stage(dyn, Ah, Al, Bh, Bl, m0, n0, K, 0, tid);

    for (int kc = 0, s = 0; kc < K; kc += 32, s ^= 1) {
        if (kc + 32 < K) {
            gemm_load_stage(dyn + (s^1)*4*GARR, Ah, Al, Bh, Bl, m0, n0, K, kc + 32, tid);
            CP_WAIT(1);
        } else {
            CP_WAIT(0);
        }
        __syncthreads();
        uint32_t ahu = dynb + s*4*GARR;
        uint32_t bhu = ahu + 2*GARR;
#pragma unroll
        for (int kk = 0; kk < 2; kk++) {
            unsigned afh[4][4], afl[4][4], bfh[8], bfl[8];
#pragma unroll
            for (int mt = 0; mt < 4; mt++) {
                uint32_t aaddr = ahu + (wm*64 + mt*16 + amrow) * ROWB + kk*32 + akoff;
                LDSM4(afh[mt][0], afh[mt][1], afh[mt][2], afh[mt][3], aaddr);
                LDSM4(afl[mt][0], afl[mt][1], afl[mt][2], afl[mt][3], aaddr + GARR);
            }
#pragma unroll
            for (int p = 0; p < 2; p++) {
                uint32_t baddr = bhu + (wn*32 + p*16 + bnblk*8 + bnrow) * ROWB + kk*32 + bkoff;
                LDSM4(bfh[p*4+0], bfh[p*4+1], bfh[p*4+2], bfh[p*4+3], baddr);
                LDSM4(bfl[p*4+0], bfl[p*4+1], bfl[p*4+2], bfl[p*4+3], baddr + GARR);
            }
#pragma unroll
            for (int mt = 0; mt < 4; mt++)
#pragma unroll
                for (int nt = 0; nt < 4; nt++) {
                    mma_bf16(acc[mt][nt], afh[mt], &bfh[nt*2]);
                    mma_bf16(acc[mt][nt], afl[mt], &bfh[nt*2]);
                    mma_bf16(acc[mt][nt], afh[mt], &bfl[nt*2]);
                }
        }
        __syncthreads();
    }
}

// ---------------- GEMM1: qkv projection ----------------
__global__ __launch_bounds__(256) void gemm_qkv_mma(const float* __restrict__ bias) {
    extern __shared__ char dyn[];
    float acc[4][4][4] = {};
    int m0 = blockIdx.y << 7, n0 = blockIdx.x << 7;
    gemm_mainloop(g_xh, g_xl, g_w1h, g_w1l, m0, n0, EMBED, dyn, acc);

    int tid = threadIdx.x;
    int lane = tid & 31, wid = tid >> 5;
    int wm = wid & 1, wn = wid >> 1;
    int fr = lane >> 2, fc = lane & 3;
#pragma unroll
    for (int mt = 0; mt < 4; mt++) {
#pragma unroll
        for (int half = 0; half < 2; half++) {
            int m = m0 + wm*64 + mt*16 + fr + half*8;
            int b = m >> 10, l = m & (LL - 1);
#pragma unroll
            for (int nt = 0; nt < 4; nt++) {
                int n = n0 + wn*32 + nt*8 + 2*fc;
                float v0 = acc[mt][nt][half*2 + 0] + __ldg(&bias[n]);
                float v1 = acc[mt][nt][half*2 + 1] + __ldg(&bias[n+1]);
                int part = n / EMBED;
                int hn = n - part * EMBED;
                int h = hn >> 6, d = hn & 63;
                int bh = b * HEADS + h;
                if (part == 0) {
                    v0 *= 0.125f; v1 *= 0.125f;
                    int idx = (bh * LL + l) * HD + d;
                    *(unsigned*)&g_aqh[idx] = pack_bf16(v0, v1);
                    *(unsigned*)&g_aql[idx] = pack_bf16(v0 - bf_hi(v0), v1 - bf_hi(v1));
                } else if (part == 1) {
                    int idx = (bh * LL + l) * HD + d;
                    *(unsigned*)&g_akh[idx] = pack_bf16(v0, v1);
                    *(unsigned*)&g_akl[idx] = pack_bf16(v0 - bf_hi(v0), v1 - bf_hi(v1));
                } else {
                    int i0 = (bh * HD + d) * LL + l;
                    int i1 = (bh * HD + d + 1) * LL + l;
                    g_avh[i0] = __float2bfloat16(v0);
                    g_avl[i0] = __float2bfloat16(v0 - bf_hi(v0));
                    g_avh[i1] = __float2bfloat16(v1);
                    g_avl[i1] = __float2bfloat16(v1 - bf_hi(v1));
                }
            }
        }
    }
}

// ---------------- GEMM2: out projection ----------------
__global__ __launch_bounds__(256) void gemm_out_mma(const float* __restrict__ bias,
                                                    float* __restrict__ out) {
    extern __shared__ char dyn[];
    float acc[4][4][4] = {};
    int m0 = blockIdx.y << 7, n0 = blockIdx.x << 7;
    gemm_mainloop(g_ah, g_al, g_w2h, g_w2l, m0, n0, EMBED, dyn, acc);

    int tid = threadIdx.x;
    int lane = tid & 31, wid = tid >> 5;
    int wm = wid & 1, wn = wid >> 1;
    int fr = lane >> 2, fc = lane & 3;
#pragma unroll
    for (int mt = 0; mt < 4; mt++) {
#pragma unroll
        for (int half = 0; half < 2; half++) {
            int m = m0 + wm*64 + mt*16 + fr + half*8;
#pragma unroll
            for (int nt = 0; nt < 4; nt++) {
                int n = n0 + wn*32 + nt*8 + 2*fc;
                float v0 = acc[mt][nt][half*2 + 0] + __ldg(&bias[n]);
                float v1 = acc[mt][nt][half*2 + 1] + __ldg(&bias[n+1]);
                *(float2*)&out[(size_t)m * EMBED + n] = make_float2(v0, v1);
            }
        }
    }
}

// ---------------- tensor-core flash attention, pipelined + ldmatrix ----------------
#define ATP 72
#define ATPB (ATP*2)                 // row stride bytes (144)
#define AARR (64*ATPB)               // bytes per bf16 array
#define ASTAGE (4*AARR + 256)
#define ASMEM_TOTAL (2*ASTAGE)

__device__ __forceinline__ void attn_load_stage(
    char* st, const __nv_bfloat16* gkh, const __nv_bfloat16* gkl,
    const __nv_bfloat16* gvh, const __nv_bfloat16* gvl,
    const float* patch_k, int k0, int tid) {
#pragma unroll
    for (int i = 0; i < 2; i++) {
        int id = tid + (i << 8);
        int row = id >> 3, seg = (id & 7) * 8;
        int so = row * ATPB + seg * 2;
        cp16(st + 0*AARR + so, gkh + (k0+row)*HD + seg);
        cp16(st + 1*AARR + so, gkl + (k0+row)*HD + seg);
        cp16(st + 2*AARR + so, gvh + row*LL + k0 + seg);
        cp16(st + 3*AARR + so, gvl + row*LL + k0 + seg);
    }
    if (tid < 16) cp16(st + 4*AARR + tid*16, patch_k + k0 + tid*4);
    CP_COMMIT();
}

__global__ __launch_bounds__(256) void attn_mma(const float* __restrict__ patch,
                                                const float* __restrict__ rel_bias) {
    extern __shared__ char dyn[];
    __shared__ float sBias[104], sPq[128];

    int tid = threadIdx.x;
    int lane = tid & 31, w = tid >> 5;
    int fr = lane >> 2, fc = lane & 3;
    int bh = blockIdx.y;
    int b = bh / HEADS, h = bh - b * HEADS;
    int q0 = blockIdx.x << 7;
    float inv_dt = 1.0f / g_dt[b];
    uint32_t dynb = smem_u32(dyn);

    // ldmatrix lane roles for B-operand tiles
    int l7 = lane & 7;
    int bnrow = l7;
    int bnblk = (lane >> 4) & 1;
    int bkoff = ((lane >> 3) & 1) * 16;

    if (tid < 101) sBias[tid] = rel_bias[h*101 + tid];
    if (tid < 128) sPq[tid] = patch[b*LL + q0 + tid];

    const __nv_bfloat16* gqh = g_aqh + (size_t)bh*LL*HD;
    const __nv_bfloat16* gql = g_aql + (size_t)bh*LL*HD;
    const __nv_bfloat16* gkh = g_akh + (size_t)bh*LL*HD;
    const __nv_bfloat16* gkl = g_akl + (size_t)bh*LL*HD;
    const __nv_bfloat16* gvh = g_avh + (size_t)bh*HD*LL;
    const __nv_bfloat16* gvl = g_avl + (size_t)bh*HD*LL;
    const float* patch_b = patch + b*LL;

    attn_load_stage(dyn, gkh, gkl, gvh, gvl, patch_b, 0, tid);

    unsigned qh[4][4], ql[4][4];
    int qr = q0 + w*16;
#pragma unroll
    for (int ks = 0; ks < 4; ks++) {
        int k = ks*16 + 2*fc;
        qh[ks][0] = *(const unsigned*)&gqh[(qr+fr)*HD + k];
        qh[ks][1] = *(const unsigned*)&gqh[(qr+fr+8)*HD + k];
        qh[ks][2] = *(const unsigned*)&gqh[(qr+fr)*HD + k + 8];
        qh[ks][3] = *(const unsigned*)&gqh[(qr+fr+8)*HD + k + 8];
        ql[ks][0] = *(const unsigned*)&gql[(qr+fr)*HD + k];
        ql[ks][1] = *(const unsigned*)&gql[(qr+fr+8)*HD + k];
        ql[ks][2] = *(const unsigned*)&gql[(qr+fr)*HD + k + 8];
        ql[ks][3] = *(const unsigned*)&gql[(qr+fr+8)*HD + k + 8];
    }

    float accO[8][4] = {};
    float m0 = -INFINITY, m1 = -INFINITY, l0 = 0.f, l1 = 0.f;
    int i0 = qr + fr, i1 = i0 + 8;
    float pq0 = 0.f, pq1 = 0.f;

    for (int k0 = 0, s = 0; k0 < LL; k0 += 64, s ^= 1) {
        if (k0 + 64 < LL) {
            attn_load_stage(dyn + (s^1)*ASTAGE, gkh, gkl, gvh, gvl, patch_b, k0 + 64, tid);
            CP_WAIT(1);
        } else {
            CP_WAIT(0);
        }
        __syncthreads();
        uint32_t sKhU = dynb + s*ASTAGE;
        const float* sPk = (const float*)(dyn + s*ASTAGE + 4*AARR);
        if (k0 == 0) { pq0 = sPq[w*16 + fr]; pq1 = sPq[w*16 + fr + 8]; }

        // ---- S = Q K^T (ldmatrix B-frags) ----
        float accS[8][4] = {};
#pragma unroll
        for (int ks = 0; ks < 4; ks++) {
            unsigned bkh[16], bkl[16];
#pragma unroll
            for (int p = 0; p < 4; p++) {
                uint32_t ad = sKhU + (p*16 + bnblk*8 + bnrow) * ATPB + ks*32 + bkoff;
                LDSM4(bkh[p*4+0], bkh[p*4+1], bkh[p*4+2], bkh[p*4+3], ad);
                LDSM4(bkl[p*4+0], bkl[p*4+1], bkl[p*4+2], bkl[p*4+3], ad + AARR);
            }
#pragma unroll
            for (int nt = 0; nt < 8; nt++) {
                mma_bf16(accS[nt], qh[ks], &bkh[nt*2]);
                mma_bf16(accS[nt], qh[ks], &bkl[nt*2]);
                mma_bf16(accS[nt], ql[ks], &bkh[nt*2]);
            }
        }

        // ---- bias + online softmax ----
        float mx0 = -INFINITY, mx1 = -INFINITY;
#pragma unroll
        for (int nt = 0; nt < 8; nt++) {
#pragma unroll
            for (int e = 0; e < 2; e++) {
                int jl = nt*8 + 2*fc + e;
                int j = k0 + jl;
                float pk = sPk[jl];
                int d1 = min(MAXREL, max(-MAXREL, j - i0)) + MAXREL;
                float rt = pq0 - pk;
                if (!(rt >= -50.f && rt <= 50.f)) rt = 0.f;
                float rr = fminf(50.f, fmaxf(-50.f, rintf(rt * inv_dt)));
                float s0 = accS[nt][e] + sBias[d1] + sBias[(int)rr + MAXREL];
                accS[nt][e] = s0;
                mx0 = fmaxf(mx0, s0);
                int d2 = min(MAXREL, max(-MAXREL, j - i1)) + MAXREL;
                float rt1 = pq1 - pk;
                if (!(rt1 >= -50.f && rt1 <= 50.f)) rt1 = 0.f;
                float rr1 = fminf(50.f, fmaxf(-50.f, rintf(rt1 * inv_dt)));
                float s1 = accS[nt][2+e] + sBias[d2] + sBias[(int)rr1 + MAXREL];
                accS[nt][2+e] = s1;
                mx1 = fmaxf(mx1, s1);
            }
        }
        mx0 = fmaxf(mx0, __shfl_xor_sync(0xffffffffu, mx0, 1));
        mx0 = fmaxf(mx0, __shfl_xor_sync(0xffffffffu, mx0, 2));
        mx1 = fmaxf(mx1, __shfl_xor_sync(0xffffffffu, mx1, 1));
        mx1 = fmaxf(mx1, __shfl_xor_sync(0xffffffffu, mx1, 2));
        float mn0 = fmaxf(m0, mx0), mn1 = fmaxf(m1, mx1);
        float al0 = __expf(m0 - mn0), al1 = __expf(m1 - mn1);
        m0 = mn0; m1 = mn1;
        l0 *= al0; l1 *= al1;
#pragma unroll
        for (int nt = 0; nt < 8; nt++) {
            accO[nt][0] *= al0; accO[nt][1] *= al0;
            accO[nt][2] *= al1; accO[nt][3] *= al1;
        }

        // ---- P = exp(S - m), register-direct A-frag pack ----
        unsigned pfh[4][4], pfl[4][4];
#pragma unroll
        for (int nt = 0; nt < 8; nt++) {
            float p0 = __expf(accS[nt][0] - m0);
            float p1 = __expf(accS[nt][1] - m0);
            float p2 = __expf(accS[nt][2] - m1);
            float p3 = __expf(accS[nt][3] - m1);
            l0 += p0 + p1; l1 += p2 + p3;
            int kc = nt >> 1, off = (nt & 1) << 1;
            pfh[kc][off]   = pack_bf16(p0, p1);
            pfh[kc][off+1] = pack_bf16(p2, p3);
            pfl[kc][off]   = pack_bf16(p0 - bf_hi(p0), p1 - bf_hi(p1));
            pfl[kc][off+1] = pack_bf16(p2 - bf_hi(p2), p3 - bf_hi(p3));
        }

        // ---- O += P Vt (ldmatrix B-frags) ----
        uint32_t sVhU = sKhU + 2*AARR;
#pragma unroll
        for (int kc = 0; kc < 4; kc++) {
            unsigned bvh[16], bvl[16];
#pragma unroll
            for (int p = 0; p < 4; p++) {
                uint32_t ad = sVhU + (p*16 + bnblk*8 + bnrow) * ATPB + kc*32 + bkoff;
                LDSM4(bvh[p*4+0], bvh[p*4+1], bvh[p*4+2], bvh[p*4+3], ad);
                LDSM4(bvl[p*4+0], bvl[p*4+1], bvl[p*4+2], bvl[p*4+3], ad + AARR);
            }
#pragma unroll
            for (int nt = 0; nt < 8; nt++) {
                mma_bf16(accO[nt], pfh[kc], &bvh[nt*2]);
                mma_bf16(accO[nt], pfh[kc], &bvl[nt*2]);
                mma_bf16(accO[nt], pfl[kc], &bvh[nt*2]);
            }
        }
        __syncthreads();
    }

    l0 += __shfl_xor_sync(0xffffffffu, l0, 1);
    l0 += __shfl_xor_sync(0xffffffffu, l0, 2);
    l1 += __shfl_xor_sync(0xffffffffu, l1, 1);
    l1 += __shfl_xor_sync(0xffffffffu, l1, 2);
    float inv0 = 1.0f / l0, inv1 = 1.0f / l1;

#pragma unroll
    for (int nt = 0; nt < 8; nt++) {
        int d = nt*8 + 2*fc;
        size_t r0 = (size_t)(b*LL + i0) * EMBED + h*HD + d;
        size_t r1 = (size_t)(b*LL + i1) * EMBED + h*HD + d;
        float v0 = accO[nt][0] * inv0, v1 = accO[nt][1] * inv0;
        float v2 = accO[nt][2] * inv1, v3 = accO[nt][3] * inv1;
        *(unsigned*)&g_ah[r0] = pack_bf16(v0, v1);
        *(unsigned*)&g_al[r0] = pack_bf16(v0 - bf_hi(v0), v1 - bf_hi(v1));
        *(unsigned*)&g_ah[r1] = pack_bf16(v2, v3);
        *(unsigned*)&g_al[r1] = pack_bf16(v2 - bf_hi(v2), v3 - bf_hi(v3));
    }
}

// ---------------- launch ----------------
extern "C" void kernel_launch(void* const* d_in, const int* in_sizes, int n_in,
                              void* d_out, int out_size) {
    const float* query    = (const float*)d_in[0];
    const float* patch    = (const float*)d_in[3];
    const float* in_w     = (const float*)d_in[4];
    const float* in_b     = (const float*)d_in[5];
    const float* out_w    = (const float*)d_in[6];
    const float* out_b    = (const float*)d_in[7];
    const float* rel_bias = (const float*)d_in[8];
    float* out = (float*)d_out;

    dt_kernel<<<BB, 1024>>>(patch);

    __nv_bfloat16 *xh, *xl, *w1h, *w1l, *w2h, *w2l;
    cudaGetSymbolAddress((void**)&xh,  g_xh);  cudaGetSymbolAddress((void**)&xl,  g_xl);
    cudaGetSymbolAddress((void**)&w1h, g_w1h); cudaGetSymbolAddress((void**)&w1l, g_w1l);
    cudaGetSymbolAddress((void**)&w2h, g_w2h); cudaGetSymbolAddress((void**)&w2l, g_w2l);
    cvt_kernel<<<(MTOT*EMBED/4 + 255)/256, 256>>>((const float4*)query, (uint2*)xh, (uint2*)xl, MTOT*EMBED/4);
    cvt_kernel<<<(N_QKV*EMBED/4 + 255)/256, 256>>>((const float4*)in_w, (uint2*)w1h, (uint2*)w1l, N_QKV*EMBED/4);
    cvt_kernel<<<(EMBED*EMBED/4 + 255)/256, 256>>>((const float4*)out_w, (uint2*)w2h, (uint2*)w2l, EMBED*EMBED/4);

    cudaFuncSetAttribute(gemm_qkv_mma, cudaFuncAttributeMaxDynamicSharedMemorySize, GSMEM_TOTAL);
    cudaFuncSetAttribute(gemm_out_mma, cudaFuncAttributeMaxDynamicSharedMemorySize, GSMEM_TOTAL);
    cudaFuncSetAttribute(attn_mma, cudaFuncAttributeMaxDynamicSharedMemorySize, ASMEM_TOTAL);

    gemm_qkv_mma<<<dim3(N_QKV/128, MTOT/128), 256, GSMEM_TOTAL>>>(in_b);
    attn_mma<<<dim3(LL/128, BB*HEADS), 256, ASMEM_TOTAL>>>(patch, rel_bias);
    gemm_out_mma<<<dim3(EMBED/128, MTOT/128), 256, GSMEM_TOTAL>>>(out_b, out);
}

// round 7
// speedup vs baseline: 3.9041x; 1.2766x over previous
#include <cuda_runtime.h>
#include <cuda_bf16.h>
#include <cuda_fp16.h>
#include <math.h>
#include <cstdint>

#define EMBED 768
#define HEADS 12
#define HD 64
#define MAXREL 50
#define BB 4
#define LL 1024
#define MTOT (BB*LL)
#define N_QKV (3*EMBED)

// ---------------- device scratch ----------------
__device__ float g_dt[BB];
__device__ __align__(16) __nv_bfloat16 g_xh[MTOT*EMBED];
__device__ __align__(16) __nv_bfloat16 g_xl[MTOT*EMBED];
__device__ __align__(16) __nv_bfloat16 g_w1h[N_QKV*EMBED];
__device__ __align__(16) __nv_bfloat16 g_w1l[N_QKV*EMBED];
__device__ __align__(16) __nv_bfloat16 g_w2h[EMBED*EMBED];
__device__ __align__(16) __nv_bfloat16 g_w2l[EMBED*EMBED];
// fp16 per-head q/k ([bh][l][d]) and v transposed ([bh][d][l])
__device__ __align__(16) __half g_aq[BB*HEADS*LL*HD];
__device__ __align__(16) __half g_ak[BB*HEADS*LL*HD];
__device__ __align__(16) __half g_av[BB*HEADS*LL*HD];
// attention output hi/lo (bf16) for GEMM2
__device__ __align__(16) __nv_bfloat16 g_ah[MTOT*EMBED];
__device__ __align__(16) __nv_bfloat16 g_al[MTOT*EMBED];

// ---------------- helpers ----------------
__device__ __forceinline__ void mma_bf16(float* c, const unsigned* a, const unsigned* b) {
    asm volatile(
        "mma.sync.aligned.m16n8k16.row.col.f32.bf16.bf16.f32 "
        "{%0,%1,%2,%3}, {%4,%5,%6,%7}, {%8,%9}, {%0,%1,%2,%3};"
        : "+f"(c[0]), "+f"(c[1]), "+f"(c[2]), "+f"(c[3])
        : "r"(a[0]), "r"(a[1]), "r"(a[2]), "r"(a[3]), "r"(b[0]), "r"(b[1]));
}
__device__ __forceinline__ void mma_f16(float* c, const unsigned* a, const unsigned* b) {
    asm volatile(
        "mma.sync.aligned.m16n8k16.row.col.f32.f16.f16.f32 "
        "{%0,%1,%2,%3}, {%4,%5,%6,%7}, {%8,%9}, {%0,%1,%2,%3};"
        : "+f"(c[0]), "+f"(c[1]), "+f"(c[2]), "+f"(c[3])
        : "r"(a[0]), "r"(a[1]), "r"(a[2]), "r"(a[3]), "r"(b[0]), "r"(b[1]));
}
__device__ __forceinline__ unsigned pack_bf16(float a, float b) {
    __nv_bfloat162 t = __floats2bfloat162_rn(a, b);
    return *(unsigned*)&t;
}
__device__ __forceinline__ unsigned pack_f16(float a, float b) {
    __half2 t = __floats2half2_rn(a, b);
    return *(unsigned*)&t;
}
__device__ __forceinline__ float bf_hi(float x) {
    return __bfloat162float(__float2bfloat16(x));
}
__device__ __forceinline__ uint32_t smem_u32(const void* p) {
    uint32_t a;
    asm("{ .reg .u64 t; cvta.to.shared.u64 t, %1; cvt.u32.u64 %0, t; }" : "=r"(a) : "l"(p));
    return a;
}
__device__ __forceinline__ void cp16(void* dst, const void* src) {
    asm volatile("cp.async.cg.shared.global [%0], [%1], 16;"
        :: "r"(smem_u32(dst)), "l"(src));
}
#define CP_COMMIT() asm volatile("cp.async.commit_group;" ::: "memory")
#define CP_WAIT(n)  asm volatile("cp.async.wait_group %0;" :: "n"(n) : "memory")

#define LDSM4(r0, r1, r2, r3, addr) \
    asm volatile("ldmatrix.sync.aligned.m8n8.x4.shared.b16 {%0,%1,%2,%3}, [%4];" \
        : "=r"(r0), "=r"(r1), "=r"(r2), "=r"(r3) : "r"(addr))

// ---------------- fp32 -> bf16 hi/lo split (x4 vectorized) ----------------
__global__ void cvt_kernel(const float4* __restrict__ src,
                           uint2* __restrict__ hi, uint2* __restrict__ lo, int n4) {
    int i = blockIdx.x * blockDim.x + threadIdx.x;
    if (i < n4) {
        float4 x = src[i];
        hi[i] = make_uint2(pack_bf16(x.x, x.y), pack_bf16(x.z, x.w));
        lo[i] = make_uint2(pack_bf16(x.x - bf_hi(x.x), x.y - bf_hi(x.y)),
                           pack_bf16(x.z - bf_hi(x.z), x.w - bf_hi(x.w)));
    }
}

// ---------------- dt = guarded nanmedian of deltas ----------------
__global__ void dt_kernel(const float* __restrict__ patch) {
    int b = blockIdx.x;
    int tid = threadIdx.x;
    __shared__ float sd[LL-1];
    __shared__ int cnt;
    __shared__ float sLo, sHi;
    if (tid == 0) { cnt = 0; sLo = nanf(""); sHi = nanf(""); }
    __syncthreads();
    int local = 0;
    for (int i = tid; i < LL-1; i += blockDim.x) {
        float d = patch[b*LL + i + 1] - patch[b*LL + i];
        sd[i] = d;
        if (!isnan(d)) local++;
    }
    if (local) atomicAdd(&cnt, local);
    __syncthreads();
    int n = cnt;
    if (n > 0) {
        int kLo = (n - 1) >> 1, kHi = n >> 1;
        for (int i = tid; i < LL-1; i += blockDim.x) {
            float x = sd[i];
            if (isnan(x)) continue;
            int less = 0, eq = 0;
            for (int j = 0; j < LL-1; j++) {
                float y = sd[j];
                less += (y < x);
                eq   += (y == x);
            }
            if (less <= kLo && kLo < less + eq) sLo = x;
            if (less <= kHi && kHi < less + eq) sHi = x;
        }
    }
    __syncthreads();
    if (tid == 0) {
        float med = 0.5f * (sLo + sHi);
        if (n == 0) med = nanf("");
        g_dt[b] = (isfinite(med) && med > 0.f) ? med : 1.0f;
    }
}

// ---------------- GEMM (bf16 3-pass) with cp.async + ldmatrix ----------------
#define ROWB 80
#define GARR (128*ROWB)
#define GSMEM_TOTAL (2*4*GARR)

__device__ __forceinline__ void gemm_load_stage(
    char* st, const __nv_bfloat16* Ah, const __nv_bfloat16* Al,
    const __nv_bfloat16* Bh, const __nv_bfloat16* Bl,
    int m0, int n0, int K, int kc, int tid) {
#pragma unroll
    for (int i = 0; i < 2; i++) {
        int id = tid + (i << 8);
        int row = id >> 2, part = id & 3;
        size_t ga = (size_t)(m0 + row) * K + kc + part * 8;
        size_t gb = (size_t)(n0 + row) * K + kc + part * 8;
        int so = row * ROWB + part * 16;
        cp16(st + 0*GARR + so, Ah + ga);
        cp16(st + 1*GARR + so, Al + ga);
        cp16(st + 2*GARR + so, Bh + gb);
        cp16(st + 3*GARR + so, Bl + gb);
    }
    CP_COMMIT();
}

__device__ __forceinline__ void gemm_mainloop(
    const __nv_bfloat16* __restrict__ Ah, const __nv_bfloat16* __restrict__ Al,
    const __nv_bfloat16* __restrict__ Bh, const __nv_bfloat16* __restrict__ Bl,
    int m0, int n0, int K, char* dyn, float acc[4][4][4]) {
    int tid = threadIdx.x;
    int lane = tid & 31, wid = tid >> 5;
    int wm = wid & 1, wn = wid >> 1;
    uint32_t dynb = smem_u32(dyn);

    int l7 = lane & 7;
    int amrow = ((lane >> 3) & 1) * 8 + l7;
    int akoff = (lane >> 4) * 16;
    int bnrow = l7;
    int bnblk = (lane >> 4) & 1;
    int bkoff = ((lane >> 3) & 1) * 16;

    gemm_load_stage(dyn, Ah, Al, Bh, Bl, m0, n0, K, 0, tid);

    for (int kc = 0, s = 0; kc < K; kc += 32, s ^= 1) {
        if (kc + 32 < K) {
            gemm_load_stage(dyn + (s^1)*4*GARR, Ah, Al, Bh, Bl, m0, n0, K, kc + 32, tid);
            CP_WAIT(1);
        } else {
            CP_WAIT(0);
        }
        __syncthreads();
        uint32_t ahu = dynb + s*4*GARR;
        uint32_t bhu = ahu + 2*GARR;
#pragma unroll
        for (int kk = 0; kk < 2; kk++) {
            unsigned afh[4][4], afl[4][4], bfh[8], bfl[8];
#pragma unroll
            for (int mt = 0; mt < 4; mt++) {
                uint32_t aaddr = ahu + (wm*64 + mt*16 + amrow) * ROWB + kk*32 + akoff;
                LDSM4(afh[mt][0], afh[mt][1], afh[mt][2], afh[mt][3], aaddr);
                LDSM4(afl[mt][0], afl[mt][1], afl[mt][2], afl[mt][3], aaddr + GARR);
            }
#pragma unroll
            for (int p = 0; p < 2; p++) {
                uint32_t baddr = bhu + (wn*32 + p*16 + bnblk*8 + bnrow) * ROWB + kk*32 + bkoff;
                LDSM4(bfh[p*4+0], bfh[p*4+1], bfh[p*4+2], bfh[p*4+3], baddr);
                LDSM4(bfl[p*4+0], bfl[p*4+1], bfl[p*4+2], bfl[p*4+3], baddr + GARR);
            }
#pragma unroll
            for (int mt = 0; mt < 4; mt++)
#pragma unroll
                for (int nt = 0; nt < 4; nt++) {
                    mma_bf16(acc[mt][nt], afh[mt], &bfh[nt*2]);
                    mma_bf16(acc[mt][nt], afl[mt], &bfh[nt*2]);
                    mma_bf16(acc[mt][nt], afh[mt], &bfl[nt*2]);
                }
        }
        __syncthreads();
    }
}

// ---------------- GEMM1: qkv projection, fp16 epilogue ----------------
__global__ __launch_bounds__(256) void gemm_qkv_mma(const float* __restrict__ bias) {
    extern __shared__ char dyn[];
    float acc[4][4][4] = {};
    int m0 = blockIdx.y << 7, n0 = blockIdx.x << 7;
    gemm_mainloop(g_xh, g_xl, g_w1h, g_w1l, m0, n0, EMBED, dyn, acc);

    int tid = threadIdx.x;
    int lane = tid & 31, wid = tid >> 5;
    int wm = wid & 1, wn = wid >> 1;
    int fr = lane >> 2, fc = lane & 3;
#pragma unroll
    for (int mt = 0; mt < 4; mt++) {
#pragma unroll
        for (int half = 0; half < 2; half++) {
            int m = m0 + wm*64 + mt*16 + fr + half*8;
            int b = m >> 10, l = m & (LL - 1);
#pragma unroll
            for (int nt = 0; nt < 4; nt++) {
                int n = n0 + wn*32 + nt*8 + 2*fc;
                float v0 = acc[mt][nt][half*2 + 0] + __ldg(&bias[n]);
                float v1 = acc[mt][nt][half*2 + 1] + __ldg(&bias[n+1]);
                int part = n / EMBED;
                int hn = n - part * EMBED;
                int h = hn >> 6, d = hn & 63;
                int bh = b * HEADS + h;
                if (part == 0) {
                    *(unsigned*)&g_aq[(bh * LL + l) * HD + d] = pack_f16(v0 * 0.125f, v1 * 0.125f);
                } else if (part == 1) {
                    *(unsigned*)&g_ak[(bh * LL + l) * HD + d] = pack_f16(v0, v1);
                } else {
                    g_av[(bh * HD + d) * LL + l]     = __float2half_rn(v0);
                    g_av[(bh * HD + d + 1) * LL + l] = __float2half_rn(v1);
                }
            }
        }
    }
}

// ---------------- GEMM2: out projection (bf16 3-pass) ----------------
__global__ __launch_bounds__(256) void gemm_out_mma(const float* __restrict__ bias,
                                                    float* __restrict__ out) {
    extern __shared__ char dyn[];
    float acc[4][4][4] = {};
    int m0 = blockIdx.y << 7, n0 = blockIdx.x << 7;
    gemm_mainloop(g_ah, g_al, g_w2h, g_w2l, m0, n0, EMBED, dyn, acc);

    int tid = threadIdx.x;
    int lane = tid & 31, wid = tid >> 5;
    int wm = wid & 1, wn = wid >> 1;
    int fr = lane >> 2, fc = lane & 3;
#pragma unroll
    for (int mt = 0; mt < 4; mt++) {
#pragma unroll
        for (int half = 0; half < 2; half++) {
            int m = m0 + wm*64 + mt*16 + fr + half*8;
#pragma unroll
            for (int nt = 0; nt < 4; nt++) {
                int n = n0 + wn*32 + nt*8 + 2*fc;
                float v0 = acc[mt][nt][half*2 + 0] + __ldg(&bias[n]);
                float v1 = acc[mt][nt][half*2 + 1] + __ldg(&bias[n+1]);
                *(float2*)&out[(size_t)m * EMBED + n] = make_float2(v0, v1);
            }
        }
    }
}

// ---------------- fp16 single-pass flash attention ----------------
#define ATP 72
#define ATPB (ATP*2)                 // 144 B row stride
#define AARR (64*ATPB)               // bytes per fp16 array (K or V)
#define ASTAGE (2*AARR + 256)
#define ASMEM_TOTAL (2*ASTAGE)

__device__ __forceinline__ void attn_load_stage(
    char* st, const __half* gk, const __half* gv,
    const float* patch_k, int k0, int tid) {
#pragma unroll
    for (int i = 0; i < 2; i++) {
        int id = tid + (i << 8);
        int row = id >> 3, seg = (id & 7) * 8;
        int so = row * ATPB + seg * 2;
        cp16(st + 0*AARR + so, gk + (k0+row)*HD + seg);
        cp16(st + 1*AARR + so, gv + row*LL + k0 + seg);
    }
    if (tid < 16) cp16(st + 2*AARR + tid*16, patch_k + k0 + tid*4);
    CP_COMMIT();
}

__global__ __launch_bounds__(256) void attn_mma(const float* __restrict__ patch,
                                                const float* __restrict__ rel_bias) {
    extern __shared__ char dyn[];
    __shared__ float sBias[104], sPq[128];

    int tid = threadIdx.x;
    int lane = tid & 31, w = tid >> 5;
    int fr = lane >> 2, fc = lane & 3;
    int bh = blockIdx.y;
    int b = bh / HEADS, h = bh - b * HEADS;
    int q0 = blockIdx.x << 7;
    float inv_dt = 1.0f / g_dt[b];
    uint32_t dynb = smem_u32(dyn);

    int l7 = lane & 7;
    int bnrow = l7;
    int bnblk = (lane >> 4) & 1;
    int bkoff = ((lane >> 3) & 1) * 16;

    if (tid < 101) sBias[tid] = rel_bias[h*101 + tid];
    if (tid < 128) sPq[tid] = patch[b*LL + q0 + tid];

    const __half* gq = g_aq + (size_t)bh*LL*HD;
    const __half* gk = g_ak + (size_t)bh*LL*HD;
    const __half* gv = g_av + (size_t)bh*HD*LL;
    const float* patch_b = patch + b*LL;

    attn_load_stage(dyn, gk, gv, patch_b, 0, tid);

    unsigned qf[4][4];
    int qr = q0 + w*16;
#pragma unroll
    for (int ks = 0; ks < 4; ks++) {
        int k = ks*16 + 2*fc;
        qf[ks][0] = *(const unsigned*)&gq[(qr+fr)*HD + k];
        qf[ks][1] = *(const unsigned*)&gq[(qr+fr+8)*HD + k];
        qf[ks][2] = *(const unsigned*)&gq[(qr+fr)*HD + k + 8];
        qf[ks][3] = *(const unsigned*)&gq[(qr+fr+8)*HD + k + 8];
    }

    float accO[8][4] = {};
    float m0 = -INFINITY, m1 = -INFINITY, l0 = 0.f, l1 = 0.f;
    int i0 = qr + fr, i1 = i0 + 8;
    float pq0 = 0.f, pq1 = 0.f;

    for (int k0 = 0, s = 0; k0 < LL; k0 += 64, s ^= 1) {
        if (k0 + 64 < LL) {
            attn_load_stage(dyn + (s^1)*ASTAGE, gk, gv, patch_b, k0 + 64, tid);
            CP_WAIT(1);
        } else {
            CP_WAIT(0);
        }
        __syncthreads();
        uint32_t sKU = dynb + s*ASTAGE;
        const float* sPk = (const float*)(dyn + s*ASTAGE + 2*AARR);
        if (k0 == 0) { pq0 = sPq[w*16 + fr]; pq1 = sPq[w*16 + fr + 8]; }

        // ---- S = Q K^T (single-pass fp16) ----
        float accS[8][4] = {};
#pragma unroll
        for (int ks = 0; ks < 4; ks++) {
            unsigned bk[16];
#pragma unroll
            for (int p = 0; p < 4; p++) {
                uint32_t ad = sKU + (p*16 + bnblk*8 + bnrow) * ATPB + ks*32 + bkoff;
                LDSM4(bk[p*4+0], bk[p*4+1], bk[p*4+2], bk[p*4+3], ad);
            }
#pragma unroll
            for (int nt = 0; nt < 8; nt++)
                mma_f16(accS[nt], qf[ks], &bk[nt*2]);
        }

        // ---- bias + online softmax ----
        float mx0 = -INFINITY, mx1 = -INFINITY;
#pragma unroll
        for (int nt = 0; nt < 8; nt++) {
#pragma unroll
            for (int e = 0; e < 2; e++) {
                int jl = nt*8 + 2*fc + e;
                int j = k0 + jl;
                float pk = sPk[jl];
                int d1 = min(MAXREL, max(-MAXREL, j - i0)) + MAXREL;
                float rt = pq0 - pk;
                if (!(rt >= -50.f && rt <= 50.f)) rt = 0.f;
                float rr = fminf(50.f, fmaxf(-50.f, rintf(rt * inv_dt)));
                float s0 = accS[nt][e] + sBias[d1] + sBias[(int)rr + MAXREL];
                accS[nt][e] = s0;
                mx0 = fmaxf(mx0, s0);
                int d2 = min(MAXREL, max(-MAXREL, j - i1)) + MAXREL;
                float rt1 = pq1 - pk;
                if (!(rt1 >= -50.f && rt1 <= 50.f)) rt1 = 0.f;
                float rr1 = fminf(50.f, fmaxf(-50.f, rintf(rt1 * inv_dt)));
                float s1 = accS[nt][2+e] + sBias[d2] + sBias[(int)rr1 + MAXREL];
                accS[nt][2+e] = s1;
                mx1 = fmaxf(mx1, s1);
            }
        }
        mx0 = fmaxf(mx0, __shfl_xor_sync(0xffffffffu, mx0, 1));
        mx0 = fmaxf(mx0, __shfl_xor_sync(0xffffffffu, mx0, 2));
        mx1 = fmaxf(mx1, __shfl_xor_sync(0xffffffffu, mx1, 1));
        mx1 = fmaxf(mx1, __shfl_xor_sync(0xffffffffu, mx1, 2));
        float mn0 = fmaxf(m0, mx0), mn1 = fmaxf(m1, mx1);
        float al0 = __expf(m0 - mn0), al1 = __expf(m1 - mn1);
        m0 = mn0; m1 = mn1;
        l0 *= al0; l1 *= al1;
#pragma unroll
        for (int nt = 0; nt < 8; nt++) {
            accO[nt][0] *= al0; accO[nt][1] *= al0;
            accO[nt][2] *= al1; accO[nt][3] *= al1;
        }

        // ---- P = exp(S - m) packed fp16 ----
        unsigned pf[4][4];
#pragma unroll
        for (int nt = 0; nt < 8; nt++) {
            float p0 = __expf(accS[nt][0] - m0);
            float p1 = __expf(accS[nt][1] - m0);
            float p2 = __expf(accS[nt][2] - m1);
            float p3 = __expf(accS[nt][3] - m1);
            l0 += p0 + p1; l1 += p2 + p3;
            int kc = nt >> 1, off = (nt & 1) << 1;
            pf[kc][off]   = pack_f16(p0, p1);
            pf[kc][off+1] = pack_f16(p2, p3);
        }

        // ---- O += P Vt (single-pass fp16) ----
        uint32_t sVU = sKU + AARR;
#pragma unroll
        for (int kc = 0; kc < 4; kc++) {
            unsigned bv[16];
#pragma unroll
            for (int p = 0; p < 4; p++) {
                uint32_t ad = sVU + (p*16 + bnblk*8 + bnrow) * ATPB + kc*32 + bkoff;
                LDSM4(bv[p*4+0], bv[p*4+1], bv[p*4+2], bv[p*4+3], ad);
            }
#pragma unroll
            for (int nt = 0; nt < 8; nt++)
                mma_f16(accO[nt], pf[kc], &bv[nt*2]);
        }
        __syncthreads();
    }

    l0 += __shfl_xor_sync(0xffffffffu, l0, 1);
    l0 += __shfl_xor_sync(0xffffffffu, l0, 2);
    l1 += __shfl_xor_sync(0xffffffffu, l1, 1);
    l1 += __shfl_xor_sync(0xffffffffu, l1, 2);
    float inv0 = 1.0f / l0, inv1 = 1.0f / l1;

#pragma unroll
    for (int nt = 0; nt < 8; nt++) {
        int d = nt*8 + 2*fc;
        size_t r0 = (size_t)(b*LL + i0) * EMBED + h*HD + d;
        size_t r1 = (size_t)(b*LL + i1) * EMBED + h*HD + d;
        float v0 = accO[nt][0] * inv0, v1 = accO[nt][1] * inv0;
        float v2 = accO[nt][2] * inv1, v3 = accO[nt][3] * inv1;
        *(unsigned*)&g_ah[r0] = pack_bf16(v0, v1);
        *(unsigned*)&g_al[r0] = pack_bf16(v0 - bf_hi(v0), v1 - bf_hi(v1));
        *(unsigned*)&g_ah[r1] = pack_bf16(v2, v3);
        *(unsigned*)&g_al[r1] = pack_bf16(v2 - bf_hi(v2), v3 - bf_hi(v3));
    }
}

// ---------------- launch ----------------
extern "C" void kernel_launch(void* const* d_in, const int* in_sizes, int n_in,
                              void* d_out, int out_size) {
    const float* query    = (const float*)d_in[0];
    const float* patch    = (const float*)d_in[3];
    const float* in_w     = (const float*)d_in[4];
    const float* in_b     = (const float*)d_in[5];
    const float* out_w    = (const float*)d_in[6];
    const float* out_b    = (const float*)d_in[7];
    const float* rel_bias = (const float*)d_in[8];
    float* out = (float*)d_out;

    dt_kernel<<<BB, 1024>>>(patch);

    __nv_bfloat16 *xh, *xl, *w1h, *w1l, *w2h, *w2l;
    cudaGetSymbolAddress((void**)&xh,  g_xh);  cudaGetSymbolAddress((void**)&xl,  g_xl);
    cudaGetSymbolAddress((void**)&w1h, g_w1h); cudaGetSymbolAddress((void**)&w1l, g_w1l);
    cudaGetSymbolAddress((void**)&w2h, g_w2h); cudaGetSymbolAddress((void**)&w2l, g_w2l);
    cvt_kernel<<<(MTOT*EMBED/4 + 255)/256, 256>>>((const float4*)query, (uint2*)xh, (uint2*)xl, MTOT*EMBED/4);
    cvt_kernel<<<(N_QKV*EMBED/4 + 255)/256, 256>>>((const float4*)in_w, (uint2*)w1h, (uint2*)w1l, N_QKV*EMBED/4);
    cvt_kernel<<<(EMBED*EMBED/4 + 255)/256, 256>>>((const float4*)out_w, (uint2*)w2h, (uint2*)w2l, EMBED*EMBED/4);

    cudaFuncSetAttribute(gemm_qkv_mma, cudaFuncAttributeMaxDynamicSharedMemorySize, GSMEM_TOTAL);
    cudaFuncSetAttribute(gemm_out_mma, cudaFuncAttributeMaxDynamicSharedMemorySize, GSMEM_TOTAL);
    cudaFuncSetAttribute(attn_mma, cudaFuncAttributeMaxDynamicSharedMemorySize, ASMEM_TOTAL);

    gemm_qkv_mma<<<dim3(N_QKV/128, MTOT/128), 256, GSMEM_TOTAL>>>(in_b);
    attn_mma<<<dim3(LL/128, BB*HEADS), 256, ASMEM_TOTAL>>>(patch, rel_bias);
    gemm_out_mma<<<dim3(EMBED/128, MTOT/128), 256, GSMEM_TOTAL>>>(out_b, out);
}

// round 8
// speedup vs baseline: 5.0084x; 1.2828x over previous
#include <cuda_runtime.h>
#include <cuda_bf16.h>
#include <cuda_fp16.h>
#include <math.h>
#include <cstdint>

#define EMBED 768
#define HEADS 12
#define HD 64
#define MAXREL 50
#define BB 4
#define LL 1024
#define MTOT (BB*LL)
#define N_QKV (3*EMBED)

// ---------------- device scratch ----------------
__device__ float g_dt[BB];
// fp16 GEMM1 operands
__device__ __align__(16) __half g_x16[MTOT*EMBED];
__device__ __align__(16) __half g_w116[N_QKV*EMBED];
// bf16 hi/lo GEMM2 weight
__device__ __align__(16) __nv_bfloat16 g_w2h[EMBED*EMBED];
__device__ __align__(16) __nv_bfloat16 g_w2l[EMBED*EMBED];
// fp16 per-head q/k ([bh][l][d]) and v transposed ([bh][d][l])
__device__ __align__(16) __half g_aq[BB*HEADS*LL*HD];
__device__ __align__(16) __half g_ak[BB*HEADS*LL*HD];
__device__ __align__(16) __half g_av[BB*HEADS*LL*HD];
// attention output hi/lo (bf16) for GEMM2
__device__ __align__(16) __nv_bfloat16 g_ah[MTOT*EMBED];
__device__ __align__(16) __nv_bfloat16 g_al[MTOT*EMBED];

// ---------------- helpers ----------------
__device__ __forceinline__ void mma_bf16(float* c, const unsigned* a, const unsigned* b) {
    asm volatile(
        "mma.sync.aligned.m16n8k16.row.col.f32.bf16.bf16.f32 "
        "{%0,%1,%2,%3}, {%4,%5,%6,%7}, {%8,%9}, {%0,%1,%2,%3};"
        : "+f"(c[0]), "+f"(c[1]), "+f"(c[2]), "+f"(c[3])
        : "r"(a[0]), "r"(a[1]), "r"(a[2]), "r"(a[3]), "r"(b[0]), "r"(b[1]));
}
__device__ __forceinline__ void mma_f16(float* c, const unsigned* a, const unsigned* b) {
    asm volatile(
        "mma.sync.aligned.m16n8k16.row.col.f32.f16.f16.f32 "
        "{%0,%1,%2,%3}, {%4,%5,%6,%7}, {%8,%9}, {%0,%1,%2,%3};"
        : "+f"(c[0]), "+f"(c[1]), "+f"(c[2]), "+f"(c[3])
        : "r"(a[0]), "r"(a[1]), "r"(a[2]), "r"(a[3]), "r"(b[0]), "r"(b[1]));
}
__device__ __forceinline__ unsigned pack_bf16(float a, float b) {
    __nv_bfloat162 t = __floats2bfloat162_rn(a, b);
    return *(unsigned*)&t;
}
__device__ __forceinline__ unsigned pack_f16(float a, float b) {
    __half2 t = __floats2half2_rn(a, b);
    return *(unsigned*)&t;
}
__device__ __forceinline__ float bf_hi(float x) {
    return __bfloat162float(__float2bfloat16(x));
}
__device__ __forceinline__ uint32_t smem_u32(const void* p) {
    uint32_t a;
    asm("{ .reg .u64 t; cvta.to.shared.u64 t, %1; cvt.u32.u64 %0, t; }" : "=r"(a) : "l"(p));
    return a;
}
__device__ __forceinline__ void cp16(void* dst, const void* src) {
    asm volatile("cp.async.cg.shared.global [%0], [%1], 16;"
        :: "r"(smem_u32(dst)), "l"(src));
}
#define CP_COMMIT() asm volatile("cp.async.commit_group;" ::: "memory")
#define CP_WAIT(n)  asm volatile("cp.async.wait_group %0;" :: "n"(n) : "memory")

#define LDSM4(r0, r1, r2, r3, addr) \
    asm volatile("ldmatrix.sync.aligned.m8n8.x4.shared.b16 {%0,%1,%2,%3}, [%4];" \
        : "=r"(r0), "=r"(r1), "=r"(r2), "=r"(r3) : "r"(addr))

// ---------------- fp32 -> fp16 convert ----------------
__global__ void cvt_f16_kernel(const float4* __restrict__ src,
                               uint2* __restrict__ dst, int n4) {
    int i = blockIdx.x * blockDim.x + threadIdx.x;
    if (i < n4) {
        float4 x = src[i];
        dst[i] = make_uint2(pack_f16(x.x, x.y), pack_f16(x.z, x.w));
    }
}

// ---------------- fp32 -> bf16 hi/lo split ----------------
__global__ void cvt_kernel(const float4* __restrict__ src,
                           uint2* __restrict__ hi, uint2* __restrict__ lo, int n4) {
    int i = blockIdx.x * blockDim.x + threadIdx.x;
    if (i < n4) {
        float4 x = src[i];
        hi[i] = make_uint2(pack_bf16(x.x, x.y), pack_bf16(x.z, x.w));
        lo[i] = make_uint2(pack_bf16(x.x - bf_hi(x.x), x.y - bf_hi(x.y)),
                           pack_bf16(x.z - bf_hi(x.z), x.w - bf_hi(x.w)));
    }
}

// ---------------- dt = guarded nanmedian of deltas ----------------
__global__ void dt_kernel(const float* __restrict__ patch) {
    int b = blockIdx.x;
    int tid = threadIdx.x;
    __shared__ float sd[LL-1];
    __shared__ int cnt;
    __shared__ float sLo, sHi;
    if (tid == 0) { cnt = 0; sLo = nanf(""); sHi = nanf(""); }
    __syncthreads();
    int local = 0;
    for (int i = tid; i < LL-1; i += blockDim.x) {
        float d = patch[b*LL + i + 1] - patch[b*LL + i];
        sd[i] = d;
        if (!isnan(d)) local++;
    }
    if (local) atomicAdd(&cnt, local);
    __syncthreads();
    int n = cnt;
    if (n > 0) {
        int kLo = (n - 1) >> 1, kHi = n >> 1;
        for (int i = tid; i < LL-1; i += blockDim.x) {
            float x = sd[i];
            if (isnan(x)) continue;
            int less = 0, eq = 0;
            for (int j = 0; j < LL-1; j++) {
                float y = sd[j];
                less += (y < x);
                eq   += (y == x);
            }
            if (less <= kLo && kLo < less + eq) sLo = x;
            if (less <= kHi && kHi < less + eq) sHi = x;
        }
    }
    __syncthreads();
    if (tid == 0) {
        float med = 0.5f * (sLo + sHi);
        if (n == 0) med = nanf("");
        g_dt[b] = (isfinite(med) && med > 0.f) ? med : 1.0f;
    }
}

// ---------------- shared GEMM constants ----------------
#define ROWB 80
#define GARR (128*ROWB)
#define GSMEM_F16 (2*2*GARR)        // 2 stages x 2 arrays
#define GSMEM_BF16 (2*4*GARR)       // 2 stages x 4 arrays

// ---------------- fp16 single-pass GEMM mainloop ----------------
__device__ __forceinline__ void gemm_load_stage_f16(
    char* st, const __half* A, const __half* B,
    int m0, int n0, int K, int kc, int tid) {
#pragma unroll
    for (int i = 0; i < 2; i++) {
        int id = tid + (i << 8);
        int row = id >> 2, part = id & 3;
        int so = row * ROWB + part * 16;
        cp16(st + so,        A + (size_t)(m0 + row) * K + kc + part * 8);
        cp16(st + GARR + so, B + (size_t)(n0 + row) * K + kc + part * 8);
    }
    CP_COMMIT();
}

__device__ __forceinline__ void gemm_mainloop_f16(
    const __half* __restrict__ A, const __half* __restrict__ B,
    int m0, int n0, int K, char* dyn, float acc[4][4][4]) {
    int tid = threadIdx.x;
    int lane = tid & 31, wid = tid >> 5;
    int wm = wid & 1, wn = wid >> 1;
    uint32_t dynb = smem_u32(dyn);

    int l7 = lane & 7;
    int amrow = ((lane >> 3) & 1) * 8 + l7;
    int akoff = (lane >> 4) * 16;
    int bnrow = l7;
    int bnblk = (lane >> 4) & 1;
    int bkoff = ((lane >> 3) & 1) * 16;

    gemm_load_stage_f16(dyn, A, B, m0, n0, K, 0, tid);

    for (int kc = 0, s = 0; kc < K; kc += 32, s ^= 1) {
        if (kc + 32 < K) {
            gemm_load_stage_f16(dyn + (s^1)*2*GARR, A, B, m0, n0, K, kc + 32, tid);
            CP_WAIT(1);
        } else {
            CP_WAIT(0);
        }
        __syncthreads();
        uint32_t au = dynb + s*2*GARR;
        uint32_t bu = au + GARR;
#pragma unroll
        for (int kk = 0; kk < 2; kk++) {
            unsigned af[4][4], bf[8];
#pragma unroll
            for (int mt = 0; mt < 4; mt++) {
                uint32_t aaddr = au + (wm*64 + mt*16 + amrow) * ROWB + kk*32 + akoff;
                LDSM4(af[mt][0], af[mt][1], af[mt][2], af[mt][3], aaddr);
            }
#pragma unroll
            for (int p = 0; p < 2; p++) {
                uint32_t baddr = bu + (wn*32 + p*16 + bnblk*8 + bnrow) * ROWB + kk*32 + bkoff;
                LDSM4(bf[p*4+0], bf[p*4+1], bf[p*4+2], bf[p*4+3], baddr);
            }
#pragma unroll
            for (int mt = 0; mt < 4; mt++)
#pragma unroll
                for (int nt = 0; nt < 4; nt++)
                    mma_f16(acc[mt][nt], af[mt], &bf[nt*2]);
        }
        __syncthreads();
    }
}

// ---------------- bf16 3-pass GEMM mainloop (GEMM2) ----------------
__device__ __forceinline__ void gemm_load_stage_bf16(
    char* st, const __nv_bfloat16* Ah, const __nv_bfloat16* Al,
    const __nv_bfloat16* Bh, const __nv_bfloat16* Bl,
    int m0, int n0, int K, int kc, int tid) {
#pragma unroll
    for (int i = 0; i < 2; i++) {
        int id = tid + (i << 8);
        int row = id >> 2, part = id & 3;
        size_t ga = (size_t)(m0 + row) * K + kc + part * 8;
        size_t gb = (size_t)(n0 + row) * K + kc + part * 8;
        int so = row * ROWB + part * 16;
        cp16(st + 0*GARR + so, Ah + ga);
        cp16(st + 1*GARR + so, Al + ga);
        cp16(st + 2*GARR + so, Bh + gb);
        cp16(st + 3*GARR + so, Bl + gb);
    }
    CP_COMMIT();
}

__device__ __forceinline__ void gemm_mainloop_bf16(
    const __nv_bfloat16* __restrict__ Ah, const __nv_bfloat16* __restrict__ Al,
    const __nv_bfloat16* __restrict__ Bh, const __nv_bfloat16* __restrict__ Bl,
    int m0, int n0, int K, char* dyn, float acc[4][4][4]) {
    int tid = threadIdx.x;
    int lane = tid & 31, wid = tid >> 5;
    int wm = wid & 1, wn = wid >> 1;
    uint32_t dynb = smem_u32(dyn);

    int l7 = lane & 7;
    int amrow = ((lane >> 3) & 1) * 8 + l7;
    int akoff = (lane >> 4) * 16;
    int bnrow = l7;
    int bnblk = (lane >> 4) & 1;
    int bkoff = ((lane >> 3) & 1) * 16;

    gemm_load_stage_bf16(dyn, Ah, Al, Bh, Bl, m0, n0, K, 0, tid);

    for (int kc = 0, s = 0; kc < K; kc += 32, s ^= 1) {
        if (kc + 32 < K) {
            gemm_load_stage_bf16(dyn + (s^1)*4*GARR, Ah, Al, Bh, Bl, m0, n0, K, kc + 32, tid);
            CP_WAIT(1);
        } else {
            CP_WAIT(0);
        }
        __syncthreads();
        uint32_t ahu = dynb + s*4*GARR;
        uint32_t bhu = ahu + 2*GARR;
#pragma unroll
        for (int kk = 0; kk < 2; kk++) {
            unsigned afh[4][4], afl[4][4], bfh[8], bfl[8];
#pragma unroll
            for (int mt = 0; mt < 4; mt++) {
                uint32_t aaddr = ahu + (wm*64 + mt*16 + amrow) * ROWB + kk*32 + akoff;
                LDSM4(afh[mt][0], afh[mt][1], afh[mt][2], afh[mt][3], aaddr);
                LDSM4(afl[mt][0], afl[mt][1], afl[mt][2], afl[mt][3], aaddr + GARR);
            }
#pragma unroll
            for (int p = 0; p < 2; p++) {
                uint32_t baddr = bhu + (wn*32 + p*16 + bnblk*8 + bnrow) * ROWB + kk*32 + bkoff;
                LDSM4(bfh[p*4+0], bfh[p*4+1], bfh[p*4+2], bfh[p*4+3], baddr);
                LDSM4(bfl[p*4+0], bfl[p*4+1], bfl[p*4+2], bfl[p*4+3], baddr + GARR);
            }
#pragma unroll
            for (int mt = 0; mt < 4; mt++)
#pragma unroll
                for (int nt = 0; nt < 4; nt++) {
                    mma_bf16(acc[mt][nt], afh[mt], &bfh[nt*2]);
                    mma_bf16(acc[mt][nt], afl[mt], &bfh[nt*2]);
                    mma_bf16(acc[mt][nt], afh[mt], &bfl[nt*2]);
                }
        }
        __syncthreads();
    }
}

// ---------------- GEMM1: qkv projection (fp16 single pass) ----------------
__global__ __launch_bounds__(256) void gemm_qkv_mma(const float* __restrict__ bias) {
    extern __shared__ char dyn[];
    float acc[4][4][4] = {};
    int m0 = blockIdx.y << 7, n0 = blockIdx.x << 7;
    gemm_mainloop_f16(g_x16, g_w116, m0, n0, EMBED, dyn, acc);

    int tid = threadIdx.x;
    int lane = tid & 31, wid = tid >> 5;
    int wm = wid & 1, wn = wid >> 1;
    int fr = lane >> 2, fc = lane & 3;
#pragma unroll
    for (int mt = 0; mt < 4; mt++) {
#pragma unroll
        for (int half = 0; half < 2; half++) {
            int m = m0 + wm*64 + mt*16 + fr + half*8;
            int b = m >> 10, l = m & (LL - 1);
#pragma unroll
            for (int nt = 0; nt < 4; nt++) {
                int n = n0 + wn*32 + nt*8 + 2*fc;
                float v0 = acc[mt][nt][half*2 + 0] + __ldg(&bias[n]);
                float v1 = acc[mt][nt][half*2 + 1] + __ldg(&bias[n+1]);
                int part = n / EMBED;
                int hn = n - part * EMBED;
                int h = hn >> 6, d = hn & 63;
                int bh = b * HEADS + h;
                if (part == 0) {
                    *(unsigned*)&g_aq[(bh * LL + l) * HD + d] = pack_f16(v0 * 0.125f, v1 * 0.125f);
                } else if (part == 1) {
                    *(unsigned*)&g_ak[(bh * LL + l) * HD + d] = pack_f16(v0, v1);
                } else {
                    g_av[(bh * HD + d) * LL + l]     = __float2half_rn(v0);
                    g_av[(bh * HD + d + 1) * LL + l] = __float2half_rn(v1);
                }
            }
        }
    }
}

// ---------------- GEMM2: out projection (bf16 3-pass) ----------------
__global__ __launch_bounds__(256) void gemm_out_mma(const float* __restrict__ bias,
                                                    float* __restrict__ out) {
    extern __shared__ char dyn[];
    float acc[4][4][4] = {};
    int m0 = blockIdx.y << 7, n0 = blockIdx.x << 7;
    gemm_mainloop_bf16(g_ah, g_al, g_w2h, g_w2l, m0, n0, EMBED, dyn, acc);

    int tid = threadIdx.x;
    int lane = tid & 31, wid = tid >> 5;
    int wm = wid & 1, wn = wid >> 1;
    int fr = lane >> 2, fc = lane & 3;
#pragma unroll
    for (int mt = 0; mt < 4; mt++) {
#pragma unroll
        for (int half = 0; half < 2; half++) {
            int m = m0 + wm*64 + mt*16 + fr + half*8;
#pragma unroll
            for (int nt = 0; nt < 4; nt++) {
                int n = n0 + wn*32 + nt*8 + 2*fc;
                float v0 = acc[mt][nt][half*2 + 0] + __ldg(&bias[n]);
                float v1 = acc[mt][nt][half*2 + 1] + __ldg(&bias[n+1]);
                *(float2*)&out[(size_t)m * EMBED + n] = make_float2(v0, v1);
            }
        }
    }
}

// ---------------- fp16 single-pass flash attention ----------------
#define ATP 72
#define ATPB (ATP*2)
#define AARR (64*ATPB)
#define ASTAGE (2*AARR + 256)
#define ASMEM_TOTAL (2*ASTAGE)

__device__ __forceinline__ void attn_load_stage(
    char* st, const __half* gk, const __half* gv,
    const float* patch_k, int k0, int tid) {
#pragma unroll
    for (int i = 0; i < 2; i++) {
        int id = tid + (i << 8);
        int row = id >> 3, seg = (id & 7) * 8;
        int so = row * ATPB + seg * 2;
        cp16(st + 0*AARR + so, gk + (k0+row)*HD + seg);
        cp16(st + 1*AARR + so, gv + row*LL + k0 + seg);
    }
    if (tid < 16) cp16(st + 2*AARR + tid*16, patch_k + k0 + tid*4);
    CP_COMMIT();
}

__global__ __launch_bounds__(256) void attn_mma(const float* __restrict__ patch,
                                                const float* __restrict__ rel_bias) {
    extern __shared__ char dyn[];
    __shared__ float sBias[104], sPq[128];

    int tid = threadIdx.x;
    int lane = tid & 31, w = tid >> 5;
    int fr = lane >> 2, fc = lane & 3;
    int bh = blockIdx.y;
    int b = bh / HEADS, h = bh - b * HEADS;
    int q0 = blockIdx.x << 7;
    float inv_dt = 1.0f / g_dt[b];
    uint32_t dynb = smem_u32(dyn);

    int l7 = lane & 7;
    int bnrow = l7;
    int bnblk = (lane >> 4) & 1;
    int bkoff = ((lane >> 3) & 1) * 16;

    if (tid < 101) sBias[tid] = rel_bias[h*101 + tid];
    if (tid < 128) sPq[tid] = patch[b*LL + q0 + tid];

    const __half* gq = g_aq + (size_t)bh*LL*HD;
    const __half* gk = g_ak + (size_t)bh*LL*HD;
    const __half* gv = g_av + (size_t)bh*HD*LL;
    const float* patch_b = patch + b*LL;

    attn_load_stage(dyn, gk, gv, patch_b, 0, tid);

    unsigned qf[4][4];
    int qr = q0 + w*16;
#pragma unroll
    for (int ks = 0; ks < 4; ks++) {
        int k = ks*16 + 2*fc;
        qf[ks][0] = *(const unsigned*)&gq[(qr+fr)*HD + k];
        qf[ks][1] = *(const unsigned*)&gq[(qr+fr+8)*HD + k];
        qf[ks][2] = *(const unsigned*)&gq[(qr+fr)*HD + k + 8];
        qf[ks][3] = *(const unsigned*)&gq[(qr+fr+8)*HD + k + 8];
    }

    float accO[8][4] = {};
    float m0 = -INFINITY, m1 = -INFINITY, l0 = 0.f, l1 = 0.f;
    int i0 = qr + fr, i1 = i0 + 8;
    float pq0 = 0.f, pq1 = 0.f;

    for (int k0 = 0, s = 0; k0 < LL; k0 += 64, s ^= 1) {
        if (k0 + 64 < LL) {
            attn_load_stage(dyn + (s^1)*ASTAGE, gk, gv, patch_b, k0 + 64, tid);
            CP_WAIT(1);
        } else {
            CP_WAIT(0);
        }
        __syncthreads();
        uint32_t sKU = dynb + s*ASTAGE;
        const float* sPk = (const float*)(dyn + s*ASTAGE + 2*AARR);
        if (k0 == 0) { pq0 = sPq[w*16 + fr]; pq1 = sPq[w*16 + fr + 8]; }

        // ---- S = Q K^T ----
        float accS[8][4] = {};
#pragma unroll
        for (int ks = 0; ks < 4; ks++) {
            unsigned bk[16];
#pragma unroll
            for (int p = 0; p < 4; p++) {
                uint32_t ad = sKU + (p*16 + bnblk*8 + bnrow) * ATPB + ks*32 + bkoff;
                LDSM4(bk[p*4+0], bk[p*4+1], bk[p*4+2], bk[p*4+3], ad);
            }
#pragma unroll
            for (int nt = 0; nt < 8; nt++)
                mma_f16(accS[nt], qf[ks], &bk[nt*2]);
        }

        // ---- bias + online softmax ----
        float mx0 = -INFINITY, mx1 = -INFINITY;
#pragma unroll
        for (int nt = 0; nt < 8; nt++) {
#pragma unroll
            for (int e = 0; e < 2; e++) {
                int jl = nt*8 + 2*fc + e;
                int j = k0 + jl;
                float pk = sPk[jl];
                int d1 = min(MAXREL, max(-MAXREL, j - i0)) + MAXREL;
                float rt = pq0 - pk;
                if (!(rt >= -50.f && rt <= 50.f)) rt = 0.f;
                float rr = fminf(50.f, fmaxf(-50.f, rintf(rt * inv_dt)));
                float s0 = accS[nt][e] + sBias[d1] + sBias[(int)rr + MAXREL];
                accS[nt][e] = s0;
                mx0 = fmaxf(mx0, s0);
                int d2 = min(MAXREL, max(-MAXREL, j - i1)) + MAXREL;
                float rt1 = pq1 - pk;
                if (!(rt1 >= -50.f && rt1 <= 50.f)) rt1 = 0.f;
                float rr1 = fminf(50.f, fmaxf(-50.f, rintf(rt1 * inv_dt)));
                float s1 = accS[nt][2+e] + sBias[d2] + sBias[(int)rr1 + MAXREL];
                accS[nt][2+e] = s1;
                mx1 = fmaxf(mx1, s1);
            }
        }
        mx0 = fmaxf(mx0, __shfl_xor_sync(0xffffffffu, mx0, 1));
        mx0 = fmaxf(mx0, __shfl_xor_sync(0xffffffffu, mx0, 2));
        mx1 = fmaxf(mx1, __shfl_xor_sync(0xffffffffu, mx1, 1));
        mx1 = fmaxf(mx1, __shfl_xor_sync(0xffffffffu, mx1, 2));
        float mn0 = fmaxf(m0, mx0), mn1 = fmaxf(m1, mx1);
        float al0 = __expf(m0 - mn0), al1 = __expf(m1 - mn1);
        m0 = mn0; m1 = mn1;
        l0 *= al0; l1 *= al1;
#pragma unroll
        for (int nt = 0; nt < 8; nt++) {
            accO[nt][0] *= al0; accO[nt][1] *= al0;
            accO[nt][2] *= al1; accO[nt][3] *= al1;
        }

        // ---- P = exp(S - m) packed fp16 ----
        unsigned pf[4][4];
#pragma unroll
        for (int nt = 0; nt < 8; nt++) {
            float p0 = __expf(accS[nt][0] - m0);
            float p1 = __expf(accS[nt][1] - m0);
            float p2 = __expf(accS[nt][2] - m1);
            float p3 = __expf(accS[nt][3] - m1);
            l0 += p0 + p1; l1 += p2 + p3;
            int kc = nt >> 1, off = (nt & 1) << 1;
            pf[kc][off]   = pack_f16(p0, p1);
            pf[kc][off+1] = pack_f16(p2, p3);
        }

        // ---- O += P Vt ----
        uint32_t sVU = sKU + AARR;
#pragma unroll
        for (int kc = 0; kc < 4; kc++) {
            unsigned bv[16];
#pragma unroll
            for (int p = 0; p < 4; p++) {
                uint32_t ad = sVU + (p*16 + bnblk*8 + bnrow) * ATPB + kc*32 + bkoff;
                LDSM4(bv[p*4+0], bv[p*4+1], bv[p*4+2], bv[p*4+3], ad);
            }
#pragma unroll
            for (int nt = 0; nt < 8; nt++)
                mma_f16(accO[nt], pf[kc], &bv[nt*2]);
        }
        __syncthreads();
    }

    l0 += __shfl_xor_sync(0xffffffffu, l0, 1);
    l0 += __shfl_xor_sync(0xffffffffu, l0, 2);
    l1 += __shfl_xor_sync(0xffffffffu, l1, 1);
    l1 += __shfl_xor_sync(0xffffffffu, l1, 2);
    float inv0 = 1.0f / l0, inv1 = 1.0f / l1;

#pragma unroll
    for (int nt = 0; nt < 8; nt++) {
        int d = nt*8 + 2*fc;
        size_t r0 = (size_t)(b*LL + i0) * EMBED + h*HD + d;
        size_t r1 = (size_t)(b*LL + i1) * EMBED + h*HD + d;
        float v0 = accO[nt][0] * inv0, v1 = accO[nt][1] * inv0;
        float v2 = accO[nt][2] * inv1, v3 = accO[nt][3] * inv1;
        *(unsigned*)&g_ah[r0] = pack_bf16(v0, v1);
        *(unsigned*)&g_al[r0] = pack_bf16(v0 - bf_hi(v0), v1 - bf_hi(v1));
        *(unsigned*)&g_ah[r1] = pack_bf16(v2, v3);
        *(unsigned*)&g_al[r1] = pack_bf16(v2 - bf_hi(v2), v3 - bf_hi(v3));
    }
}

// ---------------- launch ----------------
extern "C" void kernel_launch(void* const* d_in, const int* in_sizes, int n_in,
                              void* d_out, int out_size) {
    const float* query    = (const float*)d_in[0];
    const float* patch    = (const float*)d_in[3];
    const float* in_w     = (const float*)d_in[4];
    const float* in_b     = (const float*)d_in[5];
    const float* out_w    = (const float*)d_in[6];
    const float* out_b    = (const float*)d_in[7];
    const float* rel_bias = (const float*)d_in[8];
    float* out = (float*)d_out;

    dt_kernel<<<BB, 1024>>>(patch);

    __half *x16, *w116;
    __nv_bfloat16 *w2h, *w2l;
    cudaGetSymbolAddress((void**)&x16,  g_x16);
    cudaGetSymbolAddress((void**)&w116, g_w116);
    cudaGetSymbolAddress((void**)&w2h,  g_w2h);
    cudaGetSymbolAddress((void**)&w2l,  g_w2l);
    cvt_f16_kernel<<<(MTOT*EMBED/4 + 255)/256, 256>>>((const float4*)query, (uint2*)x16, MTOT*EMBED/4);
    cvt_f16_kernel<<<(N_QKV*EMBED/4 + 255)/256, 256>>>((const float4*)in_w, (uint2*)w116, N_QKV*EMBED/4);
    cvt_kernel<<<(EMBED*EMBED/4 + 255)/256, 256>>>((const float4*)out_w, (uint2*)w2h, (uint2*)w2l, EMBED*EMBED/4);

    cudaFuncSetAttribute(gemm_qkv_mma, cudaFuncAttributeMaxDynamicSharedMemorySize, GSMEM_F16);
    cudaFuncSetAttribute(gemm_out_mma, cudaFuncAttributeMaxDynamicSharedMemorySize, GSMEM_BF16);
    cudaFuncSetAttribute(attn_mma, cudaFuncAttributeMaxDynamicSharedMemorySize, ASMEM_TOTAL);

    gemm_qkv_mma<<<dim3(N_QKV/128, MTOT/128), 256, GSMEM_F16>>>(in_b);
    attn_mma<<<dim3(LL/128, BB*HEADS), 256, ASMEM_TOTAL>>>(patch, rel_bias);
    gemm_out_mma<<<dim3(EMBED/128, MTOT/128), 256, GSMEM_BF16>>>(out_b, out);
}

// round 9
// speedup vs baseline: 5.9775x; 1.1935x over previous
#include <cuda_runtime.h>
#include <cuda_fp16.h>
#include <math.h>
#include <cstdint>

#define EMBED 768
#define HEADS 12
#define HD 64
#define MAXREL 50
#define BB 4
#define LL 1024
#define MTOT (BB*LL)
#define N_QKV (3*EMBED)

// ---------------- device scratch ----------------
__device__ float g_dt[BB];
// fp16 GEMM operands
__device__ __align__(16) __half g_x16[MTOT*EMBED];
__device__ __align__(16) __half g_w116[N_QKV*EMBED];
__device__ __align__(16) __half g_w216[EMBED*EMBED];
// fp16 per-head q/k ([bh][l][d]) and v transposed ([bh][d][l])
__device__ __align__(16) __half g_aq[BB*HEADS*LL*HD];
__device__ __align__(16) __half g_ak[BB*HEADS*LL*HD];
__device__ __align__(16) __half g_av[BB*HEADS*LL*HD];
// fp16 attention output for GEMM2
__device__ __align__(16) __half g_a16[MTOT*EMBED];

// ---------------- helpers ----------------
__device__ __forceinline__ void mma_f16(float* c, const unsigned* a, const unsigned* b) {
    asm volatile(
        "mma.sync.aligned.m16n8k16.row.col.f32.f16.f16.f32 "
        "{%0,%1,%2,%3}, {%4,%5,%6,%7}, {%8,%9}, {%0,%1,%2,%3};"
        : "+f"(c[0]), "+f"(c[1]), "+f"(c[2]), "+f"(c[3])
        : "r"(a[0]), "r"(a[1]), "r"(a[2]), "r"(a[3]), "r"(b[0]), "r"(b[1]));
}
__device__ __forceinline__ unsigned pack_f16(float a, float b) {
    __half2 t = __floats2half2_rn(a, b);
    return *(unsigned*)&t;
}
__device__ __forceinline__ uint32_t smem_u32(const void* p) {
    uint32_t a;
    asm("{ .reg .u64 t; cvta.to.shared.u64 t, %1; cvt.u32.u64 %0, t; }" : "=r"(a) : "l"(p));
    return a;
}
__device__ __forceinline__ void cp16(void* dst, const void* src) {
    asm volatile("cp.async.cg.shared.global [%0], [%1], 16;"
        :: "r"(smem_u32(dst)), "l"(src));
}
#define CP_COMMIT() asm volatile("cp.async.commit_group;" ::: "memory")
#define CP_WAIT(n)  asm volatile("cp.async.wait_group %0;" :: "n"(n) : "memory")

#define LDSM4(r0, r1, r2, r3, addr) \
    asm volatile("ldmatrix.sync.aligned.m8n8.x4.shared.b16 {%0,%1,%2,%3}, [%4];" \
        : "=r"(r0), "=r"(r1), "=r"(r2), "=r"(r3) : "r"(addr))

// ---------------- fp32 -> fp16 convert ----------------
__global__ void cvt_f16_kernel(const float4* __restrict__ src,
                               uint2* __restrict__ dst, int n4) {
    int i = blockIdx.x * blockDim.x + threadIdx.x;
    if (i < n4) {
        float4 x = src[i];
        dst[i] = make_uint2(pack_f16(x.x, x.y), pack_f16(x.z, x.w));
    }
}

// ---------------- dt = guarded nanmedian of deltas ----------------
__global__ void dt_kernel(const float* __restrict__ patch) {
    int b = blockIdx.x;
    int tid = threadIdx.x;
    __shared__ float sd[LL-1];
    __shared__ int cnt;
    __shared__ float sLo, sHi;
    if (tid == 0) { cnt = 0; sLo = nanf(""); sHi = nanf(""); }
    __syncthreads();
    int local = 0;
    for (int i = tid; i < LL-1; i += blockDim.x) {
        float d = patch[b*LL + i + 1] - patch[b*LL + i];
        sd[i] = d;
        if (!isnan(d)) local++;
    }
    if (local) atomicAdd(&cnt, local);
    __syncthreads();
    int n = cnt;
    if (n > 0) {
        int kLo = (n - 1) >> 1, kHi = n >> 1;
        for (int i = tid; i < LL-1; i += blockDim.x) {
            float x = sd[i];
            if (isnan(x)) continue;
            int less = 0, eq = 0;
            for (int j = 0; j < LL-1; j++) {
                float y = sd[j];
                less += (y < x);
                eq   += (y == x);
            }
            if (less <= kLo && kLo < less + eq) sLo = x;
            if (less <= kHi && kHi < less + eq) sHi = x;
        }
    }
    __syncthreads();
    if (tid == 0) {
        float med = 0.5f * (sLo + sHi);
        if (n == 0) med = nanf("");
        g_dt[b] = (isfinite(med) && med > 0.f) ? med : 1.0f;
    }
}

// ---------------- fp16 single-pass GEMM ----------------
#define ROWB 80
#define GARR (128*ROWB)
#define GSMEM_F16 (2*2*GARR)

__device__ __forceinline__ void gemm_load_stage_f16(
    char* st, const __half* A, const __half* B,
    int m0, int n0, int K, int kc, int tid) {
#pragma unroll
    for (int i = 0; i < 2; i++) {
        int id = tid + (i << 8);
        int row = id >> 2, part = id & 3;
        int so = row * ROWB + part * 16;
        cp16(st + so,        A + (size_t)(m0 + row) * K + kc + part * 8);
        cp16(st + GARR + so, B + (size_t)(n0 + row) * K + kc + part * 8);
    }
    CP_COMMIT();
}

__device__ __forceinline__ void gemm_mainloop_f16(
    const __half* __restrict__ A, const __half* __restrict__ B,
    int m0, int n0, int K, char* dyn, float acc[4][4][4]) {
    int tid = threadIdx.x;
    int lane = tid & 31, wid = tid >> 5;
    int wm = wid & 1, wn = wid >> 1;
    uint32_t dynb = smem_u32(dyn);

    int l7 = lane & 7;
    int amrow = ((lane >> 3) & 1) * 8 + l7;
    int akoff = (lane >> 4) * 16;
    int bnrow = l7;
    int bnblk = (lane >> 4) & 1;
    int bkoff = ((lane >> 3) & 1) * 16;

    gemm_load_stage_f16(dyn, A, B, m0, n0, K, 0, tid);

    for (int kc = 0, s = 0; kc < K; kc += 32, s ^= 1) {
        if (kc + 32 < K) {
            gemm_load_stage_f16(dyn + (s^1)*2*GARR, A, B, m0, n0, K, kc + 32, tid);
            CP_WAIT(1);
        } else {
            CP_WAIT(0);
        }
        __syncthreads();
        uint32_t au = dynb + s*2*GARR;
        uint32_t bu = au + GARR;
#pragma unroll
        for (int kk = 0; kk < 2; kk++) {
            unsigned af[4][4], bf[8];
#pragma unroll
            for (int mt = 0; mt < 4; mt++) {
                uint32_t aaddr = au + (wm*64 + mt*16 + amrow) * ROWB + kk*32 + akoff;
                LDSM4(af[mt][0], af[mt][1], af[mt][2], af[mt][3], aaddr);
            }
#pragma unroll
            for (int p = 0; p < 2; p++) {
                uint32_t baddr = bu + (wn*32 + p*16 + bnblk*8 + bnrow) * ROWB + kk*32 + bkoff;
                LDSM4(bf[p*4+0], bf[p*4+1], bf[p*4+2], bf[p*4+3], baddr);
            }
#pragma unroll
            for (int mt = 0; mt < 4; mt++)
#pragma unroll
                for (int nt = 0; nt < 4; nt++)
                    mma_f16(acc[mt][nt], af[mt], &bf[nt*2]);
        }
        __syncthreads();
    }
}

// ---------------- GEMM1: qkv projection ----------------
__global__ __launch_bounds__(256) void gemm_qkv_mma(const float* __restrict__ bias) {
    extern __shared__ char dyn[];
    float acc[4][4][4] = {};
    int m0 = blockIdx.y << 7, n0 = blockIdx.x << 7;
    gemm_mainloop_f16(g_x16, g_w116, m0, n0, EMBED, dyn, acc);

    int tid = threadIdx.x;
    int lane = tid & 31, wid = tid >> 5;
    int wm = wid & 1, wn = wid >> 1;
    int fr = lane >> 2, fc = lane & 3;
#pragma unroll
    for (int mt = 0; mt < 4; mt++) {
#pragma unroll
        for (int half = 0; half < 2; half++) {
            int m = m0 + wm*64 + mt*16 + fr + half*8;
            int b = m >> 10, l = m & (LL - 1);
#pragma unroll
            for (int nt = 0; nt < 4; nt++) {
                int n = n0 + wn*32 + nt*8 + 2*fc;
                float v0 = acc[mt][nt][half*2 + 0] + __ldg(&bias[n]);
                float v1 = acc[mt][nt][half*2 + 1] + __ldg(&bias[n+1]);
                int part = n / EMBED;
                int hn = n - part * EMBED;
                int h = hn >> 6, d = hn & 63;
                int bh = b * HEADS + h;
                if (part == 0) {
                    *(unsigned*)&g_aq[(bh * LL + l) * HD + d] = pack_f16(v0 * 0.125f, v1 * 0.125f);
                } else if (part == 1) {
                    *(unsigned*)&g_ak[(bh * LL + l) * HD + d] = pack_f16(v0, v1);
                } else {
                    g_av[(bh * HD + d) * LL + l]     = __float2half_rn(v0);
                    g_av[(bh * HD + d + 1) * LL + l] = __float2half_rn(v1);
                }
            }
        }
    }
}

// ---------------- GEMM2: out projection (fp16 single pass) ----------------
__global__ __launch_bounds__(256) void gemm_out_mma(const float* __restrict__ bias,
                                                    float* __restrict__ out) {
    extern __shared__ char dyn[];
    float acc[4][4][4] = {};
    int m0 = blockIdx.y << 7, n0 = blockIdx.x << 7;
    gemm_mainloop_f16(g_a16, g_w216, m0, n0, EMBED, dyn, acc);

    int tid = threadIdx.x;
    int lane = tid & 31, wid = tid >> 5;
    int wm = wid & 1, wn = wid >> 1;
    int fr = lane >> 2, fc = lane & 3;
#pragma unroll
    for (int mt = 0; mt < 4; mt++) {
#pragma unroll
        for (int half = 0; half < 2; half++) {
            int m = m0 + wm*64 + mt*16 + fr + half*8;
#pragma unroll
            for (int nt = 0; nt < 4; nt++) {
                int n = n0 + wn*32 + nt*8 + 2*fc;
                float v0 = acc[mt][nt][half*2 + 0] + __ldg(&bias[n]);
                float v1 = acc[mt][nt][half*2 + 1] + __ldg(&bias[n+1]);
                *(float2*)&out[(size_t)m * EMBED + n] = make_float2(v0, v1);
            }
        }
    }
}

// ---------------- fp16 single-pass flash attention ----------------
#define ATP 72
#define ATPB (ATP*2)
#define AARR (64*ATPB)
#define ASTAGE (2*AARR + 256)
#define ASMEM_TOTAL (2*ASTAGE)

__device__ __forceinline__ void attn_load_stage(
    char* st, const __half* gk, const __half* gv,
    const float* patch_k, int k0, int tid) {
#pragma unroll
    for (int i = 0; i < 2; i++) {
        int id = tid + (i << 8);
        int row = id >> 3, seg = (id & 7) * 8;
        int so = row * ATPB + seg * 2;
        cp16(st + 0*AARR + so, gk + (k0+row)*HD + seg);
        cp16(st + 1*AARR + so, gv + row*LL + k0 + seg);
    }
    if (tid < 16) cp16(st + 2*AARR + tid*16, patch_k + k0 + tid*4);
    CP_COMMIT();
}

__global__ __launch_bounds__(256) void attn_mma(const float* __restrict__ patch,
                                                const float* __restrict__ rel_bias) {
    extern __shared__ char dyn[];
    __shared__ float sBias[104], sPq[128];

    int tid = threadIdx.x;
    int lane = tid & 31, w = tid >> 5;
    int fr = lane >> 2, fc = lane & 3;
    int bh = blockIdx.y;
    int b = bh / HEADS, h = bh - b * HEADS;
    int q0 = blockIdx.x << 7;
    float inv_dt = 1.0f / g_dt[b];
    uint32_t dynb = smem_u32(dyn);

    int l7 = lane & 7;
    int bnrow = l7;
    int bnblk = (lane >> 4) & 1;
    int bkoff = ((lane >> 3) & 1) * 16;

    if (tid < 101) sBias[tid] = rel_bias[h*101 + tid];
    if (tid < 128) sPq[tid] = patch[b*LL + q0 + tid];

    const __half* gq = g_aq + (size_t)bh*LL*HD;
    const __half* gk = g_ak + (size_t)bh*LL*HD;
    const __half* gv = g_av + (size_t)bh*HD*LL;
    const float* patch_b = patch + b*LL;

    attn_load_stage(dyn, gk, gv, patch_b, 0, tid);

    unsigned qf[4][4];
    int qr = q0 + w*16;
#pragma unroll
    for (int ks = 0; ks < 4; ks++) {
        int k = ks*16 + 2*fc;
        qf[ks][0] = *(const unsigned*)&gq[(qr+fr)*HD + k];
        qf[ks][1] = *(const unsigned*)&gq[(qr+fr+8)*HD + k];
        qf[ks][2] = *(const unsigned*)&gq[(qr+fr)*HD + k + 8];
        qf[ks][3] = *(const unsigned*)&gq[(qr+fr+8)*HD + k + 8];
    }

    float accO[8][4] = {};
    float m0 = -INFINITY, m1 = -INFINITY, l0 = 0.f, l1 = 0.f;
    int i0 = qr + fr, i1 = i0 + 8;
    float pq0 = 0.f, pq1 = 0.f;

    for (int k0 = 0, s = 0; k0 < LL; k0 += 64, s ^= 1) {
        if (k0 + 64 < LL) {
            attn_load_stage(dyn + (s^1)*ASTAGE, gk, gv, patch_b, k0 + 64, tid);
            CP_WAIT(1);
        } else {
            CP_WAIT(0);
        }
        __syncthreads();
        uint32_t sKU = dynb + s*ASTAGE;
        const float* sPk = (const float*)(dyn + s*ASTAGE + 2*AARR);
        if (k0 == 0) { pq0 = sPq[w*16 + fr]; pq1 = sPq[w*16 + fr + 8]; }

        // ---- S = Q K^T ----
        float accS[8][4] = {};
#pragma unroll
        for (int ks = 0; ks < 4; ks++) {
            unsigned bk[16];
#pragma unroll
            for (int p = 0; p < 4; p++) {
                uint32_t ad = sKU + (p*16 + bnblk*8 + bnrow) * ATPB + ks*32 + bkoff;
                LDSM4(bk[p*4+0], bk[p*4+1], bk[p*4+2], bk[p*4+3], ad);
            }
#pragma unroll
            for (int nt = 0; nt < 8; nt++)
                mma_f16(accS[nt], qf[ks], &bk[nt*2]);
        }

        // ---- bias + online softmax ----
        float mx0 = -INFINITY, mx1 = -INFINITY;
#pragma unroll
        for (int nt = 0; nt < 8; nt++) {
#pragma unroll
            for (int e = 0; e < 2; e++) {
                int jl = nt*8 + 2*fc + e;
                int j = k0 + jl;
                float pk = sPk[jl];
                int d1 = min(MAXREL, max(-MAXREL, j - i0)) + MAXREL;
                float rt = pq0 - pk;
                if (!(rt >= -50.f && rt <= 50.f)) rt = 0.f;
                float rr = fminf(50.f, fmaxf(-50.f, rintf(rt * inv_dt)));
                float s0 = accS[nt][e] + sBias[d1] + sBias[(int)rr + MAXREL];
                accS[nt][e] = s0;
                mx0 = fmaxf(mx0, s0);
                int d2 = min(MAXREL, max(-MAXREL, j - i1)) + MAXREL;
                float rt1 = pq1 - pk;
                if (!(rt1 >= -50.f && rt1 <= 50.f)) rt1 = 0.f;
                float rr1 = fminf(50.f, fmaxf(-50.f, rintf(rt1 * inv_dt)));
                float s1 = accS[nt][2+e] + sBias[d2] + sBias[(int)rr1 + MAXREL];
                accS[nt][2+e] = s1;
                mx1 = fmaxf(mx1, s1);
            }
        }
        mx0 = fmaxf(mx0, __shfl_xor_sync(0xffffffffu, mx0, 1));
        mx0 = fmaxf(mx0, __shfl_xor_sync(0xffffffffu, mx0, 2));
        mx1 = fmaxf(mx1, __shfl_xor_sync(0xffffffffu, mx1, 1));
        mx1 = fmaxf(mx1, __shfl_xor_sync(0xffffffffu, mx1, 2));
        float mn0 = fmaxf(m0, mx0), mn1 = fmaxf(m1, mx1);
        float al0 = __expf(m0 - mn0), al1 = __expf(m1 - mn1);
        m0 = mn0; m1 = mn1;
        l0 *= al0; l1 *= al1;
#pragma unroll
        for (int nt = 0; nt < 8; nt++) {
            accO[nt][0] *= al0; accO[nt][1] *= al0;
            accO[nt][2] *= al1; accO[nt][3] *= al1;
        }

        // ---- P = exp(S - m) packed fp16 ----
        unsigned pf[4][4];
#pragma unroll
        for (int nt = 0; nt < 8; nt++) {
            float p0 = __expf(accS[nt][0] - m0);
            float p1 = __expf(accS[nt][1] - m0);
            float p2 = __expf(accS[nt][2] - m1);
            float p3 = __expf(accS[nt][3] - m1);
            l0 += p0 + p1; l1 += p2 + p3;
            int kc = nt >> 1, off = (nt & 1) << 1;
            pf[kc][off]   = pack_f16(p0, p1);
            pf[kc][off+1] = pack_f16(p2, p3);
        }

        // ---- O += P Vt ----
        uint32_t sVU = sKU + AARR;
#pragma unroll
        for (int kc = 0; kc < 4; kc++) {
            unsigned bv[16];
#pragma unroll
            for (int p = 0; p < 4; p++) {
                uint32_t ad = sVU + (p*16 + bnblk*8 + bnrow) * ATPB + kc*32 + bkoff;
                LDSM4(bv[p*4+0], bv[p*4+1], bv[p*4+2], bv[p*4+3], ad);
            }
#pragma unroll
            for (int nt = 0; nt < 8; nt++)
                mma_f16(accO[nt], pf[kc], &bv[nt*2]);
        }
        __syncthreads();
    }

    l0 += __shfl_xor_sync(0xffffffffu, l0, 1);
    l0 += __shfl_xor_sync(0xffffffffu, l0, 2);
    l1 += __shfl_xor_sync(0xffffffffu, l1, 1);
    l1 += __shfl_xor_sync(0xffffffffu, l1, 2);
    float inv0 = 1.0f / l0, inv1 = 1.0f / l1;

    // epilogue: write fp16 attention output [m][768]
#pragma unroll
    for (int nt = 0; nt < 8; nt++) {
        int d = nt*8 + 2*fc;
        size_t r0 = (size_t)(b*LL + i0) * EMBED + h*HD + d;
        size_t r1 = (size_t)(b*LL + i1) * EMBED + h*HD + d;
        *(unsigned*)&g_a16[r0] = pack_f16(accO[nt][0] * inv0, accO[nt][1] * inv0);
        *(unsigned*)&g_a16[r1] = pack_f16(accO[nt][2] * inv1, accO[nt][3] * inv1);
    }
}

// ---------------- launch ----------------
extern "C" void kernel_launch(void* const* d_in, const int* in_sizes, int n_in,
                              void* d_out, int out_size) {
    const float* query    = (const float*)d_in[0];
    const float* patch    = (const float*)d_in[3];
    const float* in_w     = (const float*)d_in[4];
    const float* in_b     = (const float*)d_in[5];
    const float* out_w    = (const float*)d_in[6];
    const float* out_b    = (const float*)d_in[7];
    const float* rel_bias = (const float*)d_in[8];
    float* out = (float*)d_out;

    dt_kernel<<<BB, 1024>>>(patch);

    __half *x16, *w116, *w216;
    cudaGetSymbolAddress((void**)&x16,  g_x16);
    cudaGetSymbolAddress((void**)&w116, g_w116);
    cudaGetSymbolAddress((void**)&w216, g_w216);
    cvt_f16_kernel<<<(MTOT*EMBED/4 + 255)/256, 256>>>((const float4*)query, (uint2*)x16, MTOT*EMBED/4);
    cvt_f16_kernel<<<(N_QKV*EMBED/4 + 255)/256, 256>>>((const float4*)in_w, (uint2*)w116, N_QKV*EMBED/4);
    cvt_f16_kernel<<<(EMBED*EMBED/4 + 255)/256, 256>>>((const float4*)out_w, (uint2*)w216, EMBED*EMBED/4);

    cudaFuncSetAttribute(gemm_qkv_mma, cudaFuncAttributeMaxDynamicSharedMemorySize, GSMEM_F16);
    cudaFuncSetAttribute(gemm_out_mma, cudaFuncAttributeMaxDynamicSharedMemorySize, GSMEM_F16);
    cudaFuncSetAttribute(attn_mma, cudaFuncAttributeMaxDynamicSharedMemorySize, ASMEM_TOTAL);

    gemm_qkv_mma<<<dim3(N_QKV/128, MTOT/128), 256, GSMEM_F16>>>(in_b);
    attn_mma<<<dim3(LL/128, BB*HEADS), 256, ASMEM_TOTAL>>>(patch, rel_bias);
    gemm_out_mma<<<dim3(EMBED/128, MTOT/128), 256, GSMEM_F16>>>(out_b, out);
}

// round 10
// speedup vs baseline: 6.0423x; 1.0108x over previous
#include <cuda_runtime.h>
#include <cuda_fp16.h>
#include <math.h>
#include <cstdint>

#define EMBED 768
#define HEADS 12
#define HD 64
#define MAXREL 50
#define BB 4
#define LL 1024
#define MTOT (BB*LL)
#define N_QKV (3*EMBED)

// ---------------- device scratch ----------------
__device__ float g_dt[BB];
__device__ __align__(16) __half g_x16[MTOT*EMBED];
__device__ __align__(16) __half g_w116[N_QKV*EMBED];
__device__ __align__(16) __half g_w216[EMBED*EMBED];
__device__ __align__(16) __half g_aq[BB*HEADS*LL*HD];
__device__ __align__(16) __half g_ak[BB*HEADS*LL*HD];
__device__ __align__(16) __half g_av[BB*HEADS*LL*HD];
__device__ __align__(16) __half g_a16[MTOT*EMBED];

// ---------------- helpers ----------------
__device__ __forceinline__ void mma_f16(float* c, const unsigned* a, const unsigned* b) {
    asm volatile(
        "mma.sync.aligned.m16n8k16.row.col.f32.f16.f16.f32 "
        "{%0,%1,%2,%3}, {%4,%5,%6,%7}, {%8,%9}, {%0,%1,%2,%3};"
        : "+f"(c[0]), "+f"(c[1]), "+f"(c[2]), "+f"(c[3])
        : "r"(a[0]), "r"(a[1]), "r"(a[2]), "r"(a[3]), "r"(b[0]), "r"(b[1]));
}
__device__ __forceinline__ unsigned pack_f16(float a, float b) {
    __half2 t = __floats2half2_rn(a, b);
    return *(unsigned*)&t;
}
__device__ __forceinline__ uint32_t smem_u32(const void* p) {
    uint32_t a;
    asm("{ .reg .u64 t; cvta.to.shared.u64 t, %1; cvt.u32.u64 %0, t; }" : "=r"(a) : "l"(p));
    return a;
}
__device__ __forceinline__ void cp16(void* dst, const void* src) {
    asm volatile("cp.async.cg.shared.global [%0], [%1], 16;"
        :: "r"(smem_u32(dst)), "l"(src));
}
#define CP_COMMIT() asm volatile("cp.async.commit_group;" ::: "memory")
#define CP_WAIT(n)  asm volatile("cp.async.wait_group %0;" :: "n"(n) : "memory")

#define LDSM4(r0, r1, r2, r3, addr) \
    asm volatile("ldmatrix.sync.aligned.m8n8.x4.shared.b16 {%0,%1,%2,%3}, [%4];" \
        : "=r"(r0), "=r"(r1), "=r"(r2), "=r"(r3) : "r"(addr))

// ---------------- fused prologue: dt (blocks 0..3) + fp32->fp16 cvt (rest) ----------------
#define NX4  (MTOT*EMBED/4)
#define NW14 (N_QKV*EMBED/4)
#define NW24 (EMBED*EMBED/4)
#define NCVT4 (NX4 + NW14 + NW24)
#define PRO_BLOCKS (4 + (NCVT4 + 255)/256)

__global__ __launch_bounds__(256) void prologue_kernel(
    const float* __restrict__ patch,
    const float4* __restrict__ x, const float4* __restrict__ w1,
    const float4* __restrict__ w2) {
    int tid = threadIdx.x;
    if (blockIdx.x < 4) {
        // ---- dt = guarded nanmedian of deltas ----
        int b = blockIdx.x;
        __shared__ float sd[LL-1];
        __shared__ int cnt;
        __shared__ float sLo, sHi;
        if (tid == 0) { cnt = 0; sLo = nanf(""); sHi = nanf(""); }
        __syncthreads();
        int local = 0;
        for (int i = tid; i < LL-1; i += 256) {
            float d = patch[b*LL + i + 1] - patch[b*LL + i];
            sd[i] = d;
            if (!isnan(d)) local++;
        }
        if (local) atomicAdd(&cnt, local);
        __syncthreads();
        int n = cnt;
        if (n > 0) {
            int kLo = (n - 1) >> 1, kHi = n >> 1;
            for (int i = tid; i < LL-1; i += 256) {
                float v = sd[i];
                if (isnan(v)) continue;
                int less = 0, eq = 0;
                for (int j = 0; j < LL-1; j++) {
                    float y = sd[j];
                    less += (y < v);
                    eq   += (y == v);
                }
                if (less <= kLo && kLo < less + eq) sLo = v;
                if (less <= kHi && kHi < less + eq) sHi = v;
            }
        }
        __syncthreads();
        if (tid == 0) {
            float med = 0.5f * (sLo + sHi);
            if (n == 0) med = nanf("");
            g_dt[b] = (isfinite(med) && med > 0.f) ? med : 1.0f;
        }
    } else {
        int idx = (blockIdx.x - 4) * 256 + tid;
        if (idx >= NCVT4) return;
        const float4* src;
        uint2* dst;
        if (idx < NX4) {
            src = x + idx;
            dst = (uint2*)g_x16 + idx;
        } else if (idx < NX4 + NW14) {
            src = w1 + (idx - NX4);
            dst = (uint2*)g_w116 + (idx - NX4);
        } else {
            src = w2 + (idx - NX4 - NW14);
            dst = (uint2*)g_w216 + (idx - NX4 - NW14);
        }
        float4 v = *src;
        *dst = make_uint2(pack_f16(v.x, v.y), pack_f16(v.z, v.w));
    }
}

// ---------------- fp16 single-pass GEMM ----------------
#define ROWB 80
#define GARR (128*ROWB)
#define GSMEM_F16 (2*2*GARR)

__device__ __forceinline__ void gemm_load_stage_f16(
    char* st, const __half* A, const __half* B,
    int m0, int n0, int K, int kc, int tid) {
#pragma unroll
    for (int i = 0; i < 2; i++) {
        int id = tid + (i << 8);
        int row = id >> 2, part = id & 3;
        int so = row * ROWB + part * 16;
        cp16(st + so,        A + (size_t)(m0 + row) * K + kc + part * 8);
        cp16(st + GARR + so, B + (size_t)(n0 + row) * K + kc + part * 8);
    }
    CP_COMMIT();
}

__device__ __forceinline__ void gemm_mainloop_f16(
    const __half* __restrict__ A, const __half* __restrict__ B,
    int m0, int n0, int K, char* dyn, float acc[4][4][4]) {
    int tid = threadIdx.x;
    int lane = tid & 31, wid = tid >> 5;
    int wm = wid & 1, wn = wid >> 1;
    uint32_t dynb = smem_u32(dyn);

    int l7 = lane & 7;
    int amrow = ((lane >> 3) & 1) * 8 + l7;
    int akoff = (lane >> 4) * 16;
    int bnrow = l7;
    int bnblk = (lane >> 4) & 1;
    int bkoff = ((lane >> 3) & 1) * 16;

    gemm_load_stage_f16(dyn, A, B, m0, n0, K, 0, tid);

    for (int kc = 0, s = 0; kc < K; kc += 32, s ^= 1) {
        if (kc + 32 < K) {
            gemm_load_stage_f16(dyn + (s^1)*2*GARR, A, B, m0, n0, K, kc + 32, tid);
            CP_WAIT(1);
        } else {
            CP_WAIT(0);
        }
        __syncthreads();
        uint32_t au = dynb + s*2*GARR;
        uint32_t bu = au + GARR;
#pragma unroll
        for (int kk = 0; kk < 2; kk++) {
            unsigned af[4][4], bf[8];
#pragma unroll
            for (int mt = 0; mt < 4; mt++) {
                uint32_t aaddr = au + (wm*64 + mt*16 + amrow) * ROWB + kk*32 + akoff;
                LDSM4(af[mt][0], af[mt][1], af[mt][2], af[mt][3], aaddr);
            }
#pragma unroll
            for (int p = 0; p < 2; p++) {
                uint32_t baddr = bu + (wn*32 + p*16 + bnblk*8 + bnrow) * ROWB + kk*32 + bkoff;
                LDSM4(bf[p*4+0], bf[p*4+1], bf[p*4+2], bf[p*4+3], baddr);
            }
#pragma unroll
            for (int mt = 0; mt < 4; mt++)
#pragma unroll
                for (int nt = 0; nt < 4; nt++)
                    mma_f16(acc[mt][nt], af[mt], &bf[nt*2]);
        }
        __syncthreads();
    }
}

// ---------------- GEMM1: qkv projection ----------------
__global__ __launch_bounds__(256) void gemm_qkv_mma(const float* __restrict__ bias) {
    extern __shared__ char dyn[];
    float acc[4][4][4] = {};
    int m0 = blockIdx.y << 7, n0 = blockIdx.x << 7;
    gemm_mainloop_f16(g_x16, g_w116, m0, n0, EMBED, dyn, acc);

    int tid = threadIdx.x;
    int lane = tid & 31, wid = tid >> 5;
    int wm = wid & 1, wn = wid >> 1;
    int fr = lane >> 2, fc = lane & 3;
#pragma unroll
    for (int mt = 0; mt < 4; mt++) {
#pragma unroll
        for (int half = 0; half < 2; half++) {
            int m = m0 + wm*64 + mt*16 + fr + half*8;
            int b = m >> 10, l = m & (LL - 1);
#pragma unroll
            for (int nt = 0; nt < 4; nt++) {
                int n = n0 + wn*32 + nt*8 + 2*fc;
                float v0 = acc[mt][nt][half*2 + 0] + __ldg(&bias[n]);
                float v1 = acc[mt][nt][half*2 + 1] + __ldg(&bias[n+1]);
                int part = n / EMBED;
                int hn = n - part * EMBED;
                int h = hn >> 6, d = hn & 63;
                int bh = b * HEADS + h;
                if (part == 0) {
                    *(unsigned*)&g_aq[(bh * LL + l) * HD + d] = pack_f16(v0 * 0.125f, v1 * 0.125f);
                } else if (part == 1) {
                    *(unsigned*)&g_ak[(bh * LL + l) * HD + d] = pack_f16(v0, v1);
                } else {
                    g_av[(bh * HD + d) * LL + l]     = __float2half_rn(v0);
                    g_av[(bh * HD + d + 1) * LL + l] = __float2half_rn(v1);
                }
            }
        }
    }
}

// ---------------- GEMM2: out projection ----------------
__global__ __launch_bounds__(256) void gemm_out_mma(const float* __restrict__ bias,
                                                    float* __restrict__ out) {
    extern __shared__ char dyn[];
    float acc[4][4][4] = {};
    int m0 = blockIdx.y << 7, n0 = blockIdx.x << 7;
    gemm_mainloop_f16(g_a16, g_w216, m0, n0, EMBED, dyn, acc);

    int tid = threadIdx.x;
    int lane = tid & 31, wid = tid >> 5;
    int wm = wid & 1, wn = wid >> 1;
    int fr = lane >> 2, fc = lane & 3;
#pragma unroll
    for (int mt = 0; mt < 4; mt++) {
#pragma unroll
        for (int half = 0; half < 2; half++) {
            int m = m0 + wm*64 + mt*16 + fr + half*8;
#pragma unroll
            for (int nt = 0; nt < 4; nt++) {
                int n = n0 + wn*32 + nt*8 + 2*fc;
                float v0 = acc[mt][nt][half*2 + 0] + __ldg(&bias[n]);
                float v1 = acc[mt][nt][half*2 + 1] + __ldg(&bias[n+1]);
                *(float2*)&out[(size_t)m * EMBED + n] = make_float2(v0, v1);
            }
        }
    }
}

// ---------------- fp16 single-pass flash attention ----------------
#define ATP 72
#define ATPB (ATP*2)
#define AARR (64*ATPB)
#define ASTAGE (2*AARR + 256)
#define ASMEM_TOTAL (2*ASTAGE)

__device__ __forceinline__ void attn_load_stage(
    char* st, const __half* gk, const __half* gv,
    const float* patch_k, int k0, int tid) {
#pragma unroll
    for (int i = 0; i < 2; i++) {
        int id = tid + (i << 8);
        int row = id >> 3, seg = (id & 7) * 8;
        int so = row * ATPB + seg * 2;
        cp16(st + 0*AARR + so, gk + (k0+row)*HD + seg);
        cp16(st + 1*AARR + so, gv + row*LL + k0 + seg);
    }
    if (tid < 16) cp16(st + 2*AARR + tid*16, patch_k + k0 + tid*4);
    CP_COMMIT();
}

__global__ __launch_bounds__(256) void attn_mma(const float* __restrict__ patch,
                                                const float* __restrict__ rel_bias) {
    extern __shared__ char dyn[];
    __shared__ float sBias[104], sPq[128];

    int tid = threadIdx.x;
    int lane = tid & 31, w = tid >> 5;
    int fr = lane >> 2, fc = lane & 3;
    int bh = blockIdx.y;
    int b = bh / HEADS, h = bh - b * HEADS;
    int q0 = blockIdx.x << 7;
    float inv_dt = 1.0f / g_dt[b];
    uint32_t dynb = smem_u32(dyn);

    int l7 = lane & 7;
    int bnrow = l7;
    int bnblk = (lane >> 4) & 1;
    int bkoff = ((lane >> 3) & 1) * 16;

    if (tid < 101) sBias[tid] = rel_bias[h*101 + tid];
    if (tid < 128) sPq[tid] = patch[b*LL + q0 + tid];

    const __half* gq = g_aq + (size_t)bh*LL*HD;
    const __half* gk = g_ak + (size_t)bh*LL*HD;
    const __half* gv = g_av + (size_t)bh*HD*LL;
    const float* patch_b = patch + b*LL;

    attn_load_stage(dyn, gk, gv, patch_b, 0, tid);

    unsigned qf[4][4];
    int qr = q0 + w*16;
#pragma unroll
    for (int ks = 0; ks < 4; ks++) {
        int k = ks*16 + 2*fc;
        qf[ks][0] = *(const unsigned*)&gq[(qr+fr)*HD + k];
        qf[ks][1] = *(const unsigned*)&gq[(qr+fr+8)*HD + k];
        qf[ks][2] = *(const unsigned*)&gq[(qr+fr)*HD + k + 8];
        qf[ks][3] = *(const unsigned*)&gq[(qr+fr+8)*HD + k + 8];
    }

    float accO[8][4] = {};
    float m0 = -INFINITY, m1 = -INFINITY, l0 = 0.f, l1 = 0.f;
    int i0 = qr + fr, i1 = i0 + 8;
    float pq0 = 0.f, pq1 = 0.f;

    for (int k0 = 0, s = 0; k0 < LL; k0 += 64, s ^= 1) {
        if (k0 + 64 < LL) {
            attn_load_stage(dyn + (s^1)*ASTAGE, gk, gv, patch_b, k0 + 64, tid);
            CP_WAIT(1);
        } else {
            CP_WAIT(0);
        }
        __syncthreads();
        uint32_t sKU = dynb + s*ASTAGE;
        const float* sPk = (const float*)(dyn + s*ASTAGE + 2*AARR);
        if (k0 == 0) { pq0 = sPq[w*16 + fr]; pq1 = sPq[w*16 + fr + 8]; }

        // ---- S = Q K^T ----
        float accS[8][4] = {};
#pragma unroll
        for (int ks = 0; ks < 4; ks++) {
            unsigned bk[16];
#pragma unroll
            for (int p = 0; p < 4; p++) {
                uint32_t ad = sKU + (p*16 + bnblk*8 + bnrow) * ATPB + ks*32 + bkoff;
                LDSM4(bk[p*4+0], bk[p*4+1], bk[p*4+2], bk[p*4+3], ad);
            }
#pragma unroll
            for (int nt = 0; nt < 8; nt++)
                mma_f16(accS[nt], qf[ks], &bk[nt*2]);
        }

        // ---- bias + online softmax ----
        float mx0 = -INFINITY, mx1 = -INFINITY;
#pragma unroll
        for (int nt = 0; nt < 8; nt++) {
#pragma unroll
            for (int e = 0; e < 2; e++) {
                int jl = nt*8 + 2*fc + e;
                int j = k0 + jl;
                float pk = sPk[jl];
                int d1 = min(MAXREL, max(-MAXREL, j - i0)) + MAXREL;
                float rt = pq0 - pk;
                rt = (fabsf(rt) <= 50.f) ? rt : 0.f;    // NaN or |rt|>M -> 0
                float rr = fminf(50.f, fmaxf(-50.f, rintf(rt * inv_dt)));
                float s0 = accS[nt][e] + sBias[d1] + sBias[(int)rr + MAXREL];
                accS[nt][e] = s0;
                mx0 = fmaxf(mx0, s0);
                int d2 = min(MAXREL, max(-MAXREL, j - i1)) + MAXREL;
                float rt1 = pq1 - pk;
                rt1 = (fabsf(rt1) <= 50.f) ? rt1 : 0.f;
                float rr1 = fminf(50.f, fmaxf(-50.f, rintf(rt1 * inv_dt)));
                float s1 = accS[nt][2+e] + sBias[d2] + sBias[(int)rr1 + MAXREL];
                accS[nt][2+e] = s1;
                mx1 = fmaxf(mx1, s1);
            }
        }
        mx0 = fmaxf(mx0, __shfl_xor_sync(0xffffffffu, mx0, 1));
        mx0 = fmaxf(mx0, __shfl_xor_sync(0xffffffffu, mx0, 2));
        mx1 = fmaxf(mx1, __shfl_xor_sync(0xffffffffu, mx1, 1));
        mx1 = fmaxf(mx1, __shfl_xor_sync(0xffffffffu, mx1, 2));
        float mn0 = fmaxf(m0, mx0), mn1 = fmaxf(m1, mx1);
        float al0 = __expf(m0 - mn0), al1 = __expf(m1 - mn1);
        m0 = mn0; m1 = mn1;
        l0 *= al0; l1 *= al1;
        if (!(al0 == 1.f && al1 == 1.f)) {      // skip exact-1 rescale (common case)
#pragma unroll
            for (int nt = 0; nt < 8; nt++) {
                accO[nt][0] *= al0; accO[nt][1] *= al0;
                accO[nt][2] *= al1; accO[nt][3] *= al1;
            }
        }

        // ---- P = exp(S - m) packed fp16 ----
        unsigned pf[4][4];
#pragma unroll
        for (int nt = 0; nt < 8; nt++) {
            float p0 = __expf(accS[nt][0] - m0);
            float p1 = __expf(accS[nt][1] - m0);
            float p2 = __expf(accS[nt][2] - m1);
            float p3 = __expf(accS[nt][3] - m1);
            l0 += p0 + p1; l1 += p2 + p3;
            int kc = nt >> 1, off = (nt & 1) << 1;
            pf[kc][off]   = pack_f16(p0, p1);
            pf[kc][off+1] = pack_f16(p2, p3);
        }

        // ---- O += P Vt ----
        uint32_t sVU = sKU + AARR;
#pragma unroll
        for (int kc = 0; kc < 4; kc++) {
            unsigned bv[16];
#pragma unroll
            for (int p = 0; p < 4; p++) {
                uint32_t ad = sVU + (p*16 + bnblk*8 + bnrow) * ATPB + kc*32 + bkoff;
                LDSM4(bv[p*4+0], bv[p*4+1], bv[p*4+2], bv[p*4+3], ad);
            }
#pragma unroll
            for (int nt = 0; nt < 8; nt++)
                mma_f16(accO[nt], pf[kc], &bv[nt*2]);
        }
        __syncthreads();
    }

    l0 += __shfl_xor_sync(0xffffffffu, l0, 1);
    l0 += __shfl_xor_sync(0xffffffffu, l0, 2);
    l1 += __shfl_xor_sync(0xffffffffu, l1, 1);
    l1 += __shfl_xor_sync(0xffffffffu, l1, 2);
    float inv0 = 1.0f / l0, inv1 = 1.0f / l1;

#pragma unroll
    for (int nt = 0; nt < 8; nt++) {
        int d = nt*8 + 2*fc;
        size_t r0 = (size_t)(b*LL + i0) * EMBED + h*HD + d;
        size_t r1 = (size_t)(b*LL + i1) * EMBED + h*HD + d;
        *(unsigned*)&g_a16[r0] = pack_f16(accO[nt][0] * inv0, accO[nt][1] * inv0);
        *(unsigned*)&g_a16[r1] = pack_f16(accO[nt][2] * inv1, accO[nt][3] * inv1);
    }
}

// ---------------- launch ----------------
extern "C" void kernel_launch(void* const* d_in, const int* in_sizes, int n_in,
                              void* d_out, int out_size) {
    const float* query    = (const float*)d_in[0];
    const float* patch    = (const float*)d_in[3];
    const float* in_w     = (const float*)d_in[4];
    const float* in_b     = (const float*)d_in[5];
    const float* out_w    = (const float*)d_in[6];
    const float* out_b    = (const float*)d_in[7];
    const float* rel_bias = (const float*)d_in[8];
    float* out = (float*)d_out;

    prologue_kernel<<<PRO_BLOCKS, 256>>>(patch, (const float4*)query,
                                         (const float4*)in_w, (const float4*)out_w);

    cudaFuncSetAttribute(gemm_qkv_mma, cudaFuncAttributeMaxDynamicSharedMemorySize, GSMEM_F16);
    cudaFuncSetAttribute(gemm_out_mma, cudaFuncAttributeMaxDynamicSharedMemorySize, GSMEM_F16);
    cudaFuncSetAttribute(attn_mma, cudaFuncAttributeMaxDynamicSharedMemorySize, ASMEM_TOTAL);

    gemm_qkv_mma<<<dim3(N_QKV/128, MTOT/128), 256, GSMEM_F16>>>(in_b);
    attn_mma<<<dim3(LL/128, BB*HEADS), 256, ASMEM_TOTAL>>>(patch, rel_bias);
    gemm_out_mma<<<dim3(EMBED/128, MTOT/128), 256, GSMEM_F16>>>(out_b, out);
}